// round 8
// baseline (speedup 1.0000x reference)
#include <cuda_runtime.h>
#include <cuda_bf16.h>
#include <math.h>
#include <cstdint>

// Problem constants (fixed shapes)
#define Bb 2
#define Tt 4096
#define Dd 2048
#define Hh 16
#define Kk 128
#define Vv 128
#define BT 64
#define NT 64
#define TOKS (Bb*Tt)          // 8192
#define HD   (Hh*Kk)          // 2048
#define VS   32               // v-slice width in scan
#define NVS  (Vv/VS)          // 4

// ---------------- scratch (device globals; no runtime alloc) ----------------
__device__ float g_q [TOKS*HD];
__device__ float g_k [TOKS*HD];
__device__ float g_v [TOKS*HD];
__device__ float g_g [TOKS*HD];
__device__ float g_z [TOKS*HD];
__device__ float g_eta  [TOKS*Hh];
__device__ float g_theta[TOKS*Hh];
__device__ float g_lec  [32*Tt];
__device__ float g_elec [32*Tt];
__device__ float g_coef [32*Tt];
__device__ float g_M    [32*NT*BT*BT];
__device__ __nv_bfloat16 g_xhi[TOKS*Dd];
__device__ __nv_bfloat16 g_xlo[TOKS*Dd];
__device__ __nv_bfloat16 g_whi[5*Dd*Dd];
__device__ __nv_bfloat16 g_wlo[5*Dd*Dd];
__device__ __nv_bfloat16 g_oghi[TOKS*HD];
__device__ __nv_bfloat16 g_oglo[TOKS*HD];

// ---------------- helpers ----------------
typedef unsigned long long u64t;

__device__ __forceinline__ uint32_t smem_u32(const void* p) {
    uint32_t a;
    asm("{ .reg .u64 t; cvta.to.shared.u64 t, %1; cvt.u32.u64 %0, t; }" : "=r"(a) : "l"(p));
    return a;
}
__device__ __forceinline__ void ldm_x4(uint32_t (&r)[4], uint32_t addr) {
    asm volatile("ldmatrix.sync.aligned.m8n8.x4.shared.b16 {%0,%1,%2,%3}, [%4];"
                 : "=r"(r[0]), "=r"(r[1]), "=r"(r[2]), "=r"(r[3]) : "r"(addr));
}
__device__ __forceinline__ void mma16816(float (&d)[4], const uint32_t (&a)[4],
                                         uint32_t b0, uint32_t b1) {
    asm volatile(
        "mma.sync.aligned.m16n8k16.row.col.f32.bf16.bf16.f32 "
        "{%0,%1,%2,%3}, {%4,%5,%6,%7}, {%8,%9}, {%0,%1,%2,%3};"
        : "+f"(d[0]), "+f"(d[1]), "+f"(d[2]), "+f"(d[3])
        : "r"(a[0]), "r"(a[1]), "r"(a[2]), "r"(a[3]), "r"(b0), "r"(b1));
}
// packed f32x2 (FFMA2 path)
__device__ __forceinline__ u64t pk2(float lo, float hi) {
    u64t d; asm("mov.b64 %0, {%1,%2};" : "=l"(d) : "f"(lo), "f"(hi)); return d;
}
__device__ __forceinline__ void upk2(u64t s, float& lo, float& hi) {
    asm("mov.b64 {%0,%1}, %2;" : "=f"(lo), "=f"(hi) : "l"(s));
}
__device__ __forceinline__ u64t fma2(u64t a, u64t b, u64t c) {
    u64t d; asm("fma.rn.f32x2 %0, %1, %2, %3;" : "=l"(d) : "l"(a), "l"(b), "l"(c)); return d;
}
__device__ __forceinline__ u64t mul2(u64t a, u64t b) {
    u64t d; asm("mul.rn.f32x2 %0, %1, %2;" : "=l"(d) : "l"(a), "l"(b)); return d;
}
__device__ __forceinline__ u64t d2u(double x) { return __double_as_longlong(x); }
__device__ __forceinline__ double u2d(u64t x) { return __longlong_as_double(x); }
#define CP16(dst, src) \
    asm volatile("cp.async.cg.shared.global [%0], [%1], 16;" :: "r"(dst), "l"(src) : "memory")

// ---------------- fp32 -> (hi,lo) bf16 split ----------------
__global__ __launch_bounds__(256)
void split_bf16_kernel(const float* __restrict__ x, __nv_bfloat16* __restrict__ hi,
                       __nv_bfloat16* __restrict__ lo, int n4)
{
    int i = blockIdx.x * 256 + threadIdx.x;
    if (i >= n4) return;
    float4 v = ((const float4*)x)[i];
    float vv[4] = {v.x, v.y, v.z, v.w};
    __align__(8) __nv_bfloat16 h[4], l[4];
#pragma unroll
    for (int j = 0; j < 4; j++) {
        h[j] = __float2bfloat16(vv[j]);
        l[j] = __float2bfloat16(vv[j] - __bfloat162float(h[j]));
    }
    ((uint2*)hi)[i] = *(uint2*)h;
    ((uint2*)lo)[i] = *(uint2*)l;
}

// ---------------- HMMA 3xBF16 GEMM: C[8192,2048] = alpha * A @ B^T ----------------
// CTA tile 128x128, BK=32, 5-stage cp.async, 4 warps (2Mx2N), warp 64x64.
#define BKT 32
#define NKT 192                 // 3 * (2048/32)
#define ROWB 80                 // smem row stride (32 bf16 + 8 pad)
#define STG_BYTES (128*ROWB*2)  // 20480
#define NSTG 5

__device__ __forceinline__ void ld_stage(uint32_t sA, uint32_t sB,
    const __nv_bfloat16* __restrict__ A, const __nv_bfloat16* __restrict__ B,
    int bm, int bn, int k0, int tid)
{
#pragma unroll
    for (int i = 0; i < 4; i++) {
        int idx = tid + i * 128;      // 0..511
        int row = idx >> 2, c = idx & 3;
        uint32_t dA = sA + row * ROWB + c * 16;
        const void* pA = A + (size_t)(bm + row) * 2048 + k0 + c * 8;
        CP16(dA, pA);
        uint32_t dB = sB + row * ROWB + c * 16;
        const void* pB = B + (size_t)(bn + row) * 2048 + k0 + c * 8;
        CP16(dB, pB);
    }
}

__global__ __launch_bounds__(128, 2)
void gemm3_bf16(const __nv_bfloat16* __restrict__ Ahi, const __nv_bfloat16* __restrict__ Alo,
                const __nv_bfloat16* __restrict__ Bhi, const __nv_bfloat16* __restrict__ Blo,
                float* __restrict__ C, float alpha)
{
    extern __shared__ __align__(128) char dyn[];
    const int tid  = threadIdx.x;
    const int wid  = tid >> 5;
    const int lane = tid & 31;
    const int bm = blockIdx.y * 128;
    const int bn = blockIdx.x * 128;
    const uint32_t dynb = smem_u32(dyn);

    const int wm0 = (wid >> 1) * 64;        // 2 warps in M
    const int wn0 = (wid & 1) * 64;         // 2 warps in N

    const int q = lane >> 3, l8 = lane & 7;
    const uint32_t aoff = (uint32_t)((l8 + (q & 1) * 8) * ROWB + (q >> 1) * 16);
    const uint32_t boff = (uint32_t)((l8 + (q >> 1) * 8) * ROWB + (q & 1) * 16);

    float acc[4][8][4];
#pragma unroll
    for (int mf = 0; mf < 4; mf++)
#pragma unroll
        for (int nf = 0; nf < 8; nf++)
#pragma unroll
            for (int j = 0; j < 4; j++) acc[mf][nf][j] = 0.f;

    // prologue: stages 0..3 (all in segment 0: Ahi, Bhi)
#pragma unroll
    for (int s = 0; s < 4; s++) {
        uint32_t base = dynb + s * STG_BYTES;
        ld_stage(base, base + 128 * ROWB, Ahi, Bhi, bm, bn, s * BKT, tid);
        asm volatile("cp.async.commit_group;" ::: "memory");
    }

    for (int kt = 0; kt < NKT; kt++) {
        asm volatile("cp.async.wait_group 3;" ::: "memory");
        __syncthreads();   // also guarantees compute(kt-1) finished before its buffer refill

        {
            int ktn = kt + 4;
            if (ktn < NKT) {
                int seg = ktn >> 6;
                int k0  = (ktn & 63) * BKT;
                const __nv_bfloat16* As_ = (seg < 2) ? Ahi : Alo;
                const __nv_bfloat16* Bs_ = (seg == 1) ? Blo : Bhi;
                uint32_t base = dynb + (ktn % NSTG) * STG_BYTES;
                ld_stage(base, base + 128 * ROWB, As_, Bs_, bm, bn, k0, tid);
            }
            asm volatile("cp.async.commit_group;" ::: "memory");
        }

        const uint32_t sA = dynb + (kt % NSTG) * STG_BYTES;
        const uint32_t sB = sA + 128 * ROWB;
#pragma unroll
        for (int ks = 0; ks < 2; ks++) {
            uint32_t a[4][4];
#pragma unroll
            for (int mf = 0; mf < 4; mf++)
                ldm_x4(a[mf], sA + (uint32_t)(wm0 + mf * 16) * ROWB + ks * 32 + aoff);
            uint32_t b[4][4];
#pragma unroll
            for (int p = 0; p < 4; p++)
                ldm_x4(b[p], sB + (uint32_t)(wn0 + p * 16) * ROWB + ks * 32 + boff);
#pragma unroll
            for (int mf = 0; mf < 4; mf++)
#pragma unroll
                for (int p = 0; p < 4; p++) {
                    mma16816(acc[mf][2*p],   a[mf], b[p][0], b[p][1]);
                    mma16816(acc[mf][2*p+1], a[mf], b[p][2], b[p][3]);
                }
        }
    }

    const int r0 = lane >> 2, c0 = (lane & 3) * 2;
#pragma unroll
    for (int mf = 0; mf < 4; mf++) {
        int rowa = bm + wm0 + mf * 16 + r0;
#pragma unroll
        for (int nf = 0; nf < 8; nf++) {
            int col = bn + wn0 + nf * 8 + c0;
            float2 v0 = {alpha * acc[mf][nf][0], alpha * acc[mf][nf][1]};
            float2 v1 = {alpha * acc[mf][nf][2], alpha * acc[mf][nf][3]};
            *(float2*)(C + (size_t)rowa * 2048 + col)       = v0;
            *(float2*)(C + (size_t)(rowa + 8) * 2048 + col) = v1;
        }
    }
}

// ---------------- eta / theta: sigmoid projections (N=16 each) ----------------
__global__ __launch_bounds__(256)
void eta_theta_kernel(const float* __restrict__ X, const float* __restrict__ Weta,
                      const float* __restrict__ Wth, float* __restrict__ Eta,
                      float* __restrict__ Th)
{
    __shared__ float sx[Dd];
    const int tok = blockIdx.x, tid = threadIdx.x;
    for (int i = tid; i < Dd/4; i += 256)
        *(float4*)&sx[i*4] = *(const float4*)(X + (size_t)tok*Dd + i*4);
    __syncthreads();
    const int p  = tid >> 3;
    const int l8 = tid & 7;
    const int h = p & 15, which = p >> 4;
    const float* w = (which ? Wth : Weta) + (size_t)h * Dd;
    float s = 0.f;
    for (int i = l8*4; i < Dd; i += 32) {
        float4 xv = *(float4*)&sx[i];
        float4 wv = *(const float4*)(w + i);
        s += xv.x*wv.x + xv.y*wv.y + xv.z*wv.z + xv.w*wv.w;
    }
    s += __shfl_xor_sync(0xffffffffu, s, 4);
    s += __shfl_xor_sync(0xffffffffu, s, 2);
    s += __shfl_xor_sync(0xffffffffu, s, 1);
    if (l8 == 0) {
        float sig = 1.f / (1.f + expf(-s));
        if (which) Th[(size_t)tok*Hh + h] = 0.1f * sig;
        else       Eta[(size_t)tok*Hh + h] = sig;
    }
}

// ---------------- decay prep ----------------
__global__ __launch_bounds__(256)
void decay_prep_kernel(const float* __restrict__ Eta, const float* __restrict__ Th,
                       float* __restrict__ Lec, float* __restrict__ Elec,
                       float* __restrict__ Coef)
{
    const int wc   = blockIdx.x * 8 + (threadIdx.x >> 5);   // bh*64+ct
    const int lane = threadIdx.x & 31;
    const int bh = wc >> 6, ct = wc & 63;
    const int b = bh >> 4, h = bh & 15;
    const size_t tokbase = (size_t)b * Tt;
    const int t = ct * BT + lane * 2;
    float e0  = Eta[(tokbase + t) * Hh + h];
    float e1  = Eta[(tokbase + t + 1) * Hh + h];
    float th0 = Th [(tokbase + t) * Hh + h];
    float th1 = Th [(tokbase + t + 1) * Hh + h];
    float l0 = logf(fmaxf(e0, 1e-8f));
    float l1 = logf(fmaxf(e1, 1e-8f));
    float s = l0 + l1;
#pragma unroll
    for (int o = 1; o < 32; o <<= 1) {
        float n = __shfl_up_sync(0xffffffffu, s, o);
        if (lane >= o) s += n;
    }
    float lec1 = s;
    float lec0 = s - l1;
    float ltot = __shfl_sync(0xffffffffu, s, 31);
    size_t base = (size_t)bh * Tt + t;
    float2 lv = {lec0, lec1};
    float2 ev = {expf(lec0), expf(lec1)};
    float2 cv = {expf(ltot - lec0) * th0, expf(ltot - lec1) * th1};
    *(float2*)(Lec  + base) = lv;
    *(float2*)(Elec + base) = ev;
    *(float2*)(Coef + base) = cv;
}

// ---------------- qkm: M[i][j] = (q_i.k_j)*beta(i,j)*theta_j, row-major ----------------
#define KST 130   // sK row stride (floats)
__global__ __launch_bounds__(256)
void qkm_kernel(const float* __restrict__ Q, const float* __restrict__ Kc,
                const float* __restrict__ Lec, const float* __restrict__ Th,
                float* __restrict__ Mout)
{
    extern __shared__ float qsm[];
    float* sQ   = qsm;            // 64*132
    float* sK   = sQ + 64*132;    // 64*130
    float* sLec = sK + 64*KST;    // 64
    float* sTh  = sLec + 64;      // 64

    const int blk = blockIdx.x;   // bh*64+ct
    const int bh = blk >> 6, ct = blk & 63;
    const int b = bh >> 4, h = bh & 15;
    const int tid = threadIdx.x;
    const size_t tokbase = (size_t)b * Tt;
    const int t0 = ct * BT;
    const float* Qp = Q  + tokbase*HD + (size_t)h*Kk;
    const float* Kp = Kc + tokbase*HD + (size_t)h*Kk;

#pragma unroll
    for (int i = 0; i < 8; i++) {
        int idx = tid + i*256;
        int r = idx >> 5, c = (idx & 31) << 2;
        float4 qv = *(const float4*)(Qp + (size_t)(t0+r)*HD + c);
        *(float4*)&sQ[r*132 + c] = qv;
        float4 kv = *(const float4*)(Kp + (size_t)(t0+r)*HD + c);
        float2 k01 = {kv.x, kv.y}, k23 = {kv.z, kv.w};
        *(float2*)&sK[r*KST + c]     = k01;
        *(float2*)&sK[r*KST + c + 2] = k23;
    }
    if (tid < 64) {
        sLec[tid] = Lec[(size_t)bh * Tt + t0 + tid];
        sTh[tid]  = Th[(tokbase + t0 + tid) * Hh + h];
    }
    __syncthreads();

    const int tx = tid & 15, ty = tid >> 4;
    const int i0 = ty*4;
    float acc[4][4];
#pragma unroll
    for (int i = 0; i < 4; i++)
#pragma unroll
        for (int s = 0; s < 4; s++) acc[i][s] = 0.f;
#pragma unroll 4
    for (int kk = 0; kk < Kk; kk++) {
        float kj[4], qi[4];
#pragma unroll
        for (int s = 0; s < 4; s++) kj[s] = sK[(tx + 16*s)*KST + kk];
#pragma unroll
        for (int i = 0; i < 4; i++) qi[i] = sQ[(i0+i)*132 + kk];
#pragma unroll
        for (int i = 0; i < 4; i++)
#pragma unroll
            for (int s = 0; s < 4; s++) acc[i][s] += qi[i] * kj[s];
    }
    float* Mo = Mout + (size_t)blk * (BT*BT);
#pragma unroll
    for (int i = 0; i < 4; i++) {
        int ii = i0 + i;
        float li = sLec[ii];
#pragma unroll
        for (int s = 0; s < 4; s++) {
            int jj = tx + 16*s;
            float m = 0.f;
            if (jj <= ii)
                m = acc[i][s] * expf(fminf(li - sLec[jj], 0.f)) * sTh[jj];
            Mo[ii*64 + jj] = m;
        }
    }
}

// ---------------- chunked fast-weight scan: fused kW/qW, f32x2, cp.async double-buffer ----------------
// staging buffer layout (floats): Q @0 (64*132), K @8448 (64*132), VE @16896 (64*32),
//                                 M @18944 (64*68), Elec @23296 (64), Coef @23360 (64)
#define SBUF 23424

__device__ __forceinline__ void scan_prefetch(uint32_t bufb,
    const float* __restrict__ Qp, const float* __restrict__ Kp,
    const float* __restrict__ Vp, const float* __restrict__ Mp,
    const float* __restrict__ Ep, const float* __restrict__ Cp,
    int t0, int tid)
{
#pragma unroll
    for (int i = 0; i < 8; i++) {
        int idx = tid + i*256;
        int r = idx >> 5, c = (idx & 31) << 2;
        CP16(bufb + (uint32_t)(r*132 + c)*4u,        (const void*)(Qp + (size_t)(t0+r)*HD + c));
        CP16(bufb + (uint32_t)(8448 + r*132 + c)*4u, (const void*)(Kp + (size_t)(t0+r)*HD + c));
    }
#pragma unroll
    for (int i = 0; i < 2; i++) {
        int idx = tid + i*256;
        int r = idx >> 3, c = (idx & 7) << 2;
        CP16(bufb + (uint32_t)(16896 + r*VS + c)*4u, (const void*)(Vp + (size_t)(t0+r)*HD + c));
    }
#pragma unroll
    for (int i = 0; i < 4; i++) {
        int idx = tid + i*256;
        int r = idx >> 4, c = (idx & 15) << 2;
        CP16(bufb + (uint32_t)(18944 + r*68 + c)*4u, (const void*)(Mp + (size_t)t0*64 + r*64 + c));
    }
    if (tid < 16) {
        CP16(bufb + (uint32_t)(23296 + tid*4)*4u, (const void*)(Ep + t0 + tid*4));
    } else if (tid < 32) {
        int t2 = tid - 16;
        CP16(bufb + (uint32_t)(23360 + t2*4)*4u, (const void*)(Cp + t0 + t2*4));
    }
}

__global__ __launch_bounds__(256, 1)
void scan_kernel(const float* __restrict__ Q, const float* __restrict__ Kc,
                 const float* __restrict__ Vc, const float* __restrict__ Elec,
                 const float* __restrict__ Coef, const float* __restrict__ Mg,
                 float* __restrict__ Z)
{
    extern __shared__ float sm[];
    float* sWt = sm;                      // [128][32]

    const int tid = threadIdx.x;
    const int bh  = blockIdx.x;
    const int b = bh >> 4, h = bh & 15;
    const int vs0 = blockIdx.y * VS;

    const size_t tokbase = (size_t)b * Tt;
    const float* Qp = Q  + tokbase*HD + (size_t)h*Kk;
    const float* Kp = Kc + tokbase*HD + (size_t)h*Kk;
    const float* Vp = Vc + tokbase*HD + (size_t)h*Vv + vs0;
    const float* Mp = Mg + (size_t)bh * (NT*BT*BT);
    const float* Ep = Elec + (size_t)bh*Tt;
    const float* Cp = Coef + (size_t)bh*Tt;
    float*       Zp = Z  + tokbase*HD + (size_t)h*Vv + vs0;

    for (int i = tid; i < 128*VS; i += 256) sWt[i] = 0.f;

    const uint32_t smbase = smem_u32(sm);

    // prefetch chunk 0 into buffer 0
    scan_prefetch(smbase + 4096u*4u, Qp, Kp, Vp, Mp, Ep, Cp, 0, tid);
    asm volatile("cp.async.commit_group;" ::: "memory");

    const int tx = tid & 7;               // v quad
    const int ty = tid >> 3;              // 0..31
    const int v0 = tx << 2;
    const int ta = ty*2, tb = ta + 1;     // row pair
    const int k0 = ty << 2;               // 4 k-rows for W update

    for (int ct = 0; ct < NT; ct++) {
        const int t0 = ct * BT;
        const int bi = ct & 1;
        float* bQ  = sm + 4096 + bi*SBUF;
        float* bK  = bQ + 8448;
        float* bVE = bQ + 16896;
        float* bM  = bQ + 18944;
        float* bE  = bQ + 23296;
        float* bC  = bQ + 23360;

        asm volatile("cp.async.wait_group 0;" ::: "memory");
        __syncthreads();   // staged data visible; prev chunk's readers done

        if (ct + 1 < NT)
            scan_prefetch(smbase + (4096u + (uint32_t)(1-bi)*SBUF)*4u,
                          Qp, Kp, Vp, Mp, Ep, Cp, t0 + BT, tid);
        asm volatile("cp.async.commit_group;" ::: "memory");

        // ---- Phase A: e = k@W^T - v  AND  zq = q@W^T (single W pass) ----
        u64t za01, za23, zb01, zb23;
        {
            float4 va = *(float4*)&bVE[ta*VS + v0];
            float4 vb = *(float4*)&bVE[tb*VS + v0];
            u64t ea01 = pk2(-va.x, -va.y), ea23 = pk2(-va.z, -va.w);
            u64t eb01 = pk2(-vb.x, -vb.y), eb23 = pk2(-vb.z, -vb.w);
            za01 = 0ull; za23 = 0ull; zb01 = 0ull; zb23 = 0ull;
#pragma unroll 4
            for (int kk = 0; kk < Kk; kk++) {
                double2 wd = *(double2*)&sWt[kk*VS + v0];
                u64t w01 = d2u(wd.x), w23 = d2u(wd.y);
                float ka = bK[ta*132 + kk];
                float kb = bK[tb*132 + kk];
                float qa = bQ[ta*132 + kk];
                float qb = bQ[tb*132 + kk];
                u64t ka2 = pk2(ka, ka), kb2 = pk2(kb, kb);
                u64t qa2 = pk2(qa, qa), qb2 = pk2(qb, qb);
                ea01 = fma2(ka2, w01, ea01);
                ea23 = fma2(ka2, w23, ea23);
                eb01 = fma2(kb2, w01, eb01);
                eb23 = fma2(kb2, w23, eb23);
                za01 = fma2(qa2, w01, za01);
                za23 = fma2(qa2, w23, za23);
                zb01 = fma2(qb2, w01, zb01);
                zb23 = fma2(qb2, w23, zb23);
            }
            *(double2*)&bVE[ta*VS + v0] = make_double2(u2d(ea01), u2d(ea23));
            *(double2*)&bVE[tb*VS + v0] = make_double2(u2d(eb01), u2d(eb23));
        }
        __syncthreads();

        // ---- Phase B: z = elec*zq - M@e ; Phase C accum ----
        u64t ca01[4], ca23[4];
        {
            float ea = bE[ta], eb = bE[tb];
            u64t ea2 = pk2(ea, ea), eb2 = pk2(eb, eb);
            za01 = mul2(za01, ea2); za23 = mul2(za23, ea2);
            zb01 = mul2(zb01, eb2); zb23 = mul2(zb23, eb2);
            u64t sa01 = 0ull, sa23 = 0ull, sb01 = 0ull, sb23 = 0ull;
#pragma unroll 4
            for (int j = 0; j < BT; j++) {
                double2 ed = *(double2*)&bVE[j*VS + v0];
                u64t e01 = d2u(ed.x), e23 = d2u(ed.y);
                float ma = bM[ta*68 + j];
                float mb = bM[tb*68 + j];
                u64t ma2 = pk2(ma, ma), mb2 = pk2(mb, mb);
                sa01 = fma2(ma2, e01, sa01);
                sa23 = fma2(ma2, e23, sa23);
                sb01 = fma2(mb2, e01, sb01);
                sb23 = fma2(mb2, e23, sb23);
            }
            float z0, z1, s0, s1;
            float4 oa, ob;
            upk2(za01, z0, z1); upk2(sa01, s0, s1); oa.x = z0 - s0; oa.y = z1 - s1;
            upk2(za23, z0, z1); upk2(sa23, s0, s1); oa.z = z0 - s0; oa.w = z1 - s1;
            upk2(zb01, z0, z1); upk2(sb01, s0, s1); ob.x = z0 - s0; ob.y = z1 - s1;
            upk2(zb23, z0, z1); upk2(sb23, s0, s1); ob.z = z0 - s0; ob.w = z1 - s1;
            *(float4*)(Zp + (size_t)(t0+ta)*HD + v0) = oa;
            *(float4*)(Zp + (size_t)(t0+tb)*HD + v0) = ob;
        }
        {
#pragma unroll
            for (int i = 0; i < 4; i++) { ca01[i] = 0ull; ca23[i] = 0ull; }
#pragma unroll 2
            for (int t = 0; t < BT; t++) {
                float cf = -bC[t];
                u64t cf2 = pk2(cf, cf);
                double2 ed = *(double2*)&bVE[t*VS + v0];
                u64t ce01 = mul2(d2u(ed.x), cf2);
                u64t ce23 = mul2(d2u(ed.y), cf2);
                float4 k4 = *(float4*)&bK[t*132 + k0];
                u64t k20 = pk2(k4.x, k4.x), k21 = pk2(k4.y, k4.y);
                u64t k22 = pk2(k4.z, k4.z), k23 = pk2(k4.w, k4.w);
                ca01[0] = fma2(k20, ce01, ca01[0]); ca23[0] = fma2(k20, ce23, ca23[0]);
                ca01[1] = fma2(k21, ce01, ca01[1]); ca23[1] = fma2(k21, ce23, ca23[1]);
                ca01[2] = fma2(k22, ce01, ca01[2]); ca23[2] = fma2(k22, ce23, ca23[2]);
                ca01[3] = fma2(k23, ce01, ca01[3]); ca23[3] = fma2(k23, ce23, ca23[3]);
            }
        }
        __syncthreads();   // phase A/B reads of sWt complete before update

        // ---- W update ----
        {
            float dk = bE[63];
            u64t dk2 = pk2(dk, dk);
#pragma unroll
            for (int i = 0; i < 4; i++) {
                double2 wv = *(double2*)&sWt[(k0+i)*VS + v0];
                u64t w01 = fma2(d2u(wv.x), dk2, ca01[i]);
                u64t w23 = fma2(d2u(wv.y), dk2, ca23[i]);
                *(double2*)&sWt[(k0+i)*VS + v0] = make_double2(u2d(w01), u2d(w23));
            }
        }
        __syncthreads();   // W update visible before next chunk's phase A
    }
}

// ---------------- gated RMS norm -> bf16 hi/lo split ----------------
__global__ __launch_bounds__(256)
void gated_rms_split(const float* __restrict__ Zin, const float* __restrict__ G,
                     const float* __restrict__ nw, __nv_bfloat16* __restrict__ hi,
                     __nv_bfloat16* __restrict__ lo)
{
    const int gw   = blockIdx.x * 8 + (threadIdx.x >> 5);
    const int lane = threadIdx.x & 31;
    const size_t base = (size_t)gw * 128;
    float4 zv = *(const float4*)(Zin + base + lane*4);
    float ss = zv.x*zv.x + zv.y*zv.y + zv.z*zv.z + zv.w*zv.w;
#pragma unroll
    for (int o = 16; o; o >>= 1) ss += __shfl_xor_sync(0xffffffffu, ss, o);
    float r = rsqrtf(ss * (1.f/128.f) + 1e-5f);
    float4 gv = *(const float4*)(G  + base + lane*4);
    float4 wv = *(const float4*)(nw + lane*4);
    float ov[4];
    ov[0] = zv.x*r*wv.x * (gv.x / (1.f + expf(-gv.x)));
    ov[1] = zv.y*r*wv.y * (gv.y / (1.f + expf(-gv.y)));
    ov[2] = zv.z*r*wv.z * (gv.z / (1.f + expf(-gv.z)));
    ov[3] = zv.w*r*wv.w * (gv.w / (1.f + expf(-gv.w)));
    __align__(8) __nv_bfloat16 h[4], l[4];
#pragma unroll
    for (int j = 0; j < 4; j++) {
        h[j] = __float2bfloat16(ov[j]);
        l[j] = __float2bfloat16(ov[j] - __bfloat162float(h[j]));
    }
    *(uint2*)(hi + base + lane*4) = *(uint2*)h;
    *(uint2*)(lo + base + lane*4) = *(uint2*)l;
}

// ---------------- launch ----------------
extern "C" void kernel_launch(void* const* d_in, const int* in_sizes, int n_in,
                              void* d_out, int out_size)
{
    const float* X    = (const float*)d_in[0];
    const float* Wq   = (const float*)d_in[1];
    const float* Wk   = (const float*)d_in[2];
    const float* Wv   = (const float*)d_in[3];
    const float* Weta = (const float*)d_in[4];
    const float* Wth  = (const float*)d_in[5];
    const float* Wg   = (const float*)d_in[6];
    const float* nw   = (const float*)d_in[7];
    const float* Wo   = (const float*)d_in[8];
    float* out = (float*)d_out;

    float *q, *k, *v, *g, *z, *eta, *th, *lec, *elec, *coef, *Mbuf;
    __nv_bfloat16 *xhi, *xlo, *whi, *wlo, *oghi, *oglo;
    cudaGetSymbolAddress((void**)&q,    g_q);
    cudaGetSymbolAddress((void**)&k,    g_k);
    cudaGetSymbolAddress((void**)&v,    g_v);
    cudaGetSymbolAddress((void**)&g,    g_g);
    cudaGetSymbolAddress((void**)&z,    g_z);
    cudaGetSymbolAddress((void**)&eta,  g_eta);
    cudaGetSymbolAddress((void**)&th,   g_theta);
    cudaGetSymbolAddress((void**)&lec,  g_lec);
    cudaGetSymbolAddress((void**)&elec, g_elec);
    cudaGetSymbolAddress((void**)&coef, g_coef);
    cudaGetSymbolAddress((void**)&Mbuf, g_M);
    cudaGetSymbolAddress((void**)&xhi,  g_xhi);
    cudaGetSymbolAddress((void**)&xlo,  g_xlo);
    cudaGetSymbolAddress((void**)&whi,  g_whi);
    cudaGetSymbolAddress((void**)&wlo,  g_wlo);
    cudaGetSymbolAddress((void**)&oghi, g_oghi);
    cudaGetSymbolAddress((void**)&oglo, g_oglo);

    const int scan_smem = (128*VS + 2*SBUF) * 4;   // 203776
    cudaFuncSetAttribute(scan_kernel, cudaFuncAttributeMaxDynamicSharedMemorySize, scan_smem);
    const int qkm_smem = (64*132 + 64*KST + 2*64) * 4;
    cudaFuncSetAttribute(qkm_kernel, cudaFuncAttributeMaxDynamicSharedMemorySize, qkm_smem);
    const int gemm_smem = NSTG * STG_BYTES;   // 102400
    cudaFuncSetAttribute(gemm3_bf16, cudaFuncAttributeMaxDynamicSharedMemorySize, gemm_smem);

    const int WN = Dd * Dd;

    split_bf16_kernel<<<TOKS*Dd/4/256, 256>>>(X,  xhi, xlo, TOKS*Dd/4);
    split_bf16_kernel<<<WN/4/256, 256>>>(Wq, whi + 0*(size_t)WN, wlo + 0*(size_t)WN, WN/4);
    split_bf16_kernel<<<WN/4/256, 256>>>(Wk, whi + 1*(size_t)WN, wlo + 1*(size_t)WN, WN/4);
    split_bf16_kernel<<<WN/4/256, 256>>>(Wv, whi + 2*(size_t)WN, wlo + 2*(size_t)WN, WN/4);
    split_bf16_kernel<<<WN/4/256, 256>>>(Wg, whi + 3*(size_t)WN, wlo + 3*(size_t)WN, WN/4);
    split_bf16_kernel<<<WN/4/256, 256>>>(Wo, whi + 4*(size_t)WN, wlo + 4*(size_t)WN, WN/4);

    dim3 gg(HD/128, TOKS/128);   // (16, 64)
    const float qscale = 0.08838834764831845f;  // 128^-0.5

    eta_theta_kernel<<<TOKS, 256>>>(X, Weta, Wth, eta, th);
    decay_prep_kernel<<<2048/8, 256>>>(eta, th, lec, elec, coef);

    gemm3_bf16<<<gg, 128, gemm_smem>>>(xhi, xlo, whi + 0*(size_t)WN, wlo + 0*(size_t)WN, q, qscale);
    gemm3_bf16<<<gg, 128, gemm_smem>>>(xhi, xlo, whi + 1*(size_t)WN, wlo + 1*(size_t)WN, k, 1.f);
    qkm_kernel<<<32*NT, 256, qkm_smem>>>(q, k, lec, th, Mbuf);
    gemm3_bf16<<<gg, 128, gemm_smem>>>(xhi, xlo, whi + 2*(size_t)WN, wlo + 2*(size_t)WN, v, 1.f);

    scan_kernel<<<dim3(Bb*Hh, NVS), 256, scan_smem>>>(q, k, v, elec, coef, Mbuf, z);

    gemm3_bf16<<<gg, 128, gemm_smem>>>(xhi, xlo, whi + 3*(size_t)WN, wlo + 3*(size_t)WN, g, 1.f);
    gated_rms_split<<<TOKS*Hh/8, 256>>>(z, g, nw, oghi, oglo);
    gemm3_bf16<<<gg, 128, gemm_smem>>>(oghi, oglo, whi + 4*(size_t)WN, wlo + 4*(size_t)WN, out, 1.f);
}

// round 9
// speedup vs baseline: 1.0296x; 1.0296x over previous
#include <cuda_runtime.h>
#include <cuda_bf16.h>
#include <math.h>
#include <cstdint>

// Problem constants (fixed shapes)
#define Bb 2
#define Tt 4096
#define Dd 2048
#define Hh 16
#define Kk 128
#define Vv 128
#define BT 64
#define NT 64
#define TOKS (Bb*Tt)          // 8192
#define HD   (Hh*Kk)          // 2048
#define VS   16               // v-slice width in scan
#define NVS  (Vv/VS)          // 8

// ---------------- scratch (device globals; no runtime alloc) ----------------
__device__ float g_q [TOKS*HD];
__device__ float g_k [TOKS*HD];
__device__ float g_v [TOKS*HD];
__device__ float g_g [TOKS*HD];
__device__ float g_z [TOKS*HD];
__device__ float g_eta  [TOKS*Hh];
__device__ float g_theta[TOKS*Hh];
__device__ float g_lec  [32*Tt];
__device__ float g_elec [32*Tt];
__device__ float g_coef [32*Tt];
__device__ float g_M    [32*NT*BT*BT];
__device__ __nv_bfloat16 g_xhi[TOKS*Dd];
__device__ __nv_bfloat16 g_xlo[TOKS*Dd];
__device__ __nv_bfloat16 g_whi[5*Dd*Dd];
__device__ __nv_bfloat16 g_wlo[5*Dd*Dd];
__device__ __nv_bfloat16 g_oghi[TOKS*HD];
__device__ __nv_bfloat16 g_oglo[TOKS*HD];

// ---------------- helpers ----------------
typedef unsigned long long u64t;

__device__ __forceinline__ uint32_t smem_u32(const void* p) {
    uint32_t a;
    asm("{ .reg .u64 t; cvta.to.shared.u64 t, %1; cvt.u32.u64 %0, t; }" : "=r"(a) : "l"(p));
    return a;
}
__device__ __forceinline__ void ldm_x4(uint32_t (&r)[4], uint32_t addr) {
    asm volatile("ldmatrix.sync.aligned.m8n8.x4.shared.b16 {%0,%1,%2,%3}, [%4];"
                 : "=r"(r[0]), "=r"(r[1]), "=r"(r[2]), "=r"(r[3]) : "r"(addr));
}
__device__ __forceinline__ void mma16816(float (&d)[4], const uint32_t (&a)[4],
                                         uint32_t b0, uint32_t b1) {
    asm volatile(
        "mma.sync.aligned.m16n8k16.row.col.f32.bf16.bf16.f32 "
        "{%0,%1,%2,%3}, {%4,%5,%6,%7}, {%8,%9}, {%0,%1,%2,%3};"
        : "+f"(d[0]), "+f"(d[1]), "+f"(d[2]), "+f"(d[3])
        : "r"(a[0]), "r"(a[1]), "r"(a[2]), "r"(a[3]), "r"(b0), "r"(b1));
}
// packed f32x2 (FFMA2 path)
__device__ __forceinline__ u64t pk2(float lo, float hi) {
    u64t d; asm("mov.b64 %0, {%1,%2};" : "=l"(d) : "f"(lo), "f"(hi)); return d;
}
__device__ __forceinline__ void upk2(u64t s, float& lo, float& hi) {
    asm("mov.b64 {%0,%1}, %2;" : "=f"(lo), "=f"(hi) : "l"(s));
}
__device__ __forceinline__ u64t fma2(u64t a, u64t b, u64t c) {
    u64t d; asm("fma.rn.f32x2 %0, %1, %2, %3;" : "=l"(d) : "l"(a), "l"(b), "l"(c)); return d;
}
__device__ __forceinline__ u64t mul2(u64t a, u64t b) {
    u64t d; asm("mul.rn.f32x2 %0, %1, %2;" : "=l"(d) : "l"(a), "l"(b)); return d;
}
__device__ __forceinline__ u64t d2u(double x) { return __double_as_longlong(x); }
__device__ __forceinline__ double u2d(u64t x) { return __longlong_as_double(x); }
#define CP16(dst, src) \
    asm volatile("cp.async.cg.shared.global [%0], [%1], 16;" :: "r"(dst), "l"(src) : "memory")

// ---------------- fp32 -> (hi,lo) bf16 split ----------------
__global__ __launch_bounds__(256)
void split_bf16_kernel(const float* __restrict__ x, __nv_bfloat16* __restrict__ hi,
                       __nv_bfloat16* __restrict__ lo, int n4)
{
    int i = blockIdx.x * 256 + threadIdx.x;
    if (i >= n4) return;
    float4 v = ((const float4*)x)[i];
    float vv[4] = {v.x, v.y, v.z, v.w};
    __align__(8) __nv_bfloat16 h[4], l[4];
#pragma unroll
    for (int j = 0; j < 4; j++) {
        h[j] = __float2bfloat16(vv[j]);
        l[j] = __float2bfloat16(vv[j] - __bfloat162float(h[j]));
    }
    ((uint2*)hi)[i] = *(uint2*)h;
    ((uint2*)lo)[i] = *(uint2*)l;
}

// ---------------- HMMA 3xBF16 GEMM body (R7 config) ----------------
// CTA tile 128x128, BK=32, 4-stage cp.async, 4 warps (2Mx2N), warp 64x64.
#define BKT 32
#define NKT 192                 // 3 * (2048/32)
#define ROWB 80                 // smem row stride (32 bf16 + 8 pad)
#define STG_BYTES (128*ROWB*2)  // 20480
#define NSTG 4

__device__ __forceinline__ void ld_stage(uint32_t sA, uint32_t sB,
    const __nv_bfloat16* __restrict__ A, const __nv_bfloat16* __restrict__ B,
    int bm, int bn, int k0, int tid)
{
#pragma unroll
    for (int i = 0; i < 4; i++) {
        int idx = tid + i * 128;      // 0..511
        int row = idx >> 2, c = idx & 3;
        uint32_t dA = sA + row * ROWB + c * 16;
        const void* pA = A + (size_t)(bm + row) * 2048 + k0 + c * 8;
        CP16(dA, pA);
        uint32_t dB = sB + row * ROWB + c * 16;
        const void* pB = B + (size_t)(bn + row) * 2048 + k0 + c * 8;
        CP16(dB, pB);
    }
}

__device__ __forceinline__ void gemm3_body(
    const __nv_bfloat16* __restrict__ Ahi, const __nv_bfloat16* __restrict__ Alo,
    const __nv_bfloat16* __restrict__ Bhi, const __nv_bfloat16* __restrict__ Blo,
    float* __restrict__ C, float alpha, int bm, int bn, char* dyn)
{
    const int tid  = threadIdx.x;
    const int wid  = tid >> 5;
    const int lane = tid & 31;
    const uint32_t dynb = smem_u32(dyn);

    const int wm0 = (wid >> 1) * 64;        // 2 warps in M
    const int wn0 = (wid & 1) * 64;         // 2 warps in N

    const int q = lane >> 3, l8 = lane & 7;
    const uint32_t aoff = (uint32_t)((l8 + (q & 1) * 8) * ROWB + (q >> 1) * 16);
    const uint32_t boff = (uint32_t)((l8 + (q >> 1) * 8) * ROWB + (q & 1) * 16);

    float acc[4][8][4];
#pragma unroll
    for (int mf = 0; mf < 4; mf++)
#pragma unroll
        for (int nf = 0; nf < 8; nf++)
#pragma unroll
            for (int j = 0; j < 4; j++) acc[mf][nf][j] = 0.f;

    // prologue: stages 0..2
#pragma unroll
    for (int s = 0; s < 3; s++) {
        uint32_t base = dynb + s * STG_BYTES;
        ld_stage(base, base + 128 * ROWB, Ahi, Bhi, bm, bn, s * BKT, tid);
        asm volatile("cp.async.commit_group;" ::: "memory");
    }

    for (int kt = 0; kt < NKT; kt++) {
        asm volatile("cp.async.wait_group 2;" ::: "memory");
        __syncthreads();

        {
            int ktn = kt + 3;
            if (ktn < NKT) {
                int seg = ktn >> 6;
                int k0  = (ktn & 63) * BKT;
                const __nv_bfloat16* As_ = (seg < 2) ? Ahi : Alo;
                const __nv_bfloat16* Bs_ = (seg == 1) ? Blo : Bhi;
                uint32_t base = dynb + (ktn & 3) * STG_BYTES;
                ld_stage(base, base + 128 * ROWB, As_, Bs_, bm, bn, k0, tid);
            }
            asm volatile("cp.async.commit_group;" ::: "memory");
        }

        const uint32_t sA = dynb + (kt & 3) * STG_BYTES;
        const uint32_t sB = sA + 128 * ROWB;
#pragma unroll
        for (int ks = 0; ks < 2; ks++) {
            uint32_t a[4][4];
#pragma unroll
            for (int mf = 0; mf < 4; mf++)
                ldm_x4(a[mf], sA + (uint32_t)(wm0 + mf * 16) * ROWB + ks * 32 + aoff);
            uint32_t b[4][4];
#pragma unroll
            for (int p = 0; p < 4; p++)
                ldm_x4(b[p], sB + (uint32_t)(wn0 + p * 16) * ROWB + ks * 32 + boff);
#pragma unroll
            for (int mf = 0; mf < 4; mf++)
#pragma unroll
                for (int p = 0; p < 4; p++) {
                    mma16816(acc[mf][2*p],   a[mf], b[p][0], b[p][1]);
                    mma16816(acc[mf][2*p+1], a[mf], b[p][2], b[p][3]);
                }
        }
    }

    const int r0 = lane >> 2, c0 = (lane & 3) * 2;
#pragma unroll
    for (int mf = 0; mf < 4; mf++) {
        int rowa = bm + wm0 + mf * 16 + r0;
#pragma unroll
        for (int nf = 0; nf < 8; nf++) {
            int col = bn + wn0 + nf * 8 + c0;
            float2 v0 = {alpha * acc[mf][nf][0], alpha * acc[mf][nf][1]};
            float2 v1 = {alpha * acc[mf][nf][2], alpha * acc[mf][nf][3]};
            *(float2*)(C + (size_t)rowa * 2048 + col)       = v0;
            *(float2*)(C + (size_t)(rowa + 8) * 2048 + col) = v1;
        }
    }
}

// Fused q/k/v/g projection GEMM: 4096 CTAs; weight & output selected per block.
__global__ __launch_bounds__(128, 2)
void gemm3_qkvg(const __nv_bfloat16* __restrict__ Ahi, const __nv_bfloat16* __restrict__ Alo,
                const __nv_bfloat16* __restrict__ Whi, const __nv_bfloat16* __restrict__ Wlo,
                float* __restrict__ Cq, float* __restrict__ Ck,
                float* __restrict__ Cv, float* __restrict__ Cg, float qscale)
{
    extern __shared__ __align__(128) char dyn[];
    const int sel = blockIdx.x >> 4;
    const int bn  = (blockIdx.x & 15) * 128;
    const int bm  = blockIdx.y * 128;
    const __nv_bfloat16* Bhi = Whi + (size_t)sel * Dd * Dd;
    const __nv_bfloat16* Blo = Wlo + (size_t)sel * Dd * Dd;
    float* C = (sel == 0) ? Cq : (sel == 1) ? Ck : (sel == 2) ? Cv : Cg;
    float alpha = (sel == 0) ? qscale : 1.f;
    gemm3_body(Ahi, Alo, Bhi, Blo, C, alpha, bm, bn, dyn);
}

// Single GEMM (output projection)
__global__ __launch_bounds__(128, 2)
void gemm3_bf16(const __nv_bfloat16* __restrict__ Ahi, const __nv_bfloat16* __restrict__ Alo,
                const __nv_bfloat16* __restrict__ Bhi, const __nv_bfloat16* __restrict__ Blo,
                float* __restrict__ C, float alpha)
{
    extern __shared__ __align__(128) char dyn[];
    gemm3_body(Ahi, Alo, Bhi, Blo, C, alpha, blockIdx.y * 128, blockIdx.x * 128, dyn);
}

// ---------------- eta / theta: sigmoid projections (N=16 each) ----------------
__global__ __launch_bounds__(256)
void eta_theta_kernel(const float* __restrict__ X, const float* __restrict__ Weta,
                      const float* __restrict__ Wth, float* __restrict__ Eta,
                      float* __restrict__ Th)
{
    __shared__ float sx[Dd];
    const int tok = blockIdx.x, tid = threadIdx.x;
    for (int i = tid; i < Dd/4; i += 256)
        *(float4*)&sx[i*4] = *(const float4*)(X + (size_t)tok*Dd + i*4);
    __syncthreads();
    const int p  = tid >> 3;
    const int l8 = tid & 7;
    const int h = p & 15, which = p >> 4;
    const float* w = (which ? Wth : Weta) + (size_t)h * Dd;
    float s = 0.f;
    for (int i = l8*4; i < Dd; i += 32) {
        float4 xv = *(float4*)&sx[i];
        float4 wv = *(const float4*)(w + i);
        s += xv.x*wv.x + xv.y*wv.y + xv.z*wv.z + xv.w*wv.w;
    }
    s += __shfl_xor_sync(0xffffffffu, s, 4);
    s += __shfl_xor_sync(0xffffffffu, s, 2);
    s += __shfl_xor_sync(0xffffffffu, s, 1);
    if (l8 == 0) {
        float sig = 1.f / (1.f + expf(-s));
        if (which) Th[(size_t)tok*Hh + h] = 0.1f * sig;
        else       Eta[(size_t)tok*Hh + h] = sig;
    }
}

// ---------------- decay prep ----------------
__global__ __launch_bounds__(256)
void decay_prep_kernel(const float* __restrict__ Eta, const float* __restrict__ Th,
                       float* __restrict__ Lec, float* __restrict__ Elec,
                       float* __restrict__ Coef)
{
    const int wc   = blockIdx.x * 8 + (threadIdx.x >> 5);   // bh*64+ct
    const int lane = threadIdx.x & 31;
    const int bh = wc >> 6, ct = wc & 63;
    const int b = bh >> 4, h = bh & 15;
    const size_t tokbase = (size_t)b * Tt;
    const int t = ct * BT + lane * 2;
    float e0  = Eta[(tokbase + t) * Hh + h];
    float e1  = Eta[(tokbase + t + 1) * Hh + h];
    float th0 = Th [(tokbase + t) * Hh + h];
    float th1 = Th [(tokbase + t + 1) * Hh + h];
    float l0 = logf(fmaxf(e0, 1e-8f));
    float l1 = logf(fmaxf(e1, 1e-8f));
    float s = l0 + l1;
#pragma unroll
    for (int o = 1; o < 32; o <<= 1) {
        float n = __shfl_up_sync(0xffffffffu, s, o);
        if (lane >= o) s += n;
    }
    float lec1 = s;
    float lec0 = s - l1;
    float ltot = __shfl_sync(0xffffffffu, s, 31);
    size_t base = (size_t)bh * Tt + t;
    float2 lv = {lec0, lec1};
    float2 ev = {expf(lec0), expf(lec1)};
    float2 cv = {expf(ltot - lec0) * th0, expf(ltot - lec1) * th1};
    *(float2*)(Lec  + base) = lv;
    *(float2*)(Elec + base) = ev;
    *(float2*)(Coef + base) = cv;
}

// ---------------- qkm: M[i][j] = (q_i.k_j)*beta(i,j)*theta_j, row-major ----------------
#define KST 130   // sK row stride (floats)
__global__ __launch_bounds__(256)
void qkm_kernel(const float* __restrict__ Q, const float* __restrict__ Kc,
                const float* __restrict__ Lec, const float* __restrict__ Th,
                float* __restrict__ Mout)
{
    extern __shared__ float qsm[];
    float* sQ   = qsm;            // 64*132
    float* sK   = sQ + 64*132;    // 64*130
    float* sLec = sK + 64*KST;    // 64
    float* sTh  = sLec + 64;      // 64

    const int blk = blockIdx.x;   // bh*64+ct
    const int bh = blk >> 6, ct = blk & 63;
    const int b = bh >> 4, h = bh & 15;
    const int tid = threadIdx.x;
    const size_t tokbase = (size_t)b * Tt;
    const int t0 = ct * BT;
    const float* Qp = Q  + tokbase*HD + (size_t)h*Kk;
    const float* Kp = Kc + tokbase*HD + (size_t)h*Kk;

#pragma unroll
    for (int i = 0; i < 8; i++) {
        int idx = tid + i*256;
        int r = idx >> 5, c = (idx & 31) << 2;
        float4 qv = *(const float4*)(Qp + (size_t)(t0+r)*HD + c);
        *(float4*)&sQ[r*132 + c] = qv;
        float4 kv = *(const float4*)(Kp + (size_t)(t0+r)*HD + c);
        float2 k01 = {kv.x, kv.y}, k23 = {kv.z, kv.w};
        *(float2*)&sK[r*KST + c]     = k01;
        *(float2*)&sK[r*KST + c + 2] = k23;
    }
    if (tid < 64) {
        sLec[tid] = Lec[(size_t)bh * Tt + t0 + tid];
        sTh[tid]  = Th[(tokbase + t0 + tid) * Hh + h];
    }
    __syncthreads();

    const int tx = tid & 15, ty = tid >> 4;
    const int i0 = ty*4;
    float acc[4][4];
#pragma unroll
    for (int i = 0; i < 4; i++)
#pragma unroll
        for (int s = 0; s < 4; s++) acc[i][s] = 0.f;
#pragma unroll 4
    for (int kk = 0; kk < Kk; kk++) {
        float kj[4], qi[4];
#pragma unroll
        for (int s = 0; s < 4; s++) kj[s] = sK[(tx + 16*s)*KST + kk];
#pragma unroll
        for (int i = 0; i < 4; i++) qi[i] = sQ[(i0+i)*132 + kk];
#pragma unroll
        for (int i = 0; i < 4; i++)
#pragma unroll
            for (int s = 0; s < 4; s++) acc[i][s] += qi[i] * kj[s];
    }
    float* Mo = Mout + (size_t)blk * (BT*BT);
#pragma unroll
    for (int i = 0; i < 4; i++) {
        int ii = i0 + i;
        float li = sLec[ii];
#pragma unroll
        for (int s = 0; s < 4; s++) {
            int jj = tx + 16*s;
            float m = 0.f;
            if (jj <= ii)
                m = acc[i][s] * expf(fminf(li - sLec[jj], 0.f)) * sTh[jj];
            Mo[ii*64 + jj] = m;
        }
    }
}

// ---------------- chunked fast-weight scan: VS=16, 2 CTAs/SM, fused kW/qW, f32x2 ----------------
__global__ __launch_bounds__(256, 2)
void scan_kernel(const float* __restrict__ Q, const float* __restrict__ Kc,
                 const float* __restrict__ Vc, const float* __restrict__ Elec,
                 const float* __restrict__ Coef, const float* __restrict__ Mg,
                 float* __restrict__ Z)
{
    extern __shared__ float sm[];
    float* sWt   = sm;                    // [128][16]  2048
    float* sQ    = sWt  + 128*VS;         // [64][132]  8448
    float* sK    = sQ   + 64*132;         // [64][132]  8448
    float* sVE   = sK   + 64*132;         // [64][16]   1024
    float* sM    = sVE  + 64*VS;          // [64][68]   4352
    float* sElec = sM   + 64*68;          // [64]
    float* sCoef = sElec + 64;            // [64]

    const int tid = threadIdx.x;
    const int bh  = blockIdx.x;
    const int b = bh >> 4, h = bh & 15;
    const int vs0 = blockIdx.y * VS;

    const size_t tokbase = (size_t)b * Tt;
    const float* Qp = Q  + tokbase*HD + (size_t)h*Kk;
    const float* Kp = Kc + tokbase*HD + (size_t)h*Kk;
    const float* Vp = Vc + tokbase*HD + (size_t)h*Vv + vs0;
    const float* Mp = Mg + (size_t)bh * (NT*BT*BT);
    float*       Zp = Z  + tokbase*HD + (size_t)h*Vv + vs0;

    for (int i = tid; i < 128*VS; i += 256) sWt[i] = 0.f;

    const int tx = tid & 3;               // v quad (VS=16 -> 4 quads)
    const int ty = tid >> 2;              // 0..63 (one row each)
    const int v0 = tx << 2;
    const int k0 = ty << 1;               // 2 k-rows for W update

    for (int ct = 0; ct < NT; ct++) {
        const int t0 = ct * BT;
        __syncthreads();   // protect smem from previous chunk's readers

        // ---- loads ----
#pragma unroll
        for (int i = 0; i < 8; i++) {
            int idx = tid + i*256;
            int r = idx >> 5;
            int c = (idx & 31) << 2;
            *(float4*)&sQ[r*132 + c] = *(const float4*)(Qp + (size_t)(t0+r)*HD + c);
            *(float4*)&sK[r*132 + c] = *(const float4*)(Kp + (size_t)(t0+r)*HD + c);
        }
        {   // v slice: 64 rows x 4 float4 = 256 slots
            int r = tid >> 2;
            int c = (tid & 3) << 2;
            *(float4*)&sVE[r*VS + c] = *(const float4*)(Vp + (size_t)(t0+r)*HD + c);
        }
#pragma unroll
        for (int i = 0; i < 4; i++) {
            int idx = tid + i*256;
            int r = idx >> 4;
            int c = (idx & 15) << 2;
            *(float4*)&sM[r*68 + c] = *(const float4*)(Mp + ct*(BT*BT) + r*64 + c);
        }
        if (tid < 64) {
            sElec[tid] = Elec[(size_t)bh*Tt + t0 + tid];
            sCoef[tid] = Coef[(size_t)bh*Tt + t0 + tid];
        }
        __syncthreads();

        // ---- Phase A: e = k@W^T - v  AND  zq = q@W^T (single W pass, 1 row/thread) ----
        u64t za01, za23;
        {
            float4 va = *(float4*)&sVE[ty*VS + v0];
            u64t ea01 = pk2(-va.x, -va.y), ea23 = pk2(-va.z, -va.w);
            za01 = 0ull; za23 = 0ull;
#pragma unroll 8
            for (int kk = 0; kk < Kk; kk++) {
                double2 wd = *(double2*)&sWt[kk*VS + v0];
                u64t w01 = d2u(wd.x), w23 = d2u(wd.y);
                float ka = sK[ty*132 + kk];
                float qa = sQ[ty*132 + kk];
                u64t ka2 = pk2(ka, ka), qa2 = pk2(qa, qa);
                ea01 = fma2(ka2, w01, ea01);
                ea23 = fma2(ka2, w23, ea23);
                za01 = fma2(qa2, w01, za01);
                za23 = fma2(qa2, w23, za23);
            }
            *(double2*)&sVE[ty*VS + v0] = make_double2(u2d(ea01), u2d(ea23));
        }
        __syncthreads();

        // ---- Phase B: z = elec*zq - M@e ; Phase C accum ----
        u64t ca01[2], ca23[2];
        {
            float ea = sElec[ty];
            u64t ea2 = pk2(ea, ea);
            za01 = mul2(za01, ea2); za23 = mul2(za23, ea2);
            u64t sa01 = 0ull, sa23 = 0ull;
#pragma unroll 8
            for (int j = 0; j < BT; j++) {
                double2 ed = *(double2*)&sVE[j*VS + v0];
                float ma = sM[ty*68 + j];
                u64t ma2 = pk2(ma, ma);
                sa01 = fma2(ma2, d2u(ed.x), sa01);
                sa23 = fma2(ma2, d2u(ed.y), sa23);
            }
            float z0, z1, s0, s1;
            float4 oa;
            upk2(za01, z0, z1); upk2(sa01, s0, s1); oa.x = z0 - s0; oa.y = z1 - s1;
            upk2(za23, z0, z1); upk2(sa23, s0, s1); oa.z = z0 - s0; oa.w = z1 - s1;
            *(float4*)(Zp + (size_t)(t0+ty)*HD + v0) = oa;
        }
        {
            // ca = -sum_t coef[t] * k[t][k0..k0+1] * e[t][v0..v0+3]
#pragma unroll
            for (int i = 0; i < 2; i++) { ca01[i] = 0ull; ca23[i] = 0ull; }
#pragma unroll 4
            for (int t = 0; t < BT; t++) {
                float cf = -sCoef[t];
                u64t cf2 = pk2(cf, cf);
                double2 ed = *(double2*)&sVE[t*VS + v0];
                u64t ce01 = mul2(d2u(ed.x), cf2);
                u64t ce23 = mul2(d2u(ed.y), cf2);
                float2 k2 = *(float2*)&sK[t*132 + k0];
                u64t k20 = pk2(k2.x, k2.x), k21 = pk2(k2.y, k2.y);
                ca01[0] = fma2(k20, ce01, ca01[0]); ca23[0] = fma2(k20, ce23, ca23[0]);
                ca01[1] = fma2(k21, ce01, ca01[1]); ca23[1] = fma2(k21, ce23, ca23[1]);
            }
        }
        __syncthreads();   // phase A/B reads of sWt complete before update

        // ---- W update ----
        {
            float dk = sElec[63];
            u64t dk2 = pk2(dk, dk);
#pragma unroll
            for (int i = 0; i < 2; i++) {
                double2 wv = *(double2*)&sWt[(k0+i)*VS + v0];
                u64t w01 = fma2(d2u(wv.x), dk2, ca01[i]);
                u64t w23 = fma2(d2u(wv.y), dk2, ca23[i]);
                *(double2*)&sWt[(k0+i)*VS + v0] = make_double2(u2d(w01), u2d(w23));
            }
        }
    }
}

// ---------------- gated RMS norm -> bf16 hi/lo split ----------------
__global__ __launch_bounds__(256)
void gated_rms_split(const float* __restrict__ Zin, const float* __restrict__ G,
                     const float* __restrict__ nw, __nv_bfloat16* __restrict__ hi,
                     __nv_bfloat16* __restrict__ lo)
{
    const int gw   = blockIdx.x * 8 + (threadIdx.x >> 5);
    const int lane = threadIdx.x & 31;
    const size_t base = (size_t)gw * 128;
    float4 zv = *(const float4*)(Zin + base + lane*4);
    float ss = zv.x*zv.x + zv.y*zv.y + zv.z*zv.z + zv.w*zv.w;
#pragma unroll
    for (int o = 16; o; o >>= 1) ss += __shfl_xor_sync(0xffffffffu, ss, o);
    float r = rsqrtf(ss * (1.f/128.f) + 1e-5f);
    float4 gv = *(const float4*)(G  + base + lane*4);
    float4 wv = *(const float4*)(nw + lane*4);
    float ov[4];
    ov[0] = zv.x*r*wv.x * (gv.x / (1.f + expf(-gv.x)));
    ov[1] = zv.y*r*wv.y * (gv.y / (1.f + expf(-gv.y)));
    ov[2] = zv.z*r*wv.z * (gv.z / (1.f + expf(-gv.z)));
    ov[3] = zv.w*r*wv.w * (gv.w / (1.f + expf(-gv.w)));
    __align__(8) __nv_bfloat16 h[4], l[4];
#pragma unroll
    for (int j = 0; j < 4; j++) {
        h[j] = __float2bfloat16(ov[j]);
        l[j] = __float2bfloat16(ov[j] - __bfloat162float(h[j]));
    }
    *(uint2*)(hi + base + lane*4) = *(uint2*)h;
    *(uint2*)(lo + base + lane*4) = *(uint2*)l;
}

// ---------------- launch ----------------
extern "C" void kernel_launch(void* const* d_in, const int* in_sizes, int n_in,
                              void* d_out, int out_size)
{
    const float* X    = (const float*)d_in[0];
    const float* Wq   = (const float*)d_in[1];
    const float* Wk   = (const float*)d_in[2];
    const float* Wv   = (const float*)d_in[3];
    const float* Weta = (const float*)d_in[4];
    const float* Wth  = (const float*)d_in[5];
    const float* Wg   = (const float*)d_in[6];
    const float* nw   = (const float*)d_in[7];
    const float* Wo   = (const float*)d_in[8];
    float* out = (float*)d_out;

    float *q, *k, *v, *g, *z, *eta, *th, *lec, *elec, *coef, *Mbuf;
    __nv_bfloat16 *xhi, *xlo, *whi, *wlo, *oghi, *oglo;
    cudaGetSymbolAddress((void**)&q,    g_q);
    cudaGetSymbolAddress((void**)&k,    g_k);
    cudaGetSymbolAddress((void**)&v,    g_v);
    cudaGetSymbolAddress((void**)&g,    g_g);
    cudaGetSymbolAddress((void**)&z,    g_z);
    cudaGetSymbolAddress((void**)&eta,  g_eta);
    cudaGetSymbolAddress((void**)&th,   g_theta);
    cudaGetSymbolAddress((void**)&lec,  g_lec);
    cudaGetSymbolAddress((void**)&elec, g_elec);
    cudaGetSymbolAddress((void**)&coef, g_coef);
    cudaGetSymbolAddress((void**)&Mbuf, g_M);
    cudaGetSymbolAddress((void**)&xhi,  g_xhi);
    cudaGetSymbolAddress((void**)&xlo,  g_xlo);
    cudaGetSymbolAddress((void**)&whi,  g_whi);
    cudaGetSymbolAddress((void**)&wlo,  g_wlo);
    cudaGetSymbolAddress((void**)&oghi, g_oghi);
    cudaGetSymbolAddress((void**)&oglo, g_oglo);

    const int scan_smem = (128*VS + 64*132 + 64*132 + 64*VS + 64*68 + 2*64) * 4;  // 97792
    cudaFuncSetAttribute(scan_kernel, cudaFuncAttributeMaxDynamicSharedMemorySize, scan_smem);
    const int qkm_smem = (64*132 + 64*KST + 2*64) * 4;
    cudaFuncSetAttribute(qkm_kernel, cudaFuncAttributeMaxDynamicSharedMemorySize, qkm_smem);
    const int gemm_smem = NSTG * STG_BYTES;   // 81920
    cudaFuncSetAttribute(gemm3_bf16, cudaFuncAttributeMaxDynamicSharedMemorySize, gemm_smem);
    cudaFuncSetAttribute(gemm3_qkvg, cudaFuncAttributeMaxDynamicSharedMemorySize, gemm_smem);

    const int WN = Dd * Dd;

    split_bf16_kernel<<<TOKS*Dd/4/256, 256>>>(X,  xhi, xlo, TOKS*Dd/4);
    split_bf16_kernel<<<WN/4/256, 256>>>(Wq, whi + 0*(size_t)WN, wlo + 0*(size_t)WN, WN/4);
    split_bf16_kernel<<<WN/4/256, 256>>>(Wk, whi + 1*(size_t)WN, wlo + 1*(size_t)WN, WN/4);
    split_bf16_kernel<<<WN/4/256, 256>>>(Wv, whi + 2*(size_t)WN, wlo + 2*(size_t)WN, WN/4);
    split_bf16_kernel<<<WN/4/256, 256>>>(Wg, whi + 3*(size_t)WN, wlo + 3*(size_t)WN, WN/4);
    split_bf16_kernel<<<WN/4/256, 256>>>(Wo, whi + 4*(size_t)WN, wlo + 4*(size_t)WN, WN/4);

    const float qscale = 0.08838834764831845f;  // 128^-0.5

    eta_theta_kernel<<<TOKS, 256>>>(X, Weta, Wth, eta, th);
    decay_prep_kernel<<<2048/8, 256>>>(eta, th, lec, elec, coef);

    // fused q/k/v/g projections: 4096 CTAs, minimal wave quantization
    gemm3_qkvg<<<dim3(64, TOKS/128), 128, gemm_smem>>>(xhi, xlo, whi, wlo, q, k, v, g, qscale);

    qkm_kernel<<<32*NT, 256, qkm_smem>>>(q, k, lec, th, Mbuf);

    scan_kernel<<<dim3(Bb*Hh, NVS), 256, scan_smem>>>(q, k, v, elec, coef, Mbuf, z);

    gated_rms_split<<<TOKS*Hh/8, 256>>>(z, g, nw, oghi, oglo);
    gemm3_bf16<<<dim3(HD/128, TOKS/128), 128, gemm_smem>>>(oghi, oglo, whi + 4*(size_t)WN, wlo + 4*(size_t)WN, out, 1.f);
}

// round 10
// speedup vs baseline: 1.1085x; 1.0766x over previous
#include <cuda_runtime.h>
#include <cuda_bf16.h>
#include <math.h>
#include <cstdint>

// Problem constants (fixed shapes)
#define Bb 2
#define Tt 4096
#define Dd 2048
#define Hh 16
#define Kk 128
#define Vv 128
#define BT 64
#define NT 64
#define TOKS (Bb*Tt)          // 8192
#define HD   (Hh*Kk)          // 2048
#define VS   32               // v-slice width in scan
#define NVS  (Vv/VS)          // 4

// ---------------- scratch (device globals; no runtime alloc) ----------------
__device__ float g_q [TOKS*HD];
__device__ float g_k [TOKS*HD];
__device__ float g_v [TOKS*HD];
__device__ float g_g [TOKS*HD];
__device__ float g_z [TOKS*HD];
__device__ float g_eta  [TOKS*Hh];
__device__ float g_theta[TOKS*Hh];
__device__ float g_lec  [32*Tt];
__device__ float g_elec [32*Tt];
__device__ float g_coef [32*Tt];
__device__ float g_M    [32*NT*BT*BT];
__device__ __nv_bfloat16 g_xhi[TOKS*Dd];
__device__ __nv_bfloat16 g_xlo[TOKS*Dd];
__device__ __nv_bfloat16 g_whi[5*Dd*Dd];
__device__ __nv_bfloat16 g_wlo[5*Dd*Dd];
__device__ __nv_bfloat16 g_oghi[TOKS*HD];
__device__ __nv_bfloat16 g_oglo[TOKS*HD];

// ---------------- helpers ----------------
typedef unsigned long long u64t;

__device__ __forceinline__ uint32_t smem_u32(const void* p) {
    uint32_t a;
    asm("{ .reg .u64 t; cvta.to.shared.u64 t, %1; cvt.u32.u64 %0, t; }" : "=r"(a) : "l"(p));
    return a;
}
__device__ __forceinline__ void ldm_x4(uint32_t (&r)[4], uint32_t addr) {
    asm volatile("ldmatrix.sync.aligned.m8n8.x4.shared.b16 {%0,%1,%2,%3}, [%4];"
                 : "=r"(r[0]), "=r"(r[1]), "=r"(r[2]), "=r"(r[3]) : "r"(addr));
}
__device__ __forceinline__ void mma16816(float (&d)[4], const uint32_t (&a)[4],
                                         uint32_t b0, uint32_t b1) {
    asm volatile(
        "mma.sync.aligned.m16n8k16.row.col.f32.bf16.bf16.f32 "
        "{%0,%1,%2,%3}, {%4,%5,%6,%7}, {%8,%9}, {%0,%1,%2,%3};"
        : "+f"(d[0]), "+f"(d[1]), "+f"(d[2]), "+f"(d[3])
        : "r"(a[0]), "r"(a[1]), "r"(a[2]), "r"(a[3]), "r"(b0), "r"(b1));
}
// packed f32x2 (FFMA2 path)
__device__ __forceinline__ u64t pk2(float lo, float hi) {
    u64t d; asm("mov.b64 %0, {%1,%2};" : "=l"(d) : "f"(lo), "f"(hi)); return d;
}
__device__ __forceinline__ void upk2(u64t s, float& lo, float& hi) {
    asm("mov.b64 {%0,%1}, %2;" : "=f"(lo), "=f"(hi) : "l"(s));
}
__device__ __forceinline__ u64t fma2(u64t a, u64t b, u64t c) {
    u64t d; asm("fma.rn.f32x2 %0, %1, %2, %3;" : "=l"(d) : "l"(a), "l"(b), "l"(c)); return d;
}
__device__ __forceinline__ u64t mul2(u64t a, u64t b) {
    u64t d; asm("mul.rn.f32x2 %0, %1, %2;" : "=l"(d) : "l"(a), "l"(b)); return d;
}
__device__ __forceinline__ u64t d2u(double x) { return __double_as_longlong(x); }
__device__ __forceinline__ double u2d(u64t x) { return __longlong_as_double(x); }
#define CP16(dst, src) \
    asm volatile("cp.async.cg.shared.global [%0], [%1], 16;" :: "r"(dst), "l"(src) : "memory")

// ---------------- fp32 -> (hi,lo) bf16 split ----------------
__global__ __launch_bounds__(256)
void split_bf16_kernel(const float* __restrict__ x, __nv_bfloat16* __restrict__ hi,
                       __nv_bfloat16* __restrict__ lo, int n4)
{
    int i = blockIdx.x * 256 + threadIdx.x;
    if (i >= n4) return;
    float4 v = ((const float4*)x)[i];
    float vv[4] = {v.x, v.y, v.z, v.w};
    __align__(8) __nv_bfloat16 h[4], l[4];
#pragma unroll
    for (int j = 0; j < 4; j++) {
        h[j] = __float2bfloat16(vv[j]);
        l[j] = __float2bfloat16(vv[j] - __bfloat162float(h[j]));
    }
    ((uint2*)hi)[i] = *(uint2*)h;
    ((uint2*)lo)[i] = *(uint2*)l;
}

// ---------------- HMMA 3xBF16 GEMM body (R7 config) ----------------
// CTA tile 128x128, BK=32, 4-stage cp.async, 4 warps (2Mx2N), warp 64x64.
#define BKT 32
#define NKT 192                 // 3 * (2048/32)
#define ROWB 80                 // smem row stride (32 bf16 + 8 pad)
#define STG_BYTES (128*ROWB*2)  // 20480
#define NSTG 4

__device__ __forceinline__ void ld_stage(uint32_t sA, uint32_t sB,
    const __nv_bfloat16* __restrict__ A, const __nv_bfloat16* __restrict__ B,
    int bm, int bn, int k0, int tid)
{
#pragma unroll
    for (int i = 0; i < 4; i++) {
        int idx = tid + i * 128;      // 0..511
        int row = idx >> 2, c = idx & 3;
        uint32_t dA = sA + row * ROWB + c * 16;
        const void* pA = A + (size_t)(bm + row) * 2048 + k0 + c * 8;
        CP16(dA, pA);
        uint32_t dB = sB + row * ROWB + c * 16;
        const void* pB = B + (size_t)(bn + row) * 2048 + k0 + c * 8;
        CP16(dB, pB);
    }
}

__device__ __forceinline__ void gemm3_body(
    const __nv_bfloat16* __restrict__ Ahi, const __nv_bfloat16* __restrict__ Alo,
    const __nv_bfloat16* __restrict__ Bhi, const __nv_bfloat16* __restrict__ Blo,
    float* __restrict__ C, float alpha, int bm, int bn, char* dyn)
{
    const int tid  = threadIdx.x;
    const int wid  = tid >> 5;
    const int lane = tid & 31;
    const uint32_t dynb = smem_u32(dyn);

    const int wm0 = (wid >> 1) * 64;        // 2 warps in M
    const int wn0 = (wid & 1) * 64;         // 2 warps in N

    const int q = lane >> 3, l8 = lane & 7;
    const uint32_t aoff = (uint32_t)((l8 + (q & 1) * 8) * ROWB + (q >> 1) * 16);
    const uint32_t boff = (uint32_t)((l8 + (q >> 1) * 8) * ROWB + (q & 1) * 16);

    float acc[4][8][4];
#pragma unroll
    for (int mf = 0; mf < 4; mf++)
#pragma unroll
        for (int nf = 0; nf < 8; nf++)
#pragma unroll
            for (int j = 0; j < 4; j++) acc[mf][nf][j] = 0.f;

    // prologue: stages 0..2
#pragma unroll
    for (int s = 0; s < 3; s++) {
        uint32_t base = dynb + s * STG_BYTES;
        ld_stage(base, base + 128 * ROWB, Ahi, Bhi, bm, bn, s * BKT, tid);
        asm volatile("cp.async.commit_group;" ::: "memory");
    }

    for (int kt = 0; kt < NKT; kt++) {
        asm volatile("cp.async.wait_group 2;" ::: "memory");
        __syncthreads();

        {
            int ktn = kt + 3;
            if (ktn < NKT) {
                int seg = ktn >> 6;
                int k0  = (ktn & 63) * BKT;
                const __nv_bfloat16* As_ = (seg < 2) ? Ahi : Alo;
                const __nv_bfloat16* Bs_ = (seg == 1) ? Blo : Bhi;
                uint32_t base = dynb + (ktn & 3) * STG_BYTES;
                ld_stage(base, base + 128 * ROWB, As_, Bs_, bm, bn, k0, tid);
            }
            asm volatile("cp.async.commit_group;" ::: "memory");
        }

        const uint32_t sA = dynb + (kt & 3) * STG_BYTES;
        const uint32_t sB = sA + 128 * ROWB;
#pragma unroll
        for (int ks = 0; ks < 2; ks++) {
            uint32_t a[4][4];
#pragma unroll
            for (int mf = 0; mf < 4; mf++)
                ldm_x4(a[mf], sA + (uint32_t)(wm0 + mf * 16) * ROWB + ks * 32 + aoff);
            uint32_t b[4][4];
#pragma unroll
            for (int p = 0; p < 4; p++)
                ldm_x4(b[p], sB + (uint32_t)(wn0 + p * 16) * ROWB + ks * 32 + boff);
#pragma unroll
            for (int mf = 0; mf < 4; mf++)
#pragma unroll
                for (int p = 0; p < 4; p++) {
                    mma16816(acc[mf][2*p],   a[mf], b[p][0], b[p][1]);
                    mma16816(acc[mf][2*p+1], a[mf], b[p][2], b[p][3]);
                }
        }
    }

    const int r0 = lane >> 2, c0 = (lane & 3) * 2;
#pragma unroll
    for (int mf = 0; mf < 4; mf++) {
        int rowa = bm + wm0 + mf * 16 + r0;
#pragma unroll
        for (int nf = 0; nf < 8; nf++) {
            int col = bn + wn0 + nf * 8 + c0;
            float2 v0 = {alpha * acc[mf][nf][0], alpha * acc[mf][nf][1]};
            float2 v1 = {alpha * acc[mf][nf][2], alpha * acc[mf][nf][3]};
            *(float2*)(C + (size_t)rowa * 2048 + col)       = v0;
            *(float2*)(C + (size_t)(rowa + 8) * 2048 + col) = v1;
        }
    }
}

// Fused q/k/v/g projection GEMM: 4096 CTAs; weight & output selected per block.
__global__ __launch_bounds__(128, 2)
void gemm3_qkvg(const __nv_bfloat16* __restrict__ Ahi, const __nv_bfloat16* __restrict__ Alo,
                const __nv_bfloat16* __restrict__ Whi, const __nv_bfloat16* __restrict__ Wlo,
                float* __restrict__ Cq, float* __restrict__ Ck,
                float* __restrict__ Cv, float* __restrict__ Cg, float qscale)
{
    extern __shared__ __align__(128) char dyn[];
    const int sel = blockIdx.x >> 4;
    const int bn  = (blockIdx.x & 15) * 128;
    const int bm  = blockIdx.y * 128;
    const __nv_bfloat16* Bhi = Whi + (size_t)sel * Dd * Dd;
    const __nv_bfloat16* Blo = Wlo + (size_t)sel * Dd * Dd;
    float* C = (sel == 0) ? Cq : (sel == 1) ? Ck : (sel == 2) ? Cv : Cg;
    float alpha = (sel == 0) ? qscale : 1.f;
    gemm3_body(Ahi, Alo, Bhi, Blo, C, alpha, bm, bn, dyn);
}

// Single GEMM (output projection)
__global__ __launch_bounds__(128, 2)
void gemm3_bf16(const __nv_bfloat16* __restrict__ Ahi, const __nv_bfloat16* __restrict__ Alo,
                const __nv_bfloat16* __restrict__ Bhi, const __nv_bfloat16* __restrict__ Blo,
                float* __restrict__ C, float alpha)
{
    extern __shared__ __align__(128) char dyn[];
    gemm3_body(Ahi, Alo, Bhi, Blo, C, alpha, blockIdx.y * 128, blockIdx.x * 128, dyn);
}

// ---------------- eta / theta: sigmoid projections (N=16 each) ----------------
__global__ __launch_bounds__(256)
void eta_theta_kernel(const float* __restrict__ X, const float* __restrict__ Weta,
                      const float* __restrict__ Wth, float* __restrict__ Eta,
                      float* __restrict__ Th)
{
    __shared__ float sx[Dd];
    const int tok = blockIdx.x, tid = threadIdx.x;
    for (int i = tid; i < Dd/4; i += 256)
        *(float4*)&sx[i*4] = *(const float4*)(X + (size_t)tok*Dd + i*4);
    __syncthreads();
    const int p  = tid >> 3;
    const int l8 = tid & 7;
    const int h = p & 15, which = p >> 4;
    const float* w = (which ? Wth : Weta) + (size_t)h * Dd;
    float s = 0.f;
    for (int i = l8*4; i < Dd; i += 32) {
        float4 xv = *(float4*)&sx[i];
        float4 wv = *(const float4*)(w + i);
        s += xv.x*wv.x + xv.y*wv.y + xv.z*wv.z + xv.w*wv.w;
    }
    s += __shfl_xor_sync(0xffffffffu, s, 4);
    s += __shfl_xor_sync(0xffffffffu, s, 2);
    s += __shfl_xor_sync(0xffffffffu, s, 1);
    if (l8 == 0) {
        float sig = 1.f / (1.f + expf(-s));
        if (which) Th[(size_t)tok*Hh + h] = 0.1f * sig;
        else       Eta[(size_t)tok*Hh + h] = sig;
    }
}

// ---------------- decay prep ----------------
__global__ __launch_bounds__(256)
void decay_prep_kernel(const float* __restrict__ Eta, const float* __restrict__ Th,
                       float* __restrict__ Lec, float* __restrict__ Elec,
                       float* __restrict__ Coef)
{
    const int wc   = blockIdx.x * 8 + (threadIdx.x >> 5);   // bh*64+ct
    const int lane = threadIdx.x & 31;
    const int bh = wc >> 6, ct = wc & 63;
    const int b = bh >> 4, h = bh & 15;
    const size_t tokbase = (size_t)b * Tt;
    const int t = ct * BT + lane * 2;
    float e0  = Eta[(tokbase + t) * Hh + h];
    float e1  = Eta[(tokbase + t + 1) * Hh + h];
    float th0 = Th [(tokbase + t) * Hh + h];
    float th1 = Th [(tokbase + t + 1) * Hh + h];
    float l0 = logf(fmaxf(e0, 1e-8f));
    float l1 = logf(fmaxf(e1, 1e-8f));
    float s = l0 + l1;
#pragma unroll
    for (int o = 1; o < 32; o <<= 1) {
        float n = __shfl_up_sync(0xffffffffu, s, o);
        if (lane >= o) s += n;
    }
    float lec1 = s;
    float lec0 = s - l1;
    float ltot = __shfl_sync(0xffffffffu, s, 31);
    size_t base = (size_t)bh * Tt + t;
    float2 lv = {lec0, lec1};
    float2 ev = {expf(lec0), expf(lec1)};
    float2 cv = {expf(ltot - lec0) * th0, expf(ltot - lec1) * th1};
    *(float2*)(Lec  + base) = lv;
    *(float2*)(Elec + base) = ev;
    *(float2*)(Coef + base) = cv;
}

// ---------------- qkm: M[i][j] = (q_i.k_j)*beta(i,j)*theta_j, row-major ----------------
#define KST 130   // sK row stride (floats)
__global__ __launch_bounds__(256)
void qkm_kernel(const float* __restrict__ Q, const float* __restrict__ Kc,
                const float* __restrict__ Lec, const float* __restrict__ Th,
                float* __restrict__ Mout)
{
    extern __shared__ float qsm[];
    float* sQ   = qsm;            // 64*132
    float* sK   = sQ + 64*132;    // 64*130
    float* sLec = sK + 64*KST;    // 64
    float* sTh  = sLec + 64;      // 64

    const int blk = blockIdx.x;   // bh*64+ct
    const int bh = blk >> 6, ct = blk & 63;
    const int b = bh >> 4, h = bh & 15;
    const int tid = threadIdx.x;
    const size_t tokbase = (size_t)b * Tt;
    const int t0 = ct * BT;
    const float* Qp = Q  + tokbase*HD + (size_t)h*Kk;
    const float* Kp = Kc + tokbase*HD + (size_t)h*Kk;

#pragma unroll
    for (int i = 0; i < 8; i++) {
        int idx = tid + i*256;
        int r = idx >> 5, c = (idx & 31) << 2;
        float4 qv = *(const float4*)(Qp + (size_t)(t0+r)*HD + c);
        *(float4*)&sQ[r*132 + c] = qv;
        float4 kv = *(const float4*)(Kp + (size_t)(t0+r)*HD + c);
        float2 k01 = {kv.x, kv.y}, k23 = {kv.z, kv.w};
        *(float2*)&sK[r*KST + c]     = k01;
        *(float2*)&sK[r*KST + c + 2] = k23;
    }
    if (tid < 64) {
        sLec[tid] = Lec[(size_t)bh * Tt + t0 + tid];
        sTh[tid]  = Th[(tokbase + t0 + tid) * Hh + h];
    }
    __syncthreads();

    const int tx = tid & 15, ty = tid >> 4;
    const int i0 = ty*4;
    float acc[4][4];
#pragma unroll
    for (int i = 0; i < 4; i++)
#pragma unroll
        for (int s = 0; s < 4; s++) acc[i][s] = 0.f;
#pragma unroll 4
    for (int kk = 0; kk < Kk; kk++) {
        float kj[4], qi[4];
#pragma unroll
        for (int s = 0; s < 4; s++) kj[s] = sK[(tx + 16*s)*KST + kk];
#pragma unroll
        for (int i = 0; i < 4; i++) qi[i] = sQ[(i0+i)*132 + kk];
#pragma unroll
        for (int i = 0; i < 4; i++)
#pragma unroll
            for (int s = 0; s < 4; s++) acc[i][s] += qi[i] * kj[s];
    }
    float* Mo = Mout + (size_t)blk * (BT*BT);
#pragma unroll
    for (int i = 0; i < 4; i++) {
        int ii = i0 + i;
        float li = sLec[ii];
#pragma unroll
        for (int s = 0; s < 4; s++) {
            int jj = tx + 16*s;
            float m = 0.f;
            if (jj <= ii)
                m = acc[i][s] * expf(fminf(li - sLec[jj], 0.f)) * sTh[jj];
            Mo[ii*64 + jj] = m;
        }
    }
}

// ---------------- chunked fast-weight scan: VS=32, fused kW/qW pass, f32x2 (R7) ----------------
__global__ __launch_bounds__(256, 1)
void scan_kernel(const float* __restrict__ Q, const float* __restrict__ Kc,
                 const float* __restrict__ Vc, const float* __restrict__ Elec,
                 const float* __restrict__ Coef, const float* __restrict__ Mg,
                 float* __restrict__ Z)
{
    extern __shared__ float sm[];
    float* sWt   = sm;                    // [128][32]  W^T slice
    float* sQ    = sWt  + 128*VS;         // [64][132]
    float* sK    = sQ   + 64*132;         // [64][132]
    float* sVE   = sK   + 64*132;         // [64][32]
    float* sM    = sVE  + 64*VS;          // [64][68]
    float* sElec = sM   + 64*68;          // [64]
    float* sCoef = sElec + 64;            // [64]

    const int tid = threadIdx.x;
    const int bh  = blockIdx.x;
    const int b = bh >> 4, h = bh & 15;
    const int vs0 = blockIdx.y * VS;

    const size_t tokbase = (size_t)b * Tt;
    const float* Qp = Q  + tokbase*HD + (size_t)h*Kk;
    const float* Kp = Kc + tokbase*HD + (size_t)h*Kk;
    const float* Vp = Vc + tokbase*HD + (size_t)h*Vv + vs0;
    const float* Mp = Mg + (size_t)bh * (NT*BT*BT);
    float*       Zp = Z  + tokbase*HD + (size_t)h*Vv + vs0;

    for (int i = tid; i < 128*VS; i += 256) sWt[i] = 0.f;

    const int tx = tid & 7;               // v quad
    const int ty = tid >> 3;              // 0..31
    const int v0 = tx << 2;
    const int ta = ty*2, tb = ta + 1;     // row pair
    const int k0 = ty << 2;               // 4 k-rows for W update

    for (int ct = 0; ct < NT; ct++) {
        const int t0 = ct * BT;
        __syncthreads();

        // ---- loads ----
#pragma unroll
        for (int i = 0; i < 8; i++) {
            int idx = tid + i*256;
            int r = idx >> 5;
            int c = (idx & 31) << 2;
            *(float4*)&sQ[r*132 + c] = *(const float4*)(Qp + (size_t)(t0+r)*HD + c);
            *(float4*)&sK[r*132 + c] = *(const float4*)(Kp + (size_t)(t0+r)*HD + c);
        }
#pragma unroll
        for (int i = 0; i < 2; i++) {
            int idx = tid + i*256;
            int r = idx >> 3;
            int c = (idx & 7) << 2;
            *(float4*)&sVE[r*VS + c] = *(const float4*)(Vp + (size_t)(t0+r)*HD + c);
        }
#pragma unroll
        for (int i = 0; i < 4; i++) {
            int idx = tid + i*256;
            int r = idx >> 4;
            int c = (idx & 15) << 2;
            *(float4*)&sM[r*68 + c] = *(const float4*)(Mp + ct*(BT*BT) + r*64 + c);
        }
        if (tid < 64) {
            sElec[tid] = Elec[(size_t)bh*Tt + t0 + tid];
            sCoef[tid] = Coef[(size_t)bh*Tt + t0 + tid];
        }
        __syncthreads();

        // ---- Phase A: e = k@W^T - v  AND  zq = q@W^T (single W pass) ----
        u64t za01, za23, zb01, zb23;
        {
            float4 va = *(float4*)&sVE[ta*VS + v0];
            float4 vb = *(float4*)&sVE[tb*VS + v0];
            u64t ea01 = pk2(-va.x, -va.y), ea23 = pk2(-va.z, -va.w);
            u64t eb01 = pk2(-vb.x, -vb.y), eb23 = pk2(-vb.z, -vb.w);
            za01 = 0ull; za23 = 0ull; zb01 = 0ull; zb23 = 0ull;
#pragma unroll 4
            for (int kk = 0; kk < Kk; kk++) {
                double2 wd = *(double2*)&sWt[kk*VS + v0];
                u64t w01 = d2u(wd.x), w23 = d2u(wd.y);
                float ka = sK[ta*132 + kk];
                float kb = sK[tb*132 + kk];
                float qa = sQ[ta*132 + kk];
                float qb = sQ[tb*132 + kk];
                u64t ka2 = pk2(ka, ka), kb2 = pk2(kb, kb);
                u64t qa2 = pk2(qa, qa), qb2 = pk2(qb, qb);
                ea01 = fma2(ka2, w01, ea01);
                ea23 = fma2(ka2, w23, ea23);
                eb01 = fma2(kb2, w01, eb01);
                eb23 = fma2(kb2, w23, eb23);
                za01 = fma2(qa2, w01, za01);
                za23 = fma2(qa2, w23, za23);
                zb01 = fma2(qb2, w01, zb01);
                zb23 = fma2(qb2, w23, zb23);
            }
            *(double2*)&sVE[ta*VS + v0] = make_double2(u2d(ea01), u2d(ea23));
            *(double2*)&sVE[tb*VS + v0] = make_double2(u2d(eb01), u2d(eb23));
        }
        __syncthreads();

        // ---- Phase B: z = elec*zq - M@e ; Phase C accum ----
        u64t ca01[4], ca23[4];
        {
            float ea = sElec[ta], eb = sElec[tb];
            u64t ea2 = pk2(ea, ea), eb2 = pk2(eb, eb);
            za01 = mul2(za01, ea2); za23 = mul2(za23, ea2);
            zb01 = mul2(zb01, eb2); zb23 = mul2(zb23, eb2);
            u64t sa01 = 0ull, sa23 = 0ull, sb01 = 0ull, sb23 = 0ull;
#pragma unroll 4
            for (int j = 0; j < BT; j++) {
                double2 ed = *(double2*)&sVE[j*VS + v0];
                u64t e01 = d2u(ed.x), e23 = d2u(ed.y);
                float ma = sM[ta*68 + j];
                float mb = sM[tb*68 + j];
                u64t ma2 = pk2(ma, ma), mb2 = pk2(mb, mb);
                sa01 = fma2(ma2, e01, sa01);
                sa23 = fma2(ma2, e23, sa23);
                sb01 = fma2(mb2, e01, sb01);
                sb23 = fma2(mb2, e23, sb23);
            }
            float z0, z1, s0, s1;
            float4 oa, ob;
            upk2(za01, z0, z1); upk2(sa01, s0, s1); oa.x = z0 - s0; oa.y = z1 - s1;
            upk2(za23, z0, z1); upk2(sa23, s0, s1); oa.z = z0 - s0; oa.w = z1 - s1;
            upk2(zb01, z0, z1); upk2(sb01, s0, s1); ob.x = z0 - s0; ob.y = z1 - s1;
            upk2(zb23, z0, z1); upk2(sb23, s0, s1); ob.z = z0 - s0; ob.w = z1 - s1;
            *(float4*)(Zp + (size_t)(t0+ta)*HD + v0) = oa;
            *(float4*)(Zp + (size_t)(t0+tb)*HD + v0) = ob;
        }
        {
#pragma unroll
            for (int i = 0; i < 4; i++) { ca01[i] = 0ull; ca23[i] = 0ull; }
#pragma unroll 2
            for (int t = 0; t < BT; t++) {
                float cf = -sCoef[t];
                u64t cf2 = pk2(cf, cf);
                double2 ed = *(double2*)&sVE[t*VS + v0];
                u64t ce01 = mul2(d2u(ed.x), cf2);
                u64t ce23 = mul2(d2u(ed.y), cf2);
                float4 k4 = *(float4*)&sK[t*132 + k0];
                u64t k20 = pk2(k4.x, k4.x), k21 = pk2(k4.y, k4.y);
                u64t k22 = pk2(k4.z, k4.z), k23 = pk2(k4.w, k4.w);
                ca01[0] = fma2(k20, ce01, ca01[0]); ca23[0] = fma2(k20, ce23, ca23[0]);
                ca01[1] = fma2(k21, ce01, ca01[1]); ca23[1] = fma2(k21, ce23, ca23[1]);
                ca01[2] = fma2(k22, ce01, ca01[2]); ca23[2] = fma2(k22, ce23, ca23[2]);
                ca01[3] = fma2(k23, ce01, ca01[3]); ca23[3] = fma2(k23, ce23, ca23[3]);
            }
        }
        __syncthreads();

        // ---- W update ----
        {
            float dk = sElec[63];
            u64t dk2 = pk2(dk, dk);
#pragma unroll
            for (int i = 0; i < 4; i++) {
                double2 wv = *(double2*)&sWt[(k0+i)*VS + v0];
                u64t w01 = fma2(d2u(wv.x), dk2, ca01[i]);
                u64t w23 = fma2(d2u(wv.y), dk2, ca23[i]);
                *(double2*)&sWt[(k0+i)*VS + v0] = make_double2(u2d(w01), u2d(w23));
            }
        }
    }
}

// ---------------- gated RMS norm -> bf16 hi/lo split ----------------
__global__ __launch_bounds__(256)
void gated_rms_split(const float* __restrict__ Zin, const float* __restrict__ G,
                     const float* __restrict__ nw, __nv_bfloat16* __restrict__ hi,
                     __nv_bfloat16* __restrict__ lo)
{
    const int gw   = blockIdx.x * 8 + (threadIdx.x >> 5);
    const int lane = threadIdx.x & 31;
    const size_t base = (size_t)gw * 128;
    float4 zv = *(const float4*)(Zin + base + lane*4);
    float ss = zv.x*zv.x + zv.y*zv.y + zv.z*zv.z + zv.w*zv.w;
#pragma unroll
    for (int o = 16; o; o >>= 1) ss += __shfl_xor_sync(0xffffffffu, ss, o);
    float r = rsqrtf(ss * (1.f/128.f) + 1e-5f);
    float4 gv = *(const float4*)(G  + base + lane*4);
    float4 wv = *(const float4*)(nw + lane*4);
    float ov[4];
    ov[0] = zv.x*r*wv.x * (gv.x / (1.f + expf(-gv.x)));
    ov[1] = zv.y*r*wv.y * (gv.y / (1.f + expf(-gv.y)));
    ov[2] = zv.z*r*wv.z * (gv.z / (1.f + expf(-gv.z)));
    ov[3] = zv.w*r*wv.w * (gv.w / (1.f + expf(-gv.w)));
    __align__(8) __nv_bfloat16 h[4], l[4];
#pragma unroll
    for (int j = 0; j < 4; j++) {
        h[j] = __float2bfloat16(ov[j]);
        l[j] = __float2bfloat16(ov[j] - __bfloat162float(h[j]));
    }
    *(uint2*)(hi + base + lane*4) = *(uint2*)h;
    *(uint2*)(lo + base + lane*4) = *(uint2*)l;
}

// ---------------- launch ----------------
extern "C" void kernel_launch(void* const* d_in, const int* in_sizes, int n_in,
                              void* d_out, int out_size)
{
    const float* X    = (const float*)d_in[0];
    const float* Wq   = (const float*)d_in[1];
    const float* Wk   = (const float*)d_in[2];
    const float* Wv   = (const float*)d_in[3];
    const float* Weta = (const float*)d_in[4];
    const float* Wth  = (const float*)d_in[5];
    const float* Wg   = (const float*)d_in[6];
    const float* nw   = (const float*)d_in[7];
    const float* Wo   = (const float*)d_in[8];
    float* out = (float*)d_out;

    float *q, *k, *v, *g, *z, *eta, *th, *lec, *elec, *coef, *Mbuf;
    __nv_bfloat16 *xhi, *xlo, *whi, *wlo, *oghi, *oglo;
    cudaGetSymbolAddress((void**)&q,    g_q);
    cudaGetSymbolAddress((void**)&k,    g_k);
    cudaGetSymbolAddress((void**)&v,    g_v);
    cudaGetSymbolAddress((void**)&g,    g_g);
    cudaGetSymbolAddress((void**)&z,    g_z);
    cudaGetSymbolAddress((void**)&eta,  g_eta);
    cudaGetSymbolAddress((void**)&th,   g_theta);
    cudaGetSymbolAddress((void**)&lec,  g_lec);
    cudaGetSymbolAddress((void**)&elec, g_elec);
    cudaGetSymbolAddress((void**)&coef, g_coef);
    cudaGetSymbolAddress((void**)&Mbuf, g_M);
    cudaGetSymbolAddress((void**)&xhi,  g_xhi);
    cudaGetSymbolAddress((void**)&xlo,  g_xlo);
    cudaGetSymbolAddress((void**)&whi,  g_whi);
    cudaGetSymbolAddress((void**)&wlo,  g_wlo);
    cudaGetSymbolAddress((void**)&oghi, g_oghi);
    cudaGetSymbolAddress((void**)&oglo, g_oglo);

    const int scan_smem = (128*VS + 64*132 + 64*132 + 64*VS + 64*68 + 2*64) * 4;
    cudaFuncSetAttribute(scan_kernel, cudaFuncAttributeMaxDynamicSharedMemorySize, scan_smem);
    const int qkm_smem = (64*132 + 64*KST + 2*64) * 4;
    cudaFuncSetAttribute(qkm_kernel, cudaFuncAttributeMaxDynamicSharedMemorySize, qkm_smem);
    const int gemm_smem = NSTG * STG_BYTES;   // 81920
    cudaFuncSetAttribute(gemm3_bf16, cudaFuncAttributeMaxDynamicSharedMemorySize, gemm_smem);
    cudaFuncSetAttribute(gemm3_qkvg, cudaFuncAttributeMaxDynamicSharedMemorySize, gemm_smem);

    const int WN = Dd * Dd;

    split_bf16_kernel<<<TOKS*Dd/4/256, 256>>>(X,  xhi, xlo, TOKS*Dd/4);
    split_bf16_kernel<<<WN/4/256, 256>>>(Wq, whi + 0*(size_t)WN, wlo + 0*(size_t)WN, WN/4);
    split_bf16_kernel<<<WN/4/256, 256>>>(Wk, whi + 1*(size_t)WN, wlo + 1*(size_t)WN, WN/4);
    split_bf16_kernel<<<WN/4/256, 256>>>(Wv, whi + 2*(size_t)WN, wlo + 2*(size_t)WN, WN/4);
    split_bf16_kernel<<<WN/4/256, 256>>>(Wg, whi + 3*(size_t)WN, wlo + 3*(size_t)WN, WN/4);
    split_bf16_kernel<<<WN/4/256, 256>>>(Wo, whi + 4*(size_t)WN, wlo + 4*(size_t)WN, WN/4);

    const float qscale = 0.08838834764831845f;  // 128^-0.5

    eta_theta_kernel<<<TOKS, 256>>>(X, Weta, Wth, eta, th);
    decay_prep_kernel<<<2048/8, 256>>>(eta, th, lec, elec, coef);

    // fused q/k/v/g projections: 4096 CTAs, minimal wave quantization
    gemm3_qkvg<<<dim3(64, TOKS/128), 128, gemm_smem>>>(xhi, xlo, whi, wlo, q, k, v, g, qscale);

    qkm_kernel<<<32*NT, 256, qkm_smem>>>(q, k, lec, th, Mbuf);

    scan_kernel<<<dim3(Bb*Hh, NVS), 256, scan_smem>>>(q, k, v, elec, coef, Mbuf, z);

    gated_rms_split<<<TOKS*Hh/8, 256>>>(z, g, nw, oghi, oglo);
    gemm3_bf16<<<dim3(HD/128, TOKS/128), 128, gemm_smem>>>(oghi, oglo, whi + 4*(size_t)WN, wlo + 4*(size_t)WN, out, 1.f);
}

// round 11
// speedup vs baseline: 1.4379x; 1.2971x over previous
#include <cuda_runtime.h>
#include <cuda_fp16.h>
#include <math.h>
#include <cstdint>

// Problem constants (fixed shapes)
#define Bb 2
#define Tt 4096
#define Dd 2048
#define Hh 16
#define Kk 128
#define Vv 128
#define BT 64
#define NT 64
#define TOKS (Bb*Tt)          // 8192
#define HD   (Hh*Kk)          // 2048
#define VS   32               // v-slice width in scan
#define NVS  (Vv/VS)          // 4

// ---------------- scratch (device globals; no runtime alloc) ----------------
__device__ float g_q [TOKS*HD];
__device__ float g_k [TOKS*HD];
__device__ float g_v [TOKS*HD];
__device__ float g_g [TOKS*HD];
__device__ float g_z [TOKS*HD];
__device__ float g_eta  [TOKS*Hh];
__device__ float g_theta[TOKS*Hh];
__device__ float g_lec  [32*Tt];
__device__ float g_elec [32*Tt];
__device__ float g_coef [32*Tt];
__device__ float g_M    [32*NT*BT*BT];
__device__ __half g_xhi[TOKS*Dd];
__device__ __half g_xlo[TOKS*Dd];
__device__ __half g_w16[5*Dd*Dd];
__device__ __half g_oghi[TOKS*HD];
__device__ __half g_oglo[TOKS*HD];

// ---------------- helpers ----------------
typedef unsigned long long u64t;

__device__ __forceinline__ uint32_t smem_u32(const void* p) {
    uint32_t a;
    asm("{ .reg .u64 t; cvta.to.shared.u64 t, %1; cvt.u32.u64 %0, t; }" : "=r"(a) : "l"(p));
    return a;
}
__device__ __forceinline__ void ldm_x4(uint32_t (&r)[4], uint32_t addr) {
    asm volatile("ldmatrix.sync.aligned.m8n8.x4.shared.b16 {%0,%1,%2,%3}, [%4];"
                 : "=r"(r[0]), "=r"(r[1]), "=r"(r[2]), "=r"(r[3]) : "r"(addr));
}
__device__ __forceinline__ void mma16816(float (&d)[4], const uint32_t (&a)[4],
                                         uint32_t b0, uint32_t b1) {
    asm volatile(
        "mma.sync.aligned.m16n8k16.row.col.f32.f16.f16.f32 "
        "{%0,%1,%2,%3}, {%4,%5,%6,%7}, {%8,%9}, {%0,%1,%2,%3};"
        : "+f"(d[0]), "+f"(d[1]), "+f"(d[2]), "+f"(d[3])
        : "r"(a[0]), "r"(a[1]), "r"(a[2]), "r"(a[3]), "r"(b0), "r"(b1));
}
// packed f32x2 (FFMA2 path)
__device__ __forceinline__ u64t pk2(float lo, float hi) {
    u64t d; asm("mov.b64 %0, {%1,%2};" : "=l"(d) : "f"(lo), "f"(hi)); return d;
}
__device__ __forceinline__ void upk2(u64t s, float& lo, float& hi) {
    asm("mov.b64 {%0,%1}, %2;" : "=f"(lo), "=f"(hi) : "l"(s));
}
__device__ __forceinline__ u64t fma2(u64t a, u64t b, u64t c) {
    u64t d; asm("fma.rn.f32x2 %0, %1, %2, %3;" : "=l"(d) : "l"(a), "l"(b), "l"(c)); return d;
}
__device__ __forceinline__ u64t mul2(u64t a, u64t b) {
    u64t d; asm("mul.rn.f32x2 %0, %1, %2;" : "=l"(d) : "l"(a), "l"(b)); return d;
}
__device__ __forceinline__ u64t d2u(double x) { return __double_as_longlong(x); }
__device__ __forceinline__ double u2d(u64t x) { return __longlong_as_double(x); }
#define CP16(dst, src) \
    asm volatile("cp.async.cg.shared.global [%0], [%1], 16;" :: "r"(dst), "l"(src) : "memory")

// ---------------- fp32 -> (hi,lo) fp16 split (activations) ----------------
__global__ __launch_bounds__(256)
void split_fp16_kernel(const float* __restrict__ x, __half* __restrict__ hi,
                       __half* __restrict__ lo, int n4)
{
    int i = blockIdx.x * 256 + threadIdx.x;
    if (i >= n4) return;
    float4 v = ((const float4*)x)[i];
    float vv[4] = {v.x, v.y, v.z, v.w};
    __align__(8) __half h[4], l[4];
#pragma unroll
    for (int j = 0; j < 4; j++) {
        h[j] = __float2half(vv[j]);
        l[j] = __float2half(vv[j] - __half2float(h[j]));
    }
    ((uint2*)hi)[i] = *(uint2*)h;
    ((uint2*)lo)[i] = *(uint2*)l;
}

// ---------------- fp32 -> fp16 convert (weights) ----------------
__global__ __launch_bounds__(256)
void conv_fp16_kernel(const float* __restrict__ x, __half* __restrict__ w, int n4)
{
    int i = blockIdx.x * 256 + threadIdx.x;
    if (i >= n4) return;
    float4 v = ((const float4*)x)[i];
    __align__(8) __half h[4];
    h[0] = __float2half(v.x); h[1] = __float2half(v.y);
    h[2] = __float2half(v.z); h[3] = __float2half(v.w);
    ((uint2*)w)[i] = *(uint2*)h;
}

// ---------------- HMMA 2xFP16 GEMM body ----------------
// C = alpha * (Ahi + Alo) @ B^T.  2 K-segments of 2048. CTA tile 128x128, BK=32,
// 4-stage cp.async, 4 warps (2Mx2N), warp 64x64.
#define BKT 32
#define NKT 128                 // 2 * (2048/32)
#define ROWB 80                 // smem row stride (32 fp16 + 8 pad)
#define STG_BYTES (128*ROWB*2)  // 20480
#define NSTG 4

__device__ __forceinline__ void ld_stage(uint32_t sA, uint32_t sB,
    const __half* __restrict__ A, const __half* __restrict__ B,
    int bm, int bn, int k0, int tid)
{
#pragma unroll
    for (int i = 0; i < 4; i++) {
        int idx = tid + i * 128;      // 0..511
        int row = idx >> 2, c = idx & 3;
        uint32_t dA = sA + row * ROWB + c * 16;
        const void* pA = A + (size_t)(bm + row) * 2048 + k0 + c * 8;
        CP16(dA, pA);
        uint32_t dB = sB + row * ROWB + c * 16;
        const void* pB = B + (size_t)(bn + row) * 2048 + k0 + c * 8;
        CP16(dB, pB);
    }
}

__device__ __forceinline__ void gemm2_body(
    const __half* __restrict__ Ahi, const __half* __restrict__ Alo,
    const __half* __restrict__ B,
    float* __restrict__ C, float alpha, int bm, int bn, char* dyn)
{
    const int tid  = threadIdx.x;
    const int wid  = tid >> 5;
    const int lane = tid & 31;
    const uint32_t dynb = smem_u32(dyn);

    const int wm0 = (wid >> 1) * 64;        // 2 warps in M
    const int wn0 = (wid & 1) * 64;         // 2 warps in N

    const int q = lane >> 3, l8 = lane & 7;
    const uint32_t aoff = (uint32_t)((l8 + (q & 1) * 8) * ROWB + (q >> 1) * 16);
    const uint32_t boff = (uint32_t)((l8 + (q >> 1) * 8) * ROWB + (q & 1) * 16);

    float acc[4][8][4];
#pragma unroll
    for (int mf = 0; mf < 4; mf++)
#pragma unroll
        for (int nf = 0; nf < 8; nf++)
#pragma unroll
            for (int j = 0; j < 4; j++) acc[mf][nf][j] = 0.f;

    // prologue: stages 0..2 (segment 0: Ahi)
#pragma unroll
    for (int s = 0; s < 3; s++) {
        uint32_t base = dynb + s * STG_BYTES;
        ld_stage(base, base + 128 * ROWB, Ahi, B, bm, bn, s * BKT, tid);
        asm volatile("cp.async.commit_group;" ::: "memory");
    }

    for (int kt = 0; kt < NKT; kt++) {
        asm volatile("cp.async.wait_group 2;" ::: "memory");
        __syncthreads();

        {
            int ktn = kt + 3;
            if (ktn < NKT) {
                int seg = ktn >> 6;
                int k0  = (ktn & 63) * BKT;
                const __half* As_ = seg ? Alo : Ahi;
                uint32_t base = dynb + (ktn & 3) * STG_BYTES;
                ld_stage(base, base + 128 * ROWB, As_, B, bm, bn, k0, tid);
            }
            asm volatile("cp.async.commit_group;" ::: "memory");
        }

        const uint32_t sA = dynb + (kt & 3) * STG_BYTES;
        const uint32_t sB = sA + 128 * ROWB;
#pragma unroll
        for (int ks = 0; ks < 2; ks++) {
            uint32_t a[4][4];
#pragma unroll
            for (int mf = 0; mf < 4; mf++)
                ldm_x4(a[mf], sA + (uint32_t)(wm0 + mf * 16) * ROWB + ks * 32 + aoff);
            uint32_t b[4][4];
#pragma unroll
            for (int p = 0; p < 4; p++)
                ldm_x4(b[p], sB + (uint32_t)(wn0 + p * 16) * ROWB + ks * 32 + boff);
#pragma unroll
            for (int mf = 0; mf < 4; mf++)
#pragma unroll
                for (int p = 0; p < 4; p++) {
                    mma16816(acc[mf][2*p],   a[mf], b[p][0], b[p][1]);
                    mma16816(acc[mf][2*p+1], a[mf], b[p][2], b[p][3]);
                }
        }
    }

    const int r0 = lane >> 2, c0 = (lane & 3) * 2;
#pragma unroll
    for (int mf = 0; mf < 4; mf++) {
        int rowa = bm + wm0 + mf * 16 + r0;
#pragma unroll
        for (int nf = 0; nf < 8; nf++) {
            int col = bn + wn0 + nf * 8 + c0;
            float2 v0 = {alpha * acc[mf][nf][0], alpha * acc[mf][nf][1]};
            float2 v1 = {alpha * acc[mf][nf][2], alpha * acc[mf][nf][3]};
            *(float2*)(C + (size_t)rowa * 2048 + col)       = v0;
            *(float2*)(C + (size_t)(rowa + 8) * 2048 + col) = v1;
        }
    }
}

// Fused q/k/v/g projection GEMM: 4096 CTAs; weight & output selected per block.
__global__ __launch_bounds__(128, 2)
void gemm2_qkvg(const __half* __restrict__ Ahi, const __half* __restrict__ Alo,
                const __half* __restrict__ W,
                float* __restrict__ Cq, float* __restrict__ Ck,
                float* __restrict__ Cv, float* __restrict__ Cg, float qscale)
{
    extern __shared__ __align__(128) char dyn[];
    const int sel = blockIdx.x >> 4;
    const int bn  = (blockIdx.x & 15) * 128;
    const int bm  = blockIdx.y * 128;
    const __half* B = W + (size_t)sel * Dd * Dd;
    float* C = (sel == 0) ? Cq : (sel == 1) ? Ck : (sel == 2) ? Cv : Cg;
    float alpha = (sel == 0) ? qscale : 1.f;
    gemm2_body(Ahi, Alo, B, C, alpha, bm, bn, dyn);
}

// Single GEMM (output projection)
__global__ __launch_bounds__(128, 2)
void gemm2_f16(const __half* __restrict__ Ahi, const __half* __restrict__ Alo,
               const __half* __restrict__ B, float* __restrict__ C, float alpha)
{
    extern __shared__ __align__(128) char dyn[];
    gemm2_body(Ahi, Alo, B, C, alpha, blockIdx.y * 128, blockIdx.x * 128, dyn);
}

// ---------------- eta / theta: sigmoid projections (N=16 each) ----------------
__global__ __launch_bounds__(256)
void eta_theta_kernel(const float* __restrict__ X, const float* __restrict__ Weta,
                      const float* __restrict__ Wth, float* __restrict__ Eta,
                      float* __restrict__ Th)
{
    __shared__ float sx[Dd];
    const int tok = blockIdx.x, tid = threadIdx.x;
    for (int i = tid; i < Dd/4; i += 256)
        *(float4*)&sx[i*4] = *(const float4*)(X + (size_t)tok*Dd + i*4);
    __syncthreads();
    const int p  = tid >> 3;
    const int l8 = tid & 7;
    const int h = p & 15, which = p >> 4;
    const float* w = (which ? Wth : Weta) + (size_t)h * Dd;
    float s = 0.f;
    for (int i = l8*4; i < Dd; i += 32) {
        float4 xv = *(float4*)&sx[i];
        float4 wv = *(const float4*)(w + i);
        s += xv.x*wv.x + xv.y*wv.y + xv.z*wv.z + xv.w*wv.w;
    }
    s += __shfl_xor_sync(0xffffffffu, s, 4);
    s += __shfl_xor_sync(0xffffffffu, s, 2);
    s += __shfl_xor_sync(0xffffffffu, s, 1);
    if (l8 == 0) {
        float sig = 1.f / (1.f + expf(-s));
        if (which) Th[(size_t)tok*Hh + h] = 0.1f * sig;
        else       Eta[(size_t)tok*Hh + h] = sig;
    }
}

// ---------------- decay prep ----------------
__global__ __launch_bounds__(256)
void decay_prep_kernel(const float* __restrict__ Eta, const float* __restrict__ Th,
                       float* __restrict__ Lec, float* __restrict__ Elec,
                       float* __restrict__ Coef)
{
    const int wc   = blockIdx.x * 8 + (threadIdx.x >> 5);   // bh*64+ct
    const int lane = threadIdx.x & 31;
    const int bh = wc >> 6, ct = wc & 63;
    const int b = bh >> 4, h = bh & 15;
    const size_t tokbase = (size_t)b * Tt;
    const int t = ct * BT + lane * 2;
    float e0  = Eta[(tokbase + t) * Hh + h];
    float e1  = Eta[(tokbase + t + 1) * Hh + h];
    float th0 = Th [(tokbase + t) * Hh + h];
    float th1 = Th [(tokbase + t + 1) * Hh + h];
    float l0 = logf(fmaxf(e0, 1e-8f));
    float l1 = logf(fmaxf(e1, 1e-8f));
    float s = l0 + l1;
#pragma unroll
    for (int o = 1; o < 32; o <<= 1) {
        float n = __shfl_up_sync(0xffffffffu, s, o);
        if (lane >= o) s += n;
    }
    float lec1 = s;
    float lec0 = s - l1;
    float ltot = __shfl_sync(0xffffffffu, s, 31);
    size_t base = (size_t)bh * Tt + t;
    float2 lv = {lec0, lec1};
    float2 ev = {expf(lec0), expf(lec1)};
    float2 cv = {expf(ltot - lec0) * th0, expf(ltot - lec1) * th1};
    *(float2*)(Lec  + base) = lv;
    *(float2*)(Elec + base) = ev;
    *(float2*)(Coef + base) = cv;
}

// ---------------- qkm: M[i][j] = (q_i.k_j)*beta(i,j)*theta_j, row-major ----------------
#define KST 130   // sK row stride (floats)
__global__ __launch_bounds__(256)
void qkm_kernel(const float* __restrict__ Q, const float* __restrict__ Kc,
                const float* __restrict__ Lec, const float* __restrict__ Th,
                float* __restrict__ Mout)
{
    extern __shared__ float qsm[];
    float* sQ   = qsm;            // 64*132
    float* sK   = sQ + 64*132;    // 64*130
    float* sLec = sK + 64*KST;    // 64
    float* sTh  = sLec + 64;      // 64

    const int blk = blockIdx.x;   // bh*64+ct
    const int bh = blk >> 6, ct = blk & 63;
    const int b = bh >> 4, h = bh & 15;
    const int tid = threadIdx.x;
    const size_t tokbase = (size_t)b * Tt;
    const int t0 = ct * BT;
    const float* Qp = Q  + tokbase*HD + (size_t)h*Kk;
    const float* Kp = Kc + tokbase*HD + (size_t)h*Kk;

#pragma unroll
    for (int i = 0; i < 8; i++) {
        int idx = tid + i*256;
        int r = idx >> 5, c = (idx & 31) << 2;
        float4 qv = *(const float4*)(Qp + (size_t)(t0+r)*HD + c);
        *(float4*)&sQ[r*132 + c] = qv;
        float4 kv = *(const float4*)(Kp + (size_t)(t0+r)*HD + c);
        float2 k01 = {kv.x, kv.y}, k23 = {kv.z, kv.w};
        *(float2*)&sK[r*KST + c]     = k01;
        *(float2*)&sK[r*KST + c + 2] = k23;
    }
    if (tid < 64) {
        sLec[tid] = Lec[(size_t)bh * Tt + t0 + tid];
        sTh[tid]  = Th[(tokbase + t0 + tid) * Hh + h];
    }
    __syncthreads();

    const int tx = tid & 15, ty = tid >> 4;
    const int i0 = ty*4;
    float acc[4][4];
#pragma unroll
    for (int i = 0; i < 4; i++)
#pragma unroll
        for (int s = 0; s < 4; s++) acc[i][s] = 0.f;
#pragma unroll 4
    for (int kk = 0; kk < Kk; kk++) {
        float kj[4], qi[4];
#pragma unroll
        for (int s = 0; s < 4; s++) kj[s] = sK[(tx + 16*s)*KST + kk];
#pragma unroll
        for (int i = 0; i < 4; i++) qi[i] = sQ[(i0+i)*132 + kk];
#pragma unroll
        for (int i = 0; i < 4; i++)
#pragma unroll
            for (int s = 0; s < 4; s++) acc[i][s] += qi[i] * kj[s];
    }
    float* Mo = Mout + (size_t)blk * (BT*BT);
#pragma unroll
    for (int i = 0; i < 4; i++) {
        int ii = i0 + i;
        float li = sLec[ii];
#pragma unroll
        for (int s = 0; s < 4; s++) {
            int jj = tx + 16*s;
            float m = 0.f;
            if (jj <= ii)
                m = acc[i][s] * expf(fminf(li - sLec[jj], 0.f)) * sTh[jj];
            Mo[ii*64 + jj] = m;
        }
    }
}

// ---------------- chunked fast-weight scan: VS=32, fused kW/qW pass, f32x2 ----------------
__global__ __launch_bounds__(256, 1)
void scan_kernel(const float* __restrict__ Q, const float* __restrict__ Kc,
                 const float* __restrict__ Vc, const float* __restrict__ Elec,
                 const float* __restrict__ Coef, const float* __restrict__ Mg,
                 float* __restrict__ Z)
{
    extern __shared__ float sm[];
    float* sWt   = sm;                    // [128][32]  W^T slice
    float* sQ    = sWt  + 128*VS;         // [64][132]
    float* sK    = sQ   + 64*132;         // [64][132]
    float* sVE   = sK   + 64*132;         // [64][32]
    float* sM    = sVE  + 64*VS;          // [64][68]
    float* sElec = sM   + 64*68;          // [64]
    float* sCoef = sElec + 64;            // [64]

    const int tid = threadIdx.x;
    const int bh  = blockIdx.x;
    const int b = bh >> 4, h = bh & 15;
    const int vs0 = blockIdx.y * VS;

    const size_t tokbase = (size_t)b * Tt;
    const float* Qp = Q  + tokbase*HD + (size_t)h*Kk;
    const float* Kp = Kc + tokbase*HD + (size_t)h*Kk;
    const float* Vp = Vc + tokbase*HD + (size_t)h*Vv + vs0;
    const float* Mp = Mg + (size_t)bh * (NT*BT*BT);
    float*       Zp = Z  + tokbase*HD + (size_t)h*Vv + vs0;

    for (int i = tid; i < 128*VS; i += 256) sWt[i] = 0.f;

    const int tx = tid & 7;               // v quad
    const int ty = tid >> 3;              // 0..31
    const int v0 = tx << 2;
    const int ta = ty*2, tb = ta + 1;     // row pair
    const int k0 = ty << 2;               // 4 k-rows for W update

    for (int ct = 0; ct < NT; ct++) {
        const int t0 = ct * BT;
        __syncthreads();

        // ---- loads ----
#pragma unroll
        for (int i = 0; i < 8; i++) {
            int idx = tid + i*256;
            int r = idx >> 5;
            int c = (idx & 31) << 2;
            *(float4*)&sQ[r*132 + c] = *(const float4*)(Qp + (size_t)(t0+r)*HD + c);
            *(float4*)&sK[r*132 + c] = *(const float4*)(Kp + (size_t)(t0+r)*HD + c);
        }
#pragma unroll
        for (int i = 0; i < 2; i++) {
            int idx = tid + i*256;
            int r = idx >> 3;
            int c = (idx & 7) << 2;
            *(float4*)&sVE[r*VS + c] = *(const float4*)(Vp + (size_t)(t0+r)*HD + c);
        }
#pragma unroll
        for (int i = 0; i < 4; i++) {
            int idx = tid + i*256;
            int r = idx >> 4;
            int c = (idx & 15) << 2;
            *(float4*)&sM[r*68 + c] = *(const float4*)(Mp + ct*(BT*BT) + r*64 + c);
        }
        if (tid < 64) {
            sElec[tid] = Elec[(size_t)bh*Tt + t0 + tid];
            sCoef[tid] = Coef[(size_t)bh*Tt + t0 + tid];
        }
        __syncthreads();

        // ---- Phase A: e = k@W^T - v  AND  zq = q@W^T (single W pass) ----
        u64t za01, za23, zb01, zb23;
        {
            float4 va = *(float4*)&sVE[ta*VS + v0];
            float4 vb = *(float4*)&sVE[tb*VS + v0];
            u64t ea01 = pk2(-va.x, -va.y), ea23 = pk2(-va.z, -va.w);
            u64t eb01 = pk2(-vb.x, -vb.y), eb23 = pk2(-vb.z, -vb.w);
            za01 = 0ull; za23 = 0ull; zb01 = 0ull; zb23 = 0ull;
#pragma unroll 4
            for (int kk = 0; kk < Kk; kk++) {
                double2 wd = *(double2*)&sWt[kk*VS + v0];
                u64t w01 = d2u(wd.x), w23 = d2u(wd.y);
                float ka = sK[ta*132 + kk];
                float kb = sK[tb*132 + kk];
                float qa = sQ[ta*132 + kk];
                float qb = sQ[tb*132 + kk];
                u64t ka2 = pk2(ka, ka), kb2 = pk2(kb, kb);
                u64t qa2 = pk2(qa, qa), qb2 = pk2(qb, qb);
                ea01 = fma2(ka2, w01, ea01);
                ea23 = fma2(ka2, w23, ea23);
                eb01 = fma2(kb2, w01, eb01);
                eb23 = fma2(kb2, w23, eb23);
                za01 = fma2(qa2, w01, za01);
                za23 = fma2(qa2, w23, za23);
                zb01 = fma2(qb2, w01, zb01);
                zb23 = fma2(qb2, w23, zb23);
            }
            *(double2*)&sVE[ta*VS + v0] = make_double2(u2d(ea01), u2d(ea23));
            *(double2*)&sVE[tb*VS + v0] = make_double2(u2d(eb01), u2d(eb23));
        }
        __syncthreads();

        // ---- Phase B: z = elec*zq - M@e ; Phase C accum ----
        u64t ca01[4], ca23[4];
        {
            float ea = sElec[ta], eb = sElec[tb];
            u64t ea2 = pk2(ea, ea), eb2 = pk2(eb, eb);
            za01 = mul2(za01, ea2); za23 = mul2(za23, ea2);
            zb01 = mul2(zb01, eb2); zb23 = mul2(zb23, eb2);
            u64t sa01 = 0ull, sa23 = 0ull, sb01 = 0ull, sb23 = 0ull;
#pragma unroll 4
            for (int j = 0; j < BT; j++) {
                double2 ed = *(double2*)&sVE[j*VS + v0];
                u64t e01 = d2u(ed.x), e23 = d2u(ed.y);
                float ma = sM[ta*68 + j];
                float mb = sM[tb*68 + j];
                u64t ma2 = pk2(ma, ma), mb2 = pk2(mb, mb);
                sa01 = fma2(ma2, e01, sa01);
                sa23 = fma2(ma2, e23, sa23);
                sb01 = fma2(mb2, e01, sb01);
                sb23 = fma2(mb2, e23, sb23);
            }
            float z0, z1, s0, s1;
            float4 oa, ob;
            upk2(za01, z0, z1); upk2(sa01, s0, s1); oa.x = z0 - s0; oa.y = z1 - s1;
            upk2(za23, z0, z1); upk2(sa23, s0, s1); oa.z = z0 - s0; oa.w = z1 - s1;
            upk2(zb01, z0, z1); upk2(sb01, s0, s1); ob.x = z0 - s0; ob.y = z1 - s1;
            upk2(zb23, z0, z1); upk2(sb23, s0, s1); ob.z = z0 - s0; ob.w = z1 - s1;
            *(float4*)(Zp + (size_t)(t0+ta)*HD + v0) = oa;
            *(float4*)(Zp + (size_t)(t0+tb)*HD + v0) = ob;
        }
        {
#pragma unroll
            for (int i = 0; i < 4; i++) { ca01[i] = 0ull; ca23[i] = 0ull; }
#pragma unroll 2
            for (int t = 0; t < BT; t++) {
                float cf = -sCoef[t];
                u64t cf2 = pk2(cf, cf);
                double2 ed = *(double2*)&sVE[t*VS + v0];
                u64t ce01 = mul2(d2u(ed.x), cf2);
                u64t ce23 = mul2(d2u(ed.y), cf2);
                float4 k4 = *(float4*)&sK[t*132 + k0];
                u64t k20 = pk2(k4.x, k4.x), k21 = pk2(k4.y, k4.y);
                u64t k22 = pk2(k4.z, k4.z), k23 = pk2(k4.w, k4.w);
                ca01[0] = fma2(k20, ce01, ca01[0]); ca23[0] = fma2(k20, ce23, ca23[0]);
                ca01[1] = fma2(k21, ce01, ca01[1]); ca23[1] = fma2(k21, ce23, ca23[1]);
                ca01[2] = fma2(k22, ce01, ca01[2]); ca23[2] = fma2(k22, ce23, ca23[2]);
                ca01[3] = fma2(k23, ce01, ca01[3]); ca23[3] = fma2(k23, ce23, ca23[3]);
            }
        }
        __syncthreads();

        // ---- W update ----
        {
            float dk = sElec[63];
            u64t dk2 = pk2(dk, dk);
#pragma unroll
            for (int i = 0; i < 4; i++) {
                double2 wv = *(double2*)&sWt[(k0+i)*VS + v0];
                u64t w01 = fma2(d2u(wv.x), dk2, ca01[i]);
                u64t w23 = fma2(d2u(wv.y), dk2, ca23[i]);
                *(double2*)&sWt[(k0+i)*VS + v0] = make_double2(u2d(w01), u2d(w23));
            }
        }
    }
}

// ---------------- gated RMS norm -> fp16 hi/lo split ----------------
__global__ __launch_bounds__(256)
void gated_rms_split(const float* __restrict__ Zin, const float* __restrict__ G,
                     const float* __restrict__ nw, __half* __restrict__ hi,
                     __half* __restrict__ lo)
{
    const int gw   = blockIdx.x * 8 + (threadIdx.x >> 5);
    const int lane = threadIdx.x & 31;
    const size_t base = (size_t)gw * 128;
    float4 zv = *(const float4*)(Zin + base + lane*4);
    float ss = zv.x*zv.x + zv.y*zv.y + zv.z*zv.z + zv.w*zv.w;
#pragma unroll
    for (int o = 16; o; o >>= 1) ss += __shfl_xor_sync(0xffffffffu, ss, o);
    float r = rsqrtf(ss * (1.f/128.f) + 1e-5f);
    float4 gv = *(const float4*)(G  + base + lane*4);
    float4 wv = *(const float4*)(nw + lane*4);
    float ov[4];
    ov[0] = zv.x*r*wv.x * (gv.x / (1.f + expf(-gv.x)));
    ov[1] = zv.y*r*wv.y * (gv.y / (1.f + expf(-gv.y)));
    ov[2] = zv.z*r*wv.z * (gv.z / (1.f + expf(-gv.z)));
    ov[3] = zv.w*r*wv.w * (gv.w / (1.f + expf(-gv.w)));
    __align__(8) __half h[4], l[4];
#pragma unroll
    for (int j = 0; j < 4; j++) {
        h[j] = __float2half(ov[j]);
        l[j] = __float2half(ov[j] - __half2float(h[j]));
    }
    *(uint2*)(hi + base + lane*4) = *(uint2*)h;
    *(uint2*)(lo + base + lane*4) = *(uint2*)l;
}

// ---------------- launch ----------------
extern "C" void kernel_launch(void* const* d_in, const int* in_sizes, int n_in,
                              void* d_out, int out_size)
{
    const float* X    = (const float*)d_in[0];
    const float* Wq   = (const float*)d_in[1];
    const float* Wk   = (const float*)d_in[2];
    const float* Wv   = (const float*)d_in[3];
    const float* Weta = (const float*)d_in[4];
    const float* Wth  = (const float*)d_in[5];
    const float* Wg   = (const float*)d_in[6];
    const float* nw   = (const float*)d_in[7];
    const float* Wo   = (const float*)d_in[8];
    float* out = (float*)d_out;

    float *q, *k, *v, *g, *z, *eta, *th, *lec, *elec, *coef, *Mbuf;
    __half *xhi, *xlo, *w16, *oghi, *oglo;
    cudaGetSymbolAddress((void**)&q,    g_q);
    cudaGetSymbolAddress((void**)&k,    g_k);
    cudaGetSymbolAddress((void**)&v,    g_v);
    cudaGetSymbolAddress((void**)&g,    g_g);
    cudaGetSymbolAddress((void**)&z,    g_z);
    cudaGetSymbolAddress((void**)&eta,  g_eta);
    cudaGetSymbolAddress((void**)&th,   g_theta);
    cudaGetSymbolAddress((void**)&lec,  g_lec);
    cudaGetSymbolAddress((void**)&elec, g_elec);
    cudaGetSymbolAddress((void**)&coef, g_coef);
    cudaGetSymbolAddress((void**)&Mbuf, g_M);
    cudaGetSymbolAddress((void**)&xhi,  g_xhi);
    cudaGetSymbolAddress((void**)&xlo,  g_xlo);
    cudaGetSymbolAddress((void**)&w16,  g_w16);
    cudaGetSymbolAddress((void**)&oghi, g_oghi);
    cudaGetSymbolAddress((void**)&oglo, g_oglo);

    const int scan_smem = (128*VS + 64*132 + 64*132 + 64*VS + 64*68 + 2*64) * 4;
    cudaFuncSetAttribute(scan_kernel, cudaFuncAttributeMaxDynamicSharedMemorySize, scan_smem);
    const int qkm_smem = (64*132 + 64*KST + 2*64) * 4;
    cudaFuncSetAttribute(qkm_kernel, cudaFuncAttributeMaxDynamicSharedMemorySize, qkm_smem);
    const int gemm_smem = NSTG * STG_BYTES;   // 81920
    cudaFuncSetAttribute(gemm2_f16, cudaFuncAttributeMaxDynamicSharedMemorySize, gemm_smem);
    cudaFuncSetAttribute(gemm2_qkvg, cudaFuncAttributeMaxDynamicSharedMemorySize, gemm_smem);

    const int WN = Dd * Dd;

    split_fp16_kernel<<<TOKS*Dd/4/256, 256>>>(X, xhi, xlo, TOKS*Dd/4);
    conv_fp16_kernel<<<WN/4/256, 256>>>(Wq, w16 + 0*(size_t)WN, WN/4);
    conv_fp16_kernel<<<WN/4/256, 256>>>(Wk, w16 + 1*(size_t)WN, WN/4);
    conv_fp16_kernel<<<WN/4/256, 256>>>(Wv, w16 + 2*(size_t)WN, WN/4);
    conv_fp16_kernel<<<WN/4/256, 256>>>(Wg, w16 + 3*(size_t)WN, WN/4);
    conv_fp16_kernel<<<WN/4/256, 256>>>(Wo, w16 + 4*(size_t)WN, WN/4);

    const float qscale = 0.08838834764831845f;  // 128^-0.5

    eta_theta_kernel<<<TOKS, 256>>>(X, Weta, Wth, eta, th);
    decay_prep_kernel<<<2048/8, 256>>>(eta, th, lec, elec, coef);

    // fused q/k/v/g projections: 4096 CTAs
    gemm2_qkvg<<<dim3(64, TOKS/128), 128, gemm_smem>>>(xhi, xlo, w16, q, k, v, g, qscale);

    qkm_kernel<<<32*NT, 256, qkm_smem>>>(q, k, lec, th, Mbuf);

    scan_kernel<<<dim3(Bb*Hh, NVS), 256, scan_smem>>>(q, k, v, elec, coef, Mbuf, z);

    gated_rms_split<<<TOKS*Hh/8, 256>>>(z, g, nw, oghi, oglo);
    gemm2_f16<<<dim3(HD/128, TOKS/128), 128, gemm_smem>>>(oghi, oglo, w16 + 4*(size_t)WN, out, 1.f);
}

// round 12
// speedup vs baseline: 1.4894x; 1.0358x over previous
#include <cuda_runtime.h>
#include <cuda_fp16.h>
#include <math.h>
#include <cstdint>

// Problem constants (fixed shapes)
#define Bb 2
#define Tt 4096
#define Dd 2048
#define Hh 16
#define Kk 128
#define Vv 128
#define BT 64
#define NT 64
#define TOKS (Bb*Tt)          // 8192
#define HD   (Hh*Kk)          // 2048
#define VS   32               // v-slice width in scan
#define NVS  (Vv/VS)          // 4

// ---------------- scratch (device globals; no runtime alloc) ----------------
__device__ float g_q [TOKS*HD];
__device__ float g_k [TOKS*HD];
__device__ float g_v [TOKS*HD];
__device__ float g_g [TOKS*HD];
__device__ float g_z [TOKS*HD];
__device__ float g_eta  [TOKS*Hh];
__device__ float g_theta[TOKS*Hh];
__device__ float g_lec  [32*Tt];
__device__ float g_elec [32*Tt];
__device__ float g_coef [32*Tt];
__device__ float g_M    [32*NT*BT*BT];
__device__ __half g_xhi[TOKS*Dd];
__device__ __half g_xlo[TOKS*Dd];
__device__ __half g_w16[5*Dd*Dd];
__device__ __half g_oghi[TOKS*HD];
__device__ __half g_oglo[TOKS*HD];
__device__ __half g_qhi[TOKS*HD];
__device__ __half g_qlo[TOKS*HD];
__device__ __half g_khi[TOKS*HD];
__device__ __half g_klo[TOKS*HD];

// ---------------- helpers ----------------
typedef unsigned long long u64t;

__device__ __forceinline__ uint32_t smem_u32(const void* p) {
    uint32_t a;
    asm("{ .reg .u64 t; cvta.to.shared.u64 t, %1; cvt.u32.u64 %0, t; }" : "=r"(a) : "l"(p));
    return a;
}
__device__ __forceinline__ void ldm_x4(uint32_t (&r)[4], uint32_t addr) {
    asm volatile("ldmatrix.sync.aligned.m8n8.x4.shared.b16 {%0,%1,%2,%3}, [%4];"
                 : "=r"(r[0]), "=r"(r[1]), "=r"(r[2]), "=r"(r[3]) : "r"(addr));
}
__device__ __forceinline__ void mma16816(float (&d)[4], const uint32_t (&a)[4],
                                         uint32_t b0, uint32_t b1) {
    asm volatile(
        "mma.sync.aligned.m16n8k16.row.col.f32.f16.f16.f32 "
        "{%0,%1,%2,%3}, {%4,%5,%6,%7}, {%8,%9}, {%0,%1,%2,%3};"
        : "+f"(d[0]), "+f"(d[1]), "+f"(d[2]), "+f"(d[3])
        : "r"(a[0]), "r"(a[1]), "r"(a[2]), "r"(a[3]), "r"(b0), "r"(b1));
}
// packed f32x2 (FFMA2 path)
__device__ __forceinline__ u64t pk2(float lo, float hi) {
    u64t d; asm("mov.b64 %0, {%1,%2};" : "=l"(d) : "f"(lo), "f"(hi)); return d;
}
__device__ __forceinline__ void upk2(u64t s, float& lo, float& hi) {
    asm("mov.b64 {%0,%1}, %2;" : "=f"(lo), "=f"(hi) : "l"(s));
}
__device__ __forceinline__ u64t fma2(u64t a, u64t b, u64t c) {
    u64t d; asm("fma.rn.f32x2 %0, %1, %2, %3;" : "=l"(d) : "l"(a), "l"(b), "l"(c)); return d;
}
__device__ __forceinline__ u64t mul2(u64t a, u64t b) {
    u64t d; asm("mul.rn.f32x2 %0, %1, %2;" : "=l"(d) : "l"(a), "l"(b)); return d;
}
__device__ __forceinline__ u64t d2u(double x) { return __double_as_longlong(x); }
__device__ __forceinline__ double u2d(u64t x) { return __longlong_as_double(x); }
#define CP16(dst, src) \
    asm volatile("cp.async.cg.shared.global [%0], [%1], 16;" :: "r"(dst), "l"(src) : "memory")

// ---------------- fp32 -> (hi,lo) fp16 split (activations) ----------------
__global__ __launch_bounds__(256)
void split_fp16_kernel(const float* __restrict__ x, __half* __restrict__ hi,
                       __half* __restrict__ lo, int n4)
{
    int i = blockIdx.x * 256 + threadIdx.x;
    if (i >= n4) return;
    float4 v = ((const float4*)x)[i];
    float vv[4] = {v.x, v.y, v.z, v.w};
    __align__(8) __half h[4], l[4];
#pragma unroll
    for (int j = 0; j < 4; j++) {
        h[j] = __float2half(vv[j]);
        l[j] = __float2half(vv[j] - __half2float(h[j]));
    }
    ((uint2*)hi)[i] = *(uint2*)h;
    ((uint2*)lo)[i] = *(uint2*)l;
}

// ---------------- fp32 -> fp16 convert (single weight) ----------------
__global__ __launch_bounds__(256)
void conv_fp16_kernel(const float* __restrict__ x, __half* __restrict__ w, int n4)
{
    int i = blockIdx.x * 256 + threadIdx.x;
    if (i >= n4) return;
    float4 v = ((const float4*)x)[i];
    __align__(8) __half h[4];
    h[0] = __float2half(v.x); h[1] = __float2half(v.y);
    h[2] = __float2half(v.z); h[3] = __float2half(v.w);
    ((uint2*)w)[i] = *(uint2*)h;
}

// ---------------- fp32 -> fp16 convert, 4 weights in one launch ----------------
__global__ __launch_bounds__(256)
void conv_fp16_4(const float* __restrict__ w0, const float* __restrict__ w1,
                 const float* __restrict__ w2, const float* __restrict__ w3,
                 __half* __restrict__ out)
{
    const int sel = blockIdx.x >> 12;                 // 4096 blocks per weight
    const int i = (blockIdx.x & 4095) * 256 + threadIdx.x;   // < WN/4 = 1048576
    const float* src = (sel == 0) ? w0 : (sel == 1) ? w1 : (sel == 2) ? w2 : w3;
    float4 v = ((const float4*)src)[i];
    __align__(8) __half h[4];
    h[0] = __float2half(v.x); h[1] = __float2half(v.y);
    h[2] = __float2half(v.z); h[3] = __float2half(v.w);
    ((uint2*)(out + (size_t)sel * Dd * Dd))[i] = *(uint2*)h;
}

// ---------------- HMMA 2xFP16 GEMM body ----------------
// C = alpha * (Ahi + Alo) @ B^T.  2 K-segments of 2048. CTA tile 128x128, BK=32,
// 4-stage cp.async, 4 warps (2Mx2N), warp 64x64.
#define BKT 32
#define NKT 128                 // 2 * (2048/32)
#define ROWB 80                 // smem row stride (32 fp16 + 8 pad)
#define STG_BYTES (128*ROWB*2)  // 20480
#define NSTG 4

__device__ __forceinline__ void ld_stage(uint32_t sA, uint32_t sB,
    const __half* __restrict__ A, const __half* __restrict__ B,
    int bm, int bn, int k0, int tid)
{
#pragma unroll
    for (int i = 0; i < 4; i++) {
        int idx = tid + i * 128;      // 0..511
        int row = idx >> 2, c = idx & 3;
        uint32_t dA = sA + row * ROWB + c * 16;
        const void* pA = A + (size_t)(bm + row) * 2048 + k0 + c * 8;
        CP16(dA, pA);
        uint32_t dB = sB + row * ROWB + c * 16;
        const void* pB = B + (size_t)(bn + row) * 2048 + k0 + c * 8;
        CP16(dB, pB);
    }
}

// writes fp32 C; if Hhi/Hlo non-null, also dual-store fp16 hi/lo copies
__device__ __forceinline__ void gemm2_body(
    const __half* __restrict__ Ahi, const __half* __restrict__ Alo,
    const __half* __restrict__ B,
    float* __restrict__ C, __half* __restrict__ Hhi, __half* __restrict__ Hlo,
    float alpha, int bm, int bn, char* dyn)
{
    const int tid  = threadIdx.x;
    const int wid  = tid >> 5;
    const int lane = tid & 31;
    const uint32_t dynb = smem_u32(dyn);

    const int wm0 = (wid >> 1) * 64;        // 2 warps in M
    const int wn0 = (wid & 1) * 64;         // 2 warps in N

    const int q = lane >> 3, l8 = lane & 7;
    const uint32_t aoff = (uint32_t)((l8 + (q & 1) * 8) * ROWB + (q >> 1) * 16);
    const uint32_t boff = (uint32_t)((l8 + (q >> 1) * 8) * ROWB + (q & 1) * 16);

    float acc[4][8][4];
#pragma unroll
    for (int mf = 0; mf < 4; mf++)
#pragma unroll
        for (int nf = 0; nf < 8; nf++)
#pragma unroll
            for (int j = 0; j < 4; j++) acc[mf][nf][j] = 0.f;

    // prologue: stages 0..2 (segment 0: Ahi)
#pragma unroll
    for (int s = 0; s < 3; s++) {
        uint32_t base = dynb + s * STG_BYTES;
        ld_stage(base, base + 128 * ROWB, Ahi, B, bm, bn, s * BKT, tid);
        asm volatile("cp.async.commit_group;" ::: "memory");
    }

    for (int kt = 0; kt < NKT; kt++) {
        asm volatile("cp.async.wait_group 2;" ::: "memory");
        __syncthreads();

        {
            int ktn = kt + 3;
            if (ktn < NKT) {
                int seg = ktn >> 6;
                int k0  = (ktn & 63) * BKT;
                const __half* As_ = seg ? Alo : Ahi;
                uint32_t base = dynb + (ktn & 3) * STG_BYTES;
                ld_stage(base, base + 128 * ROWB, As_, B, bm, bn, k0, tid);
            }
            asm volatile("cp.async.commit_group;" ::: "memory");
        }

        const uint32_t sA = dynb + (kt & 3) * STG_BYTES;
        const uint32_t sB = sA + 128 * ROWB;
#pragma unroll
        for (int ks = 0; ks < 2; ks++) {
            uint32_t a[4][4];
#pragma unroll
            for (int mf = 0; mf < 4; mf++)
                ldm_x4(a[mf], sA + (uint32_t)(wm0 + mf * 16) * ROWB + ks * 32 + aoff);
            uint32_t b[4][4];
#pragma unroll
            for (int p = 0; p < 4; p++)
                ldm_x4(b[p], sB + (uint32_t)(wn0 + p * 16) * ROWB + ks * 32 + boff);
#pragma unroll
            for (int mf = 0; mf < 4; mf++)
#pragma unroll
                for (int p = 0; p < 4; p++) {
                    mma16816(acc[mf][2*p],   a[mf], b[p][0], b[p][1]);
                    mma16816(acc[mf][2*p+1], a[mf], b[p][2], b[p][3]);
                }
        }
    }

    const int r0 = lane >> 2, c0 = (lane & 3) * 2;
#pragma unroll
    for (int mf = 0; mf < 4; mf++) {
        int rowa = bm + wm0 + mf * 16 + r0;
#pragma unroll
        for (int nf = 0; nf < 8; nf++) {
            int col = bn + wn0 + nf * 8 + c0;
            float2 v0 = {alpha * acc[mf][nf][0], alpha * acc[mf][nf][1]};
            float2 v1 = {alpha * acc[mf][nf][2], alpha * acc[mf][nf][3]};
            *(float2*)(C + (size_t)rowa * 2048 + col)       = v0;
            *(float2*)(C + (size_t)(rowa + 8) * 2048 + col) = v1;
            if (Hhi) {
                __half hx = __float2half(v0.x), hy = __float2half(v0.y);
                __half lx = __float2half(v0.x - __half2float(hx));
                __half ly = __float2half(v0.y - __half2float(hy));
                *(__half2*)(Hhi + (size_t)rowa * 2048 + col) = __halves2half2(hx, hy);
                *(__half2*)(Hlo + (size_t)rowa * 2048 + col) = __halves2half2(lx, ly);
                hx = __float2half(v1.x); hy = __float2half(v1.y);
                lx = __float2half(v1.x - __half2float(hx));
                ly = __float2half(v1.y - __half2float(hy));
                *(__half2*)(Hhi + (size_t)(rowa + 8) * 2048 + col) = __halves2half2(hx, hy);
                *(__half2*)(Hlo + (size_t)(rowa + 8) * 2048 + col) = __halves2half2(lx, ly);
            }
        }
    }
}

// Fused q/k/v/g projection GEMM; q,k additionally dual-stored fp16 hi/lo.
__global__ __launch_bounds__(128, 2)
void gemm2_qkvg(const __half* __restrict__ Ahi, const __half* __restrict__ Alo,
                const __half* __restrict__ W,
                float* __restrict__ Cq, float* __restrict__ Ck,
                float* __restrict__ Cv, float* __restrict__ Cg,
                __half* __restrict__ Qhi, __half* __restrict__ Qlo,
                __half* __restrict__ Khi, __half* __restrict__ Klo, float qscale)
{
    extern __shared__ __align__(128) char dyn[];
    const int sel = blockIdx.x >> 4;
    const int bn  = (blockIdx.x & 15) * 128;
    const int bm  = blockIdx.y * 128;
    const __half* B = W + (size_t)sel * Dd * Dd;
    float* C = (sel == 0) ? Cq : (sel == 1) ? Ck : (sel == 2) ? Cv : Cg;
    __half* Hhi = (sel == 0) ? Qhi : (sel == 1) ? Khi : (__half*)0;
    __half* Hlo = (sel == 0) ? Qlo : (sel == 1) ? Klo : (__half*)0;
    float alpha = (sel == 0) ? qscale : 1.f;
    gemm2_body(Ahi, Alo, B, C, Hhi, Hlo, alpha, bm, bn, dyn);
}

// Single GEMM (output projection)
__global__ __launch_bounds__(128, 2)
void gemm2_f16(const __half* __restrict__ Ahi, const __half* __restrict__ Alo,
               const __half* __restrict__ B, float* __restrict__ C, float alpha)
{
    extern __shared__ __align__(128) char dyn[];
    gemm2_body(Ahi, Alo, B, C, (__half*)0, (__half*)0, alpha,
               blockIdx.y * 128, blockIdx.x * 128, dyn);
}

// ---------------- eta / theta: sigmoid projections (N=16 each) ----------------
__global__ __launch_bounds__(256)
void eta_theta_kernel(const float* __restrict__ X, const float* __restrict__ Weta,
                      const float* __restrict__ Wth, float* __restrict__ Eta,
                      float* __restrict__ Th)
{
    __shared__ float sx[Dd];
    const int tok = blockIdx.x, tid = threadIdx.x;
    for (int i = tid; i < Dd/4; i += 256)
        *(float4*)&sx[i*4] = *(const float4*)(X + (size_t)tok*Dd + i*4);
    __syncthreads();
    const int p  = tid >> 3;
    const int l8 = tid & 7;
    const int h = p & 15, which = p >> 4;
    const float* w = (which ? Wth : Weta) + (size_t)h * Dd;
    float s = 0.f;
    for (int i = l8*4; i < Dd; i += 32) {
        float4 xv = *(float4*)&sx[i];
        float4 wv = *(const float4*)(w + i);
        s += xv.x*wv.x + xv.y*wv.y + xv.z*wv.z + xv.w*wv.w;
    }
    s += __shfl_xor_sync(0xffffffffu, s, 4);
    s += __shfl_xor_sync(0xffffffffu, s, 2);
    s += __shfl_xor_sync(0xffffffffu, s, 1);
    if (l8 == 0) {
        float sig = 1.f / (1.f + expf(-s));
        if (which) Th[(size_t)tok*Hh + h] = 0.1f * sig;
        else       Eta[(size_t)tok*Hh + h] = sig;
    }
}

// ---------------- decay prep ----------------
__global__ __launch_bounds__(256)
void decay_prep_kernel(const float* __restrict__ Eta, const float* __restrict__ Th,
                       float* __restrict__ Lec, float* __restrict__ Elec,
                       float* __restrict__ Coef)
{
    const int wc   = blockIdx.x * 8 + (threadIdx.x >> 5);   // bh*64+ct
    const int lane = threadIdx.x & 31;
    const int bh = wc >> 6, ct = wc & 63;
    const int b = bh >> 4, h = bh & 15;
    const size_t tokbase = (size_t)b * Tt;
    const int t = ct * BT + lane * 2;
    float e0  = Eta[(tokbase + t) * Hh + h];
    float e1  = Eta[(tokbase + t + 1) * Hh + h];
    float th0 = Th [(tokbase + t) * Hh + h];
    float th1 = Th [(tokbase + t + 1) * Hh + h];
    float l0 = logf(fmaxf(e0, 1e-8f));
    float l1 = logf(fmaxf(e1, 1e-8f));
    float s = l0 + l1;
#pragma unroll
    for (int o = 1; o < 32; o <<= 1) {
        float n = __shfl_up_sync(0xffffffffu, s, o);
        if (lane >= o) s += n;
    }
    float lec1 = s;
    float lec0 = s - l1;
    float ltot = __shfl_sync(0xffffffffu, s, 31);
    size_t base = (size_t)bh * Tt + t;
    float2 lv = {lec0, lec1};
    float2 ev = {expf(lec0), expf(lec1)};
    float2 cv = {expf(ltot - lec0) * th0, expf(ltot - lec1) * th1};
    *(float2*)(Lec  + base) = lv;
    *(float2*)(Elec + base) = ev;
    *(float2*)(Coef + base) = cv;
}

// ---------------- qkm via HMMA (3-term fp16, exact): M = (q.k)*beta*theta ----------------
#define QROW 136               // halfs per smem row (128 + 8 pad)
#define QROWB (QROW*2)         // 272 bytes
__global__ __launch_bounds__(128)
void qkm_hmma(const __half* __restrict__ Qhi, const __half* __restrict__ Qlo,
              const __half* __restrict__ Khi, const __half* __restrict__ Klo,
              const float* __restrict__ Lec, const float* __restrict__ Th,
              float* __restrict__ Mout)
{
    extern __shared__ __align__(16) char qsmc[];
    __half* sQh = (__half*)qsmc;            // 64*QROW each
    __half* sQl = sQh + 64*QROW;
    __half* sKh = sQl + 64*QROW;
    __half* sKl = sKh + 64*QROW;
    float*  sLec = (float*)(sKl + 64*QROW); // 64
    float*  sTh  = sLec + 64;               // 64

    const int blk = blockIdx.x;             // bh*64 + ct
    const int bh = blk >> 6, ct = blk & 63;
    const int b = bh >> 4, h = bh & 15;
    const int tid = threadIdx.x;
    const size_t tokbase = (size_t)b * Tt;
    const int t0 = ct * BT;
    const size_t goff = tokbase * HD + (size_t)h * Kk;

    const uint32_t sb = smem_u32(qsmc);
    // loads: 4 tensors x 64 rows x 16 chunks(16B) = 4096 cp.async / 128 thr
#pragma unroll
    for (int i = 0; i < 8; i++) {
        int idx = tid + i * 128;            // 0..1023
        int r = idx >> 4, c = (idx & 15) * 8;
        uint32_t d0 = sb + (uint32_t)(r * QROW + c) * 2u;
        size_t gsrc = goff + (size_t)(t0 + r) * HD + c;
        CP16(d0,                       (const void*)(Qhi + gsrc));
        CP16(d0 + 64u*QROWB,           (const void*)(Qlo + gsrc));
        CP16(d0 + 2u*64u*QROWB,        (const void*)(Khi + gsrc));
        CP16(d0 + 3u*64u*QROWB,        (const void*)(Klo + gsrc));
    }
    if (tid < 64) {
        sLec[tid] = Lec[(size_t)bh * Tt + t0 + tid];
        sTh[tid]  = Th[(tokbase + t0 + tid) * Hh + h];
    }
    asm volatile("cp.async.commit_group;" ::: "memory");
    asm volatile("cp.async.wait_group 0;" ::: "memory");
    __syncthreads();

    const int wid = tid >> 5, lane = tid & 31;
    const int wm0 = wid * 16;               // 4 warps split M=64
    const int q8 = lane >> 3, l8 = lane & 7;
    const uint32_t aoff = (uint32_t)((l8 + (q8 & 1) * 8) * QROWB + (q8 >> 1) * 16);
    const uint32_t boff = (uint32_t)((l8 + (q8 >> 1) * 8) * QROWB + (q8 & 1) * 16);

    float acc[8][4];
#pragma unroll
    for (int nf = 0; nf < 8; nf++)
#pragma unroll
        for (int j = 0; j < 4; j++) acc[nf][j] = 0.f;

    const uint32_t bQh = sb, bQl = sb + 64u*QROWB, bKh = sb + 2u*64u*QROWB, bKl = sb + 3u*64u*QROWB;
    const uint32_t Ab[3] = {bQh, bQl, bQh};
    const uint32_t Bbv[3] = {bKh, bKh, bKl};
#pragma unroll
    for (int seg = 0; seg < 3; seg++) {
        const uint32_t As = Ab[seg] + (uint32_t)wm0 * QROWB;
        const uint32_t Bs = Bbv[seg];
#pragma unroll
        for (int ks = 0; ks < 8; ks++) {
            uint32_t a[4];
            ldm_x4(a, As + ks * 32 + aoff);
#pragma unroll
            for (int p = 0; p < 4; p++) {
                uint32_t bb[4];
                ldm_x4(bb, Bs + (uint32_t)(p * 16) * QROWB + ks * 32 + boff);
                mma16816(acc[2*p],   a, bb[0], bb[1]);
                mma16816(acc[2*p+1], a, bb[2], bb[3]);
            }
        }
    }

    // epilogue: mask/beta/theta, fp32 store
    const int r0 = lane >> 2, c0 = (lane & 3) * 2;
    float* Mo = Mout + (size_t)blk * (BT*BT);
#pragma unroll
    for (int half_ = 0; half_ < 2; half_++) {
        int ii = wm0 + r0 + half_ * 8;
        float li = sLec[ii];
#pragma unroll
        for (int nf = 0; nf < 8; nf++) {
            int col = nf * 8 + c0;
            float m0 = 0.f, m1 = 0.f;
            if (col <= ii)
                m0 = acc[nf][half_*2]   * expf(fminf(li - sLec[col], 0.f)) * sTh[col];
            if (col + 1 <= ii)
                m1 = acc[nf][half_*2+1] * expf(fminf(li - sLec[col+1], 0.f)) * sTh[col+1];
            float2 mv = {m0, m1};
            *(float2*)(Mo + ii * 64 + col) = mv;
        }
    }
}

// ---------------- chunked fast-weight scan: VS=32, fused A(kW,qW) + fused B/C, f32x2 ----------------
__global__ __launch_bounds__(256, 1)
void scan_kernel(const float* __restrict__ Q, const float* __restrict__ Kc,
                 const float* __restrict__ Vc, const float* __restrict__ Elec,
                 const float* __restrict__ Coef, const float* __restrict__ Mg,
                 float* __restrict__ Z)
{
    extern __shared__ float sm[];
    float* sWt   = sm;                    // [128][32]  W^T slice
    float* sQ    = sWt  + 128*VS;         // [64][132]
    float* sK    = sQ   + 64*132;         // [64][132]
    float* sVE   = sK   + 64*132;         // [64][32]
    float* sM    = sVE  + 64*VS;          // [64][68]
    float* sElec = sM   + 64*68;          // [64]
    float* sCoef = sElec + 64;            // [64]

    const int tid = threadIdx.x;
    const int bh  = blockIdx.x;
    const int b = bh >> 4, h = bh & 15;
    const int vs0 = blockIdx.y * VS;

    const size_t tokbase = (size_t)b * Tt;
    const float* Qp = Q  + tokbase*HD + (size_t)h*Kk;
    const float* Kp = Kc + tokbase*HD + (size_t)h*Kk;
    const float* Vp = Vc + tokbase*HD + (size_t)h*Vv + vs0;
    const float* Mp = Mg + (size_t)bh * (NT*BT*BT);
    float*       Zp = Z  + tokbase*HD + (size_t)h*Vv + vs0;

    for (int i = tid; i < 128*VS; i += 256) sWt[i] = 0.f;

    const int tx = tid & 7;               // v quad
    const int ty = tid >> 3;              // 0..31
    const int v0 = tx << 2;
    const int ta = ty*2, tb = ta + 1;     // row pair
    const int k0 = ty << 2;               // 4 k-rows for W update

    for (int ct = 0; ct < NT; ct++) {
        const int t0 = ct * BT;
        __syncthreads();   // prev chunk readers done; W-update visible

        // ---- loads ----
#pragma unroll
        for (int i = 0; i < 8; i++) {
            int idx = tid + i*256;
            int r = idx >> 5;
            int c = (idx & 31) << 2;
            *(float4*)&sQ[r*132 + c] = *(const float4*)(Qp + (size_t)(t0+r)*HD + c);
            *(float4*)&sK[r*132 + c] = *(const float4*)(Kp + (size_t)(t0+r)*HD + c);
        }
#pragma unroll
        for (int i = 0; i < 2; i++) {
            int idx = tid + i*256;
            int r = idx >> 3;
            int c = (idx & 7) << 2;
            *(float4*)&sVE[r*VS + c] = *(const float4*)(Vp + (size_t)(t0+r)*HD + c);
        }
#pragma unroll
        for (int i = 0; i < 4; i++) {
            int idx = tid + i*256;
            int r = idx >> 4;
            int c = (idx & 15) << 2;
            *(float4*)&sM[r*68 + c] = *(const float4*)(Mp + ct*(BT*BT) + r*64 + c);
        }
        if (tid < 64) {
            sElec[tid] = Elec[(size_t)bh*Tt + t0 + tid];
            sCoef[tid] = Coef[(size_t)bh*Tt + t0 + tid];
        }
        __syncthreads();

        // ---- Phase A: e = k@W^T - v  AND  zq = q@W^T (single W pass) ----
        u64t za01, za23, zb01, zb23;
        {
            float4 va = *(float4*)&sVE[ta*VS + v0];
            float4 vb = *(float4*)&sVE[tb*VS + v0];
            u64t ea01 = pk2(-va.x, -va.y), ea23 = pk2(-va.z, -va.w);
            u64t eb01 = pk2(-vb.x, -vb.y), eb23 = pk2(-vb.z, -vb.w);
            za01 = 0ull; za23 = 0ull; zb01 = 0ull; zb23 = 0ull;
#pragma unroll 4
            for (int kk = 0; kk < Kk; kk++) {
                double2 wd = *(double2*)&sWt[kk*VS + v0];
                u64t w01 = d2u(wd.x), w23 = d2u(wd.y);
                float ka = sK[ta*132 + kk];
                float kb = sK[tb*132 + kk];
                float qa = sQ[ta*132 + kk];
                float qb = sQ[tb*132 + kk];
                u64t ka2 = pk2(ka, ka), kb2 = pk2(kb, kb);
                u64t qa2 = pk2(qa, qa), qb2 = pk2(qb, qb);
                ea01 = fma2(ka2, w01, ea01);
                ea23 = fma2(ka2, w23, ea23);
                eb01 = fma2(kb2, w01, eb01);
                eb23 = fma2(kb2, w23, eb23);
                za01 = fma2(qa2, w01, za01);
                za23 = fma2(qa2, w23, za23);
                zb01 = fma2(qb2, w01, zb01);
                zb23 = fma2(qb2, w23, zb23);
            }
            *(double2*)&sVE[ta*VS + v0] = make_double2(u2d(ea01), u2d(ea23));
            *(double2*)&sVE[tb*VS + v0] = make_double2(u2d(eb01), u2d(eb23));
        }
        __syncthreads();   // e fully written; all sWt reads done (only A reads sWt)

        // ---- Fused B+C: z = elec*zq - M@e ; ca = -sum_t coef*e (x) k ; W update ----
        {
            float ea = sElec[ta], eb = sElec[tb];
            u64t ea2 = pk2(ea, ea), eb2 = pk2(eb, eb);
            za01 = mul2(za01, ea2); za23 = mul2(za23, ea2);
            zb01 = mul2(zb01, eb2); zb23 = mul2(zb23, eb2);
            u64t sa01 = 0ull, sa23 = 0ull, sb01 = 0ull, sb23 = 0ull;
            u64t ca01[4], ca23[4];
#pragma unroll
            for (int i = 0; i < 4; i++) { ca01[i] = 0ull; ca23[i] = 0ull; }
#pragma unroll 2
            for (int t = 0; t < BT; t++) {
                double2 ed = *(double2*)&sVE[t*VS + v0];
                u64t e01 = d2u(ed.x), e23 = d2u(ed.y);
                float ma = sM[ta*68 + t];
                float mb = sM[tb*68 + t];
                u64t ma2 = pk2(ma, ma), mb2 = pk2(mb, mb);
                sa01 = fma2(ma2, e01, sa01);
                sa23 = fma2(ma2, e23, sa23);
                sb01 = fma2(mb2, e01, sb01);
                sb23 = fma2(mb2, e23, sb23);
                float cf = -sCoef[t];
                u64t cf2 = pk2(cf, cf);
                u64t ce01 = mul2(e01, cf2);
                u64t ce23 = mul2(e23, cf2);
                float4 k4 = *(float4*)&sK[t*132 + k0];
                u64t k20 = pk2(k4.x, k4.x), k21 = pk2(k4.y, k4.y);
                u64t k22 = pk2(k4.z, k4.z), k23 = pk2(k4.w, k4.w);
                ca01[0] = fma2(k20, ce01, ca01[0]); ca23[0] = fma2(k20, ce23, ca23[0]);
                ca01[1] = fma2(k21, ce01, ca01[1]); ca23[1] = fma2(k21, ce23, ca23[1]);
                ca01[2] = fma2(k22, ce01, ca01[2]); ca23[2] = fma2(k22, ce23, ca23[2]);
                ca01[3] = fma2(k23, ce01, ca01[3]); ca23[3] = fma2(k23, ce23, ca23[3]);
            }
            float z0, z1, s0, s1;
            float4 oa, ob;
            upk2(za01, z0, z1); upk2(sa01, s0, s1); oa.x = z0 - s0; oa.y = z1 - s1;
            upk2(za23, z0, z1); upk2(sa23, s0, s1); oa.z = z0 - s0; oa.w = z1 - s1;
            upk2(zb01, z0, z1); upk2(sb01, s0, s1); ob.x = z0 - s0; ob.y = z1 - s1;
            upk2(zb23, z0, z1); upk2(sb23, s0, s1); ob.z = z0 - s0; ob.w = z1 - s1;
            *(float4*)(Zp + (size_t)(t0+ta)*HD + v0) = oa;
            *(float4*)(Zp + (size_t)(t0+tb)*HD + v0) = ob;

            // W update (no barrier needed: sWt is only read in phase A, guarded by top barrier)
            float dk = sElec[63];
            u64t dk2 = pk2(dk, dk);
#pragma unroll
            for (int i = 0; i < 4; i++) {
                double2 wv = *(double2*)&sWt[(k0+i)*VS + v0];
                u64t w01 = fma2(d2u(wv.x), dk2, ca01[i]);
                u64t w23 = fma2(d2u(wv.y), dk2, ca23[i]);
                *(double2*)&sWt[(k0+i)*VS + v0] = make_double2(u2d(w01), u2d(w23));
            }
        }
    }
}

// ---------------- gated RMS norm -> fp16 hi/lo split ----------------
__global__ __launch_bounds__(256)
void gated_rms_split(const float* __restrict__ Zin, const float* __restrict__ G,
                     const float* __restrict__ nw, __half* __restrict__ hi,
                     __half* __restrict__ lo)
{
    const int gw   = blockIdx.x * 8 + (threadIdx.x >> 5);
    const int lane = threadIdx.x & 31;
    const size_t base = (size_t)gw * 128;
    float4 zv = *(const float4*)(Zin + base + lane*4);
    float ss = zv.x*zv.x + zv.y*zv.y + zv.z*zv.z + zv.w*zv.w;
#pragma unroll
    for (int o = 16; o; o >>= 1) ss += __shfl_xor_sync(0xffffffffu, ss, o);
    float r = rsqrtf(ss * (1.f/128.f) + 1e-5f);
    float4 gv = *(const float4*)(G  + base + lane*4);
    float4 wv = *(const float4*)(nw + lane*4);
    float ov[4];
    ov[0] = zv.x*r*wv.x * (gv.x / (1.f + expf(-gv.x)));
    ov[1] = zv.y*r*wv.y * (gv.y / (1.f + expf(-gv.y)));
    ov[2] = zv.z*r*wv.z * (gv.z / (1.f + expf(-gv.z)));
    ov[3] = zv.w*r*wv.w * (gv.w / (1.f + expf(-gv.w)));
    __align__(8) __half h[4], l[4];
#pragma unroll
    for (int j = 0; j < 4; j++) {
        h[j] = __float2half(ov[j]);
        l[j] = __float2half(ov[j] - __half2float(h[j]));
    }
    *(uint2*)(hi + base + lane*4) = *(uint2*)h;
    *(uint2*)(lo + base + lane*4) = *(uint2*)l;
}

// ---------------- launch ----------------
extern "C" void kernel_launch(void* const* d_in, const int* in_sizes, int n_in,
                              void* d_out, int out_size)
{
    const float* X    = (const float*)d_in[0];
    const float* Wq   = (const float*)d_in[1];
    const float* Wk   = (const float*)d_in[2];
    const float* Wv   = (const float*)d_in[3];
    const float* Weta = (const float*)d_in[4];
    const float* Wth  = (const float*)d_in[5];
    const float* Wg   = (const float*)d_in[6];
    const float* nw   = (const float*)d_in[7];
    const float* Wo   = (const float*)d_in[8];
    float* out = (float*)d_out;

    float *q, *k, *v, *g, *z, *eta, *th, *lec, *elec, *coef, *Mbuf;
    __half *xhi, *xlo, *w16, *oghi, *oglo, *qhi, *qlo, *khi, *klo;
    cudaGetSymbolAddress((void**)&q,    g_q);
    cudaGetSymbolAddress((void**)&k,    g_k);
    cudaGetSymbolAddress((void**)&v,    g_v);
    cudaGetSymbolAddress((void**)&g,    g_g);
    cudaGetSymbolAddress((void**)&z,    g_z);
    cudaGetSymbolAddress((void**)&eta,  g_eta);
    cudaGetSymbolAddress((void**)&th,   g_theta);
    cudaGetSymbolAddress((void**)&lec,  g_lec);
    cudaGetSymbolAddress((void**)&elec, g_elec);
    cudaGetSymbolAddress((void**)&coef, g_coef);
    cudaGetSymbolAddress((void**)&Mbuf, g_M);
    cudaGetSymbolAddress((void**)&xhi,  g_xhi);
    cudaGetSymbolAddress((void**)&xlo,  g_xlo);
    cudaGetSymbolAddress((void**)&w16,  g_w16);
    cudaGetSymbolAddress((void**)&oghi, g_oghi);
    cudaGetSymbolAddress((void**)&oglo, g_oglo);
    cudaGetSymbolAddress((void**)&qhi,  g_qhi);
    cudaGetSymbolAddress((void**)&qlo,  g_qlo);
    cudaGetSymbolAddress((void**)&khi,  g_khi);
    cudaGetSymbolAddress((void**)&klo,  g_klo);

    const int scan_smem = (128*VS + 64*132 + 64*132 + 64*VS + 64*68 + 2*64) * 4;
    cudaFuncSetAttribute(scan_kernel, cudaFuncAttributeMaxDynamicSharedMemorySize, scan_smem);
    const int qkm_smem = 4*64*QROW*2 + 2*64*4;   // 70144
    cudaFuncSetAttribute(qkm_hmma, cudaFuncAttributeMaxDynamicSharedMemorySize, qkm_smem);
    const int gemm_smem = NSTG * STG_BYTES;   // 81920
    cudaFuncSetAttribute(gemm2_f16, cudaFuncAttributeMaxDynamicSharedMemorySize, gemm_smem);
    cudaFuncSetAttribute(gemm2_qkvg, cudaFuncAttributeMaxDynamicSharedMemorySize, gemm_smem);

    const int WN = Dd * Dd;
    const float qscale = 0.08838834764831845f;  // 128^-0.5

    split_fp16_kernel<<<TOKS*Dd/4/256, 256>>>(X, xhi, xlo, TOKS*Dd/4);   // launch 1
    conv_fp16_4<<<4*4096, 256>>>(Wq, Wk, Wv, Wg, w16);                    // launch 2
    conv_fp16_kernel<<<4096, 256>>>(Wo, w16 + 4*(size_t)WN, WN/4);        // launch 3
    eta_theta_kernel<<<TOKS, 256>>>(X, Weta, Wth, eta, th);               // launch 4
    decay_prep_kernel<<<2048/8, 256>>>(eta, th, lec, elec, coef);         // launch 5

    // launch 6 (ncu -s 5 -c 1 lands here)
    gemm2_qkvg<<<dim3(64, TOKS/128), 128, gemm_smem>>>(xhi, xlo, w16, q, k, v, g,
                                                       qhi, qlo, khi, klo, qscale);

    qkm_hmma<<<32*NT, 128, qkm_smem>>>(qhi, qlo, khi, klo, lec, th, Mbuf);

    scan_kernel<<<dim3(Bb*Hh, NVS), 256, scan_smem>>>(q, k, v, elec, coef, Mbuf, z);

    gated_rms_split<<<TOKS*Hh/8, 256>>>(z, g, nw, oghi, oglo);
    gemm2_f16<<<dim3(HD/128, TOKS/128), 128, gemm_smem>>>(oghi, oglo, w16 + 4*(size_t)WN, out, 1.f);
}

// round 13
// speedup vs baseline: 1.5467x; 1.0385x over previous
#include <cuda_runtime.h>
#include <cuda_fp16.h>
#include <math.h>
#include <cstdint>

// Problem constants (fixed shapes)
#define Bb 2
#define Tt 4096
#define Dd 2048
#define Hh 16
#define Kk 128
#define Vv 128
#define BT 64
#define NT 64
#define TOKS (Bb*Tt)          // 8192
#define HD   (Hh*Kk)          // 2048
#define VS   32               // v-slice width in scan
#define NVS  (Vv/VS)          // 4

// ---------------- scratch (device globals; no runtime alloc) ----------------
__device__ float g_v [TOKS*HD];
__device__ float g_g [TOKS*HD];
__device__ float g_z [TOKS*HD];
__device__ float g_eta  [TOKS*Hh];
__device__ float g_theta[TOKS*Hh];
__device__ float g_lec  [32*Tt];
__device__ float g_elec [32*Tt];
__device__ float g_coef [32*Tt];
__device__ float g_M    [32*NT*BT*BT];
__device__ __half g_xhi[TOKS*Dd];
__device__ __half g_xlo[TOKS*Dd];
__device__ __half g_w16[5*Dd*Dd];
__device__ __half g_w32hi[32*Dd];
__device__ __half g_w32lo[32*Dd];
__device__ __half g_oghi[TOKS*HD];
__device__ __half g_oglo[TOKS*HD];
__device__ __half g_qhi[TOKS*HD];
__device__ __half g_qlo[TOKS*HD];
__device__ __half g_khi[TOKS*HD];
__device__ __half g_klo[TOKS*HD];

// ---------------- helpers ----------------
typedef unsigned long long u64t;

__device__ __forceinline__ uint32_t smem_u32(const void* p) {
    uint32_t a;
    asm("{ .reg .u64 t; cvta.to.shared.u64 t, %1; cvt.u32.u64 %0, t; }" : "=r"(a) : "l"(p));
    return a;
}
__device__ __forceinline__ void ldm_x4(uint32_t (&r)[4], uint32_t addr) {
    asm volatile("ldmatrix.sync.aligned.m8n8.x4.shared.b16 {%0,%1,%2,%3}, [%4];"
                 : "=r"(r[0]), "=r"(r[1]), "=r"(r[2]), "=r"(r[3]) : "r"(addr));
}
__device__ __forceinline__ void mma16816(float (&d)[4], const uint32_t (&a)[4],
                                         uint32_t b0, uint32_t b1) {
    asm volatile(
        "mma.sync.aligned.m16n8k16.row.col.f32.f16.f16.f32 "
        "{%0,%1,%2,%3}, {%4,%5,%6,%7}, {%8,%9}, {%0,%1,%2,%3};"
        : "+f"(d[0]), "+f"(d[1]), "+f"(d[2]), "+f"(d[3])
        : "r"(a[0]), "r"(a[1]), "r"(a[2]), "r"(a[3]), "r"(b0), "r"(b1));
}
// packed f32x2 (FFMA2 path)
__device__ __forceinline__ u64t pk2(float lo, float hi) {
    u64t d; asm("mov.b64 %0, {%1,%2};" : "=l"(d) : "f"(lo), "f"(hi)); return d;
}
__device__ __forceinline__ void upk2(u64t s, float& lo, float& hi) {
    asm("mov.b64 {%0,%1}, %2;" : "=f"(lo), "=f"(hi) : "l"(s));
}
__device__ __forceinline__ u64t fma2(u64t a, u64t b, u64t c) {
    u64t d; asm("fma.rn.f32x2 %0, %1, %2, %3;" : "=l"(d) : "l"(a), "l"(b), "l"(c)); return d;
}
__device__ __forceinline__ u64t mul2(u64t a, u64t b) {
    u64t d; asm("mul.rn.f32x2 %0, %1, %2;" : "=l"(d) : "l"(a), "l"(b)); return d;
}
__device__ __forceinline__ u64t d2u(double x) { return __double_as_longlong(x); }
__device__ __forceinline__ double u2d(u64t x) { return __longlong_as_double(x); }
#define CP16(dst, src) \
    asm volatile("cp.async.cg.shared.global [%0], [%1], 16;" :: "r"(dst), "l"(src) : "memory")
// combine hi/lo fp16 quad -> float4
__device__ __forceinline__ float4 cvt4(uint2 h, uint2 l) {
    float2 f0 = __half22float2(*(__half2*)&h.x);
    float2 f1 = __half22float2(*(__half2*)&h.y);
    float2 g0 = __half22float2(*(__half2*)&l.x);
    float2 g1 = __half22float2(*(__half2*)&l.y);
    float4 r;
    r.x = f0.x + g0.x; r.y = f0.y + g0.y;
    r.z = f1.x + g1.x; r.w = f1.y + g1.y;
    return r;
}

// ---------------- fp32 -> (hi,lo) fp16 split (activations) ----------------
__global__ __launch_bounds__(256)
void split_fp16_kernel(const float* __restrict__ x, __half* __restrict__ hi,
                       __half* __restrict__ lo, int n4)
{
    int i = blockIdx.x * 256 + threadIdx.x;
    if (i >= n4) return;
    float4 v = ((const float4*)x)[i];
    float vv[4] = {v.x, v.y, v.z, v.w};
    __align__(8) __half h[4], l[4];
#pragma unroll
    for (int j = 0; j < 4; j++) {
        h[j] = __float2half(vv[j]);
        l[j] = __float2half(vv[j] - __half2float(h[j]));
    }
    ((uint2*)hi)[i] = *(uint2*)h;
    ((uint2*)lo)[i] = *(uint2*)l;
}

// ---------------- fp32 -> fp16 convert (single weight) ----------------
__global__ __launch_bounds__(256)
void conv_fp16_kernel(const float* __restrict__ x, __half* __restrict__ w, int n4)
{
    int i = blockIdx.x * 256 + threadIdx.x;
    if (i >= n4) return;
    float4 v = ((const float4*)x)[i];
    __align__(8) __half h[4];
    h[0] = __float2half(v.x); h[1] = __float2half(v.y);
    h[2] = __float2half(v.z); h[3] = __float2half(v.w);
    ((uint2*)w)[i] = *(uint2*)h;
}

// ---------------- fp32 -> fp16 convert, 4 weights in one launch ----------------
__global__ __launch_bounds__(256)
void conv_fp16_4(const float* __restrict__ w0, const float* __restrict__ w1,
                 const float* __restrict__ w2, const float* __restrict__ w3,
                 __half* __restrict__ out)
{
    const int sel = blockIdx.x >> 12;
    const int i = (blockIdx.x & 4095) * 256 + threadIdx.x;
    const float* src = (sel == 0) ? w0 : (sel == 1) ? w1 : (sel == 2) ? w2 : w3;
    float4 v = ((const float4*)src)[i];
    __align__(8) __half h[4];
    h[0] = __float2half(v.x); h[1] = __float2half(v.y);
    h[2] = __float2half(v.z); h[3] = __float2half(v.w);
    ((uint2*)(out + (size_t)sel * Dd * Dd))[i] = *(uint2*)h;
}

// ---------------- Weta||Wth -> 32-row hi/lo fp16 split ----------------
__global__ __launch_bounds__(256)
void split_w32(const float* __restrict__ Weta, const float* __restrict__ Wth,
               __half* __restrict__ hi, __half* __restrict__ lo)
{
    int i = blockIdx.x * 256 + threadIdx.x;   // float4 index, < 32*2048/4
    int e = i * 4;
    const float* src = (e < 16*Dd) ? (Weta + e) : (Wth + e - 16*Dd);
    float4 v = *(const float4*)src;
    float vv[4] = {v.x, v.y, v.z, v.w};
    __align__(8) __half h[4], l[4];
#pragma unroll
    for (int j = 0; j < 4; j++) {
        h[j] = __float2half(vv[j]);
        l[j] = __float2half(vv[j] - __half2float(h[j]));
    }
    ((uint2*)hi)[i] = *(uint2*)h;
    ((uint2*)lo)[i] = *(uint2*)l;
}

// ---------------- HMMA 2xFP16 GEMM body ----------------
#define BKT 32
#define NKT 128                 // 2 * (2048/32)
#define ROWB 80                 // smem row stride (32 fp16 + 8 pad)
#define STG_BYTES (128*ROWB*2)  // 20480
#define NSTG 4

__device__ __forceinline__ void ld_stage(uint32_t sA, uint32_t sB,
    const __half* __restrict__ A, const __half* __restrict__ B,
    int bm, int bn, int k0, int tid)
{
#pragma unroll
    for (int i = 0; i < 4; i++) {
        int idx = tid + i * 128;
        int row = idx >> 2, c = idx & 3;
        uint32_t dA = sA + row * ROWB + c * 16;
        const void* pA = A + (size_t)(bm + row) * 2048 + k0 + c * 8;
        CP16(dA, pA);
        uint32_t dB = sB + row * ROWB + c * 16;
        const void* pB = B + (size_t)(bn + row) * 2048 + k0 + c * 8;
        CP16(dB, pB);
    }
}

// writes fp32 C, or (when Hhi/Hlo set) fp16 hi/lo dual-store instead
__device__ __forceinline__ void gemm2_body(
    const __half* __restrict__ Ahi, const __half* __restrict__ Alo,
    const __half* __restrict__ B,
    float* __restrict__ C, __half* __restrict__ Hhi, __half* __restrict__ Hlo,
    float alpha, int bm, int bn, char* dyn)
{
    const int tid  = threadIdx.x;
    const int wid  = tid >> 5;
    const int lane = tid & 31;
    const uint32_t dynb = smem_u32(dyn);

    const int wm0 = (wid >> 1) * 64;
    const int wn0 = (wid & 1) * 64;

    const int q = lane >> 3, l8 = lane & 7;
    const uint32_t aoff = (uint32_t)((l8 + (q & 1) * 8) * ROWB + (q >> 1) * 16);
    const uint32_t boff = (uint32_t)((l8 + (q >> 1) * 8) * ROWB + (q & 1) * 16);

    float acc[4][8][4];
#pragma unroll
    for (int mf = 0; mf < 4; mf++)
#pragma unroll
        for (int nf = 0; nf < 8; nf++)
#pragma unroll
            for (int j = 0; j < 4; j++) acc[mf][nf][j] = 0.f;

#pragma unroll
    for (int s = 0; s < 3; s++) {
        uint32_t base = dynb + s * STG_BYTES;
        ld_stage(base, base + 128 * ROWB, Ahi, B, bm, bn, s * BKT, tid);
        asm volatile("cp.async.commit_group;" ::: "memory");
    }

    for (int kt = 0; kt < NKT; kt++) {
        asm volatile("cp.async.wait_group 2;" ::: "memory");
        __syncthreads();

        {
            int ktn = kt + 3;
            if (ktn < NKT) {
                int seg = ktn >> 6;
                int k0  = (ktn & 63) * BKT;
                const __half* As_ = seg ? Alo : Ahi;
                uint32_t base = dynb + (ktn & 3) * STG_BYTES;
                ld_stage(base, base + 128 * ROWB, As_, B, bm, bn, k0, tid);
            }
            asm volatile("cp.async.commit_group;" ::: "memory");
        }

        const uint32_t sA = dynb + (kt & 3) * STG_BYTES;
        const uint32_t sB = sA + 128 * ROWB;
#pragma unroll
        for (int ks = 0; ks < 2; ks++) {
            uint32_t a[4][4];
#pragma unroll
            for (int mf = 0; mf < 4; mf++)
                ldm_x4(a[mf], sA + (uint32_t)(wm0 + mf * 16) * ROWB + ks * 32 + aoff);
            uint32_t b[4][4];
#pragma unroll
            for (int p = 0; p < 4; p++)
                ldm_x4(b[p], sB + (uint32_t)(wn0 + p * 16) * ROWB + ks * 32 + boff);
#pragma unroll
            for (int mf = 0; mf < 4; mf++)
#pragma unroll
                for (int p = 0; p < 4; p++) {
                    mma16816(acc[mf][2*p],   a[mf], b[p][0], b[p][1]);
                    mma16816(acc[mf][2*p+1], a[mf], b[p][2], b[p][3]);
                }
        }
    }

    const int r0 = lane >> 2, c0 = (lane & 3) * 2;
#pragma unroll
    for (int mf = 0; mf < 4; mf++) {
        int rowa = bm + wm0 + mf * 16 + r0;
#pragma unroll
        for (int nf = 0; nf < 8; nf++) {
            int col = bn + wn0 + nf * 8 + c0;
            float2 v0 = {alpha * acc[mf][nf][0], alpha * acc[mf][nf][1]};
            float2 v1 = {alpha * acc[mf][nf][2], alpha * acc[mf][nf][3]};
            if (!Hhi) {
                *(float2*)(C + (size_t)rowa * 2048 + col)       = v0;
                *(float2*)(C + (size_t)(rowa + 8) * 2048 + col) = v1;
            } else {
                __half hx = __float2half(v0.x), hy = __float2half(v0.y);
                __half lx = __float2half(v0.x - __half2float(hx));
                __half ly = __float2half(v0.y - __half2float(hy));
                *(__half2*)(Hhi + (size_t)rowa * 2048 + col) = __halves2half2(hx, hy);
                *(__half2*)(Hlo + (size_t)rowa * 2048 + col) = __halves2half2(lx, ly);
                hx = __float2half(v1.x); hy = __float2half(v1.y);
                lx = __float2half(v1.x - __half2float(hx));
                ly = __float2half(v1.y - __half2float(hy));
                *(__half2*)(Hhi + (size_t)(rowa + 8) * 2048 + col) = __halves2half2(hx, hy);
                *(__half2*)(Hlo + (size_t)(rowa + 8) * 2048 + col) = __halves2half2(lx, ly);
            }
        }
    }
}

// Fused q/k/v/g projections; q,k stored ONLY as fp16 hi/lo (exact), v,g fp32.
__global__ __launch_bounds__(128, 2)
void gemm2_qkvg(const __half* __restrict__ Ahi, const __half* __restrict__ Alo,
                const __half* __restrict__ W,
                float* __restrict__ Cv, float* __restrict__ Cg,
                __half* __restrict__ Qhi, __half* __restrict__ Qlo,
                __half* __restrict__ Khi, __half* __restrict__ Klo, float qscale)
{
    extern __shared__ __align__(128) char dyn[];
    const int sel = blockIdx.x >> 4;
    const int bn  = (blockIdx.x & 15) * 128;
    const int bm  = blockIdx.y * 128;
    const __half* B = W + (size_t)sel * Dd * Dd;
    float* C = (sel == 2) ? Cv : (sel == 3) ? Cg : (float*)0;
    __half* Hhi = (sel == 0) ? Qhi : (sel == 1) ? Khi : (__half*)0;
    __half* Hlo = (sel == 0) ? Qlo : (sel == 1) ? Klo : (__half*)0;
    float alpha = (sel == 0) ? qscale : 1.f;
    gemm2_body(Ahi, Alo, B, C, Hhi, Hlo, alpha, bm, bn, dyn);
}

// Single GEMM (output projection)
__global__ __launch_bounds__(128, 2)
void gemm2_f16(const __half* __restrict__ Ahi, const __half* __restrict__ Alo,
               const __half* __restrict__ B, float* __restrict__ C, float alpha)
{
    extern __shared__ __align__(128) char dyn[];
    gemm2_body(Ahi, Alo, B, C, (__half*)0, (__half*)0, alpha,
               blockIdx.y * 128, blockIdx.x * 128, dyn);
}

// ---------------- eta/theta via HMMA: sigmoid(X @ [Weta;Wth]^T), 3-term fp16 (exact) ----------------
#define ENKT 192   // 3 segments * 64
__global__ __launch_bounds__(128)
void eta_theta_hmma(const __half* __restrict__ Xhi, const __half* __restrict__ Xlo,
                    const __half* __restrict__ Whi, const __half* __restrict__ Wlo,
                    float* __restrict__ Eta, float* __restrict__ Th)
{
    extern __shared__ __align__(128) char dyn[];
    const int tid  = threadIdx.x;
    const int wid  = tid >> 5;
    const int lane = tid & 31;
    const int bm   = blockIdx.x * 128;
    const uint32_t dynb = smem_u32(dyn);
    // stage: A 128*ROWB + B 32*ROWB = 12800 bytes
    const uint32_t STG_E = 160 * ROWB;

    const int wm0 = wid * 32;    // 4 warps x 32 token-rows
    const int q = lane >> 3, l8 = lane & 7;
    const uint32_t aoff = (uint32_t)((l8 + (q & 1) * 8) * ROWB + (q >> 1) * 16);
    const uint32_t boff = (uint32_t)((l8 + (q >> 1) * 8) * ROWB + (q & 1) * 16);

    float acc[2][4][4];
#pragma unroll
    for (int mf = 0; mf < 2; mf++)
#pragma unroll
        for (int nf = 0; nf < 4; nf++)
#pragma unroll
            for (int j = 0; j < 4; j++) acc[mf][nf][j] = 0.f;

    // stage loader lambda-style macro
#define ELD(stg, Asrc, Bsrc, k0) do { \
    uint32_t bsA = dynb + (stg) * STG_E; \
    uint32_t bsB = bsA + 128 * ROWB; \
    _Pragma("unroll") \
    for (int i_ = 0; i_ < 4; i_++) { \
        int idx_ = tid + i_ * 128; \
        int row_ = idx_ >> 2, c_ = idx_ & 3; \
        CP16(bsA + row_ * ROWB + c_ * 16, (const void*)((Asrc) + (size_t)(bm + row_) * 2048 + (k0) + c_ * 8)); \
    } \
    { int row_ = tid >> 2, c_ = tid & 3; \
      CP16(bsB + row_ * ROWB + c_ * 16, (const void*)((Bsrc) + (size_t)row_ * 2048 + (k0) + c_ * 8)); } \
    asm volatile("cp.async.commit_group;" ::: "memory"); \
} while (0)

#pragma unroll
    for (int s = 0; s < 3; s++) ELD(s, Xhi, Whi, s * BKT);

    for (int kt = 0; kt < ENKT; kt++) {
        asm volatile("cp.async.wait_group 2;" ::: "memory");
        __syncthreads();
        {
            int ktn = kt + 3;
            if (ktn < ENKT) {
                int seg = ktn >> 6;
                int k0  = (ktn & 63) * BKT;
                const __half* As_ = (seg == 1) ? Xlo : Xhi;
                const __half* Bs_ = (seg == 2) ? Wlo : Whi;
                ELD(ktn & 3, As_, Bs_, k0);
            } else {
                asm volatile("cp.async.commit_group;" ::: "memory");
            }
        }
        const uint32_t sA = dynb + (kt & 3) * STG_E;
        const uint32_t sB = sA + 128 * ROWB;
#pragma unroll
        for (int ks = 0; ks < 2; ks++) {
            uint32_t a[2][4];
#pragma unroll
            for (int mf = 0; mf < 2; mf++)
                ldm_x4(a[mf], sA + (uint32_t)(wm0 + mf * 16) * ROWB + ks * 32 + aoff);
            uint32_t b[2][4];
#pragma unroll
            for (int p = 0; p < 2; p++)
                ldm_x4(b[p], sB + (uint32_t)(p * 16) * ROWB + ks * 32 + boff);
#pragma unroll
            for (int mf = 0; mf < 2; mf++)
#pragma unroll
                for (int p = 0; p < 2; p++) {
                    mma16816(acc[mf][2*p],   a[mf], b[p][0], b[p][1]);
                    mma16816(acc[mf][2*p+1], a[mf], b[p][2], b[p][3]);
                }
        }
        __syncthreads();
    }
#undef ELD

    const int r0 = lane >> 2, c0 = (lane & 3) * 2;
#pragma unroll
    for (int mf = 0; mf < 2; mf++) {
        int tok0 = bm + wm0 + mf * 16 + r0;
#pragma unroll
        for (int nf = 0; nf < 4; nf++) {
            int col = nf * 8 + c0;
            float s0 = acc[mf][nf][0], s1 = acc[mf][nf][1];
            float s2 = acc[mf][nf][2], s3 = acc[mf][nf][3];
            float g0 = 1.f / (1.f + expf(-s0));
            float g1 = 1.f / (1.f + expf(-s1));
            float g2 = 1.f / (1.f + expf(-s2));
            float g3 = 1.f / (1.f + expf(-s3));
            if (col < 16) {
                float2 a0 = {g0, g1}, a1 = {g2, g3};
                *(float2*)(Eta + (size_t)tok0 * Hh + col)       = a0;
                *(float2*)(Eta + (size_t)(tok0 + 8) * Hh + col) = a1;
            } else {
                float2 a0 = {0.1f*g0, 0.1f*g1}, a1 = {0.1f*g2, 0.1f*g3};
                *(float2*)(Th + (size_t)tok0 * Hh + col - 16)       = a0;
                *(float2*)(Th + (size_t)(tok0 + 8) * Hh + col - 16) = a1;
            }
        }
    }
}

// ---------------- decay prep ----------------
__global__ __launch_bounds__(256)
void decay_prep_kernel(const float* __restrict__ Eta, const float* __restrict__ Th,
                       float* __restrict__ Lec, float* __restrict__ Elec,
                       float* __restrict__ Coef)
{
    const int wc   = blockIdx.x * 8 + (threadIdx.x >> 5);
    const int lane = threadIdx.x & 31;
    const int bh = wc >> 6, ct = wc & 63;
    const int b = bh >> 4, h = bh & 15;
    const size_t tokbase = (size_t)b * Tt;
    const int t = ct * BT + lane * 2;
    float e0  = Eta[(tokbase + t) * Hh + h];
    float e1  = Eta[(tokbase + t + 1) * Hh + h];
    float th0 = Th [(tokbase + t) * Hh + h];
    float th1 = Th [(tokbase + t + 1) * Hh + h];
    float l0 = logf(fmaxf(e0, 1e-8f));
    float l1 = logf(fmaxf(e1, 1e-8f));
    float s = l0 + l1;
#pragma unroll
    for (int o = 1; o < 32; o <<= 1) {
        float n = __shfl_up_sync(0xffffffffu, s, o);
        if (lane >= o) s += n;
    }
    float lec1 = s;
    float lec0 = s - l1;
    float ltot = __shfl_sync(0xffffffffu, s, 31);
    size_t base = (size_t)bh * Tt + t;
    float2 lv = {lec0, lec1};
    float2 ev = {expf(lec0), expf(lec1)};
    float2 cv = {expf(ltot - lec0) * th0, expf(ltot - lec1) * th1};
    *(float2*)(Lec  + base) = lv;
    *(float2*)(Elec + base) = ev;
    *(float2*)(Coef + base) = cv;
}

// ---------------- qkm via HMMA (3-term fp16, exact) ----------------
#define QROW 136
#define QROWB (QROW*2)
__global__ __launch_bounds__(128)
void qkm_hmma(const __half* __restrict__ Qhi, const __half* __restrict__ Qlo,
              const __half* __restrict__ Khi, const __half* __restrict__ Klo,
              const float* __restrict__ Lec, const float* __restrict__ Th,
              float* __restrict__ Mout)
{
    extern __shared__ __align__(16) char qsmc[];
    float*  sLec = (float*)(qsmc + 4*64*QROWB);
    float*  sTh  = sLec + 64;

    const int blk = blockIdx.x;
    const int bh = blk >> 6, ct = blk & 63;
    const int b = bh >> 4, h = bh & 15;
    const int tid = threadIdx.x;
    const size_t tokbase = (size_t)b * Tt;
    const int t0 = ct * BT;
    const size_t goff = tokbase * HD + (size_t)h * Kk;

    const uint32_t sb = smem_u32(qsmc);
#pragma unroll
    for (int i = 0; i < 8; i++) {
        int idx = tid + i * 128;
        int r = idx >> 4, c = (idx & 15) * 8;
        uint32_t d0 = sb + (uint32_t)(r * QROW + c) * 2u;
        size_t gsrc = goff + (size_t)(t0 + r) * HD + c;
        CP16(d0,                (const void*)(Qhi + gsrc));
        CP16(d0 + 64u*QROWB,    (const void*)(Qlo + gsrc));
        CP16(d0 + 2u*64u*QROWB, (const void*)(Khi + gsrc));
        CP16(d0 + 3u*64u*QROWB, (const void*)(Klo + gsrc));
    }
    if (tid < 64) {
        sLec[tid] = Lec[(size_t)bh * Tt + t0 + tid];
        sTh[tid]  = Th[(tokbase + t0 + tid) * Hh + h];
    }
    asm volatile("cp.async.commit_group;" ::: "memory");
    asm volatile("cp.async.wait_group 0;" ::: "memory");
    __syncthreads();

    const int wid = tid >> 5, lane = tid & 31;
    const int wm0 = wid * 16;
    const int q8 = lane >> 3, l8 = lane & 7;
    const uint32_t aoff = (uint32_t)((l8 + (q8 & 1) * 8) * QROWB + (q8 >> 1) * 16);
    const uint32_t boff = (uint32_t)((l8 + (q8 >> 1) * 8) * QROWB + (q8 & 1) * 16);

    float acc[8][4];
#pragma unroll
    for (int nf = 0; nf < 8; nf++)
#pragma unroll
        for (int j = 0; j < 4; j++) acc[nf][j] = 0.f;

    const uint32_t bQh = sb, bQl = sb + 64u*QROWB, bKh = sb + 2u*64u*QROWB, bKl = sb + 3u*64u*QROWB;
    const uint32_t Ab[3] = {bQh, bQl, bQh};
    const uint32_t Bbv[3] = {bKh, bKh, bKl};
#pragma unroll
    for (int seg = 0; seg < 3; seg++) {
        const uint32_t As = Ab[seg] + (uint32_t)wm0 * QROWB;
        const uint32_t Bs = Bbv[seg];
#pragma unroll
        for (int ks = 0; ks < 8; ks++) {
            uint32_t a[4];
            ldm_x4(a, As + ks * 32 + aoff);
#pragma unroll
            for (int p = 0; p < 4; p++) {
                uint32_t bb[4];
                ldm_x4(bb, Bs + (uint32_t)(p * 16) * QROWB + ks * 32 + boff);
                mma16816(acc[2*p],   a, bb[0], bb[1]);
                mma16816(acc[2*p+1], a, bb[2], bb[3]);
            }
        }
    }

    const int r0 = lane >> 2, c0 = (lane & 3) * 2;
    float* Mo = Mout + (size_t)blk * (BT*BT);
#pragma unroll
    for (int half_ = 0; half_ < 2; half_++) {
        int ii = wm0 + r0 + half_ * 8;
        float li = sLec[ii];
#pragma unroll
        for (int nf = 0; nf < 8; nf++) {
            int col = nf * 8 + c0;
            float m0 = 0.f, m1 = 0.f;
            if (col <= ii)
                m0 = acc[nf][half_*2]   * expf(fminf(li - sLec[col], 0.f)) * sTh[col];
            if (col + 1 <= ii)
                m1 = acc[nf][half_*2+1] * expf(fminf(li - sLec[col+1], 0.f)) * sTh[col+1];
            float2 mv = {m0, m1};
            *(float2*)(Mo + ii * 64 + col) = mv;
        }
    }
}

// ---------------- chunked fast-weight scan: VS=32, fused A + fused B/C, f32x2 ----------------
__global__ __launch_bounds__(256, 1)
void scan_kernel(const __half* __restrict__ Qhi, const __half* __restrict__ Qlo,
                 const __half* __restrict__ Khi, const __half* __restrict__ Klo,
                 const float* __restrict__ Vc, const float* __restrict__ Elec,
                 const float* __restrict__ Coef, const float* __restrict__ Mg,
                 float* __restrict__ Z)
{
    extern __shared__ float sm[];
    float* sWt   = sm;                    // [128][32]
    float* sQ    = sWt  + 128*VS;         // [64][132]
    float* sK    = sQ   + 64*132;         // [64][132]
    float* sVE   = sK   + 64*132;         // [64][32]
    float* sM    = sVE  + 64*VS;          // [64][68]
    float* sElec = sM   + 64*68;          // [64]
    float* sCoef = sElec + 64;            // [64]

    const int tid = threadIdx.x;
    const int bh  = blockIdx.x;
    const int b = bh >> 4, h = bh & 15;
    const int vs0 = blockIdx.y * VS;

    const size_t tokbase = (size_t)b * Tt;
    const size_t goff = tokbase * HD + (size_t)h * Kk;
    const __half* Qh = Qhi + goff;
    const __half* Ql = Qlo + goff;
    const __half* Kh = Khi + goff;
    const __half* Kl = Klo + goff;
    const float* Vp = Vc + tokbase*HD + (size_t)h*Vv + vs0;
    const float* Mp = Mg + (size_t)bh * (NT*BT*BT);
    float*       Zp = Z  + tokbase*HD + (size_t)h*Vv + vs0;

    for (int i = tid; i < 128*VS; i += 256) sWt[i] = 0.f;

    const int tx = tid & 7;
    const int ty = tid >> 3;
    const int v0 = tx << 2;
    const int ta = ty*2, tb = ta + 1;
    const int k0 = ty << 2;

    for (int ct = 0; ct < NT; ct++) {
        const int t0 = ct * BT;
        __syncthreads();

        // ---- loads (q,k from exact fp16 hi/lo pairs) ----
#pragma unroll
        for (int i = 0; i < 8; i++) {
            int idx = tid + i*256;
            int r = idx >> 5;
            int c = (idx & 31) << 2;
            size_t off = (size_t)(t0+r)*HD + c;
            uint2 qh = *(const uint2*)(Qh + off);
            uint2 ql = *(const uint2*)(Ql + off);
            *(float4*)&sQ[r*132 + c] = cvt4(qh, ql);
            uint2 kh = *(const uint2*)(Kh + off);
            uint2 kl = *(const uint2*)(Kl + off);
            *(float4*)&sK[r*132 + c] = cvt4(kh, kl);
        }
#pragma unroll
        for (int i = 0; i < 2; i++) {
            int idx = tid + i*256;
            int r = idx >> 3;
            int c = (idx & 7) << 2;
            *(float4*)&sVE[r*VS + c] = *(const float4*)(Vp + (size_t)(t0+r)*HD + c);
        }
#pragma unroll
        for (int i = 0; i < 4; i++) {
            int idx = tid + i*256;
            int r = idx >> 4;
            int c = (idx & 15) << 2;
            *(float4*)&sM[r*68 + c] = *(const float4*)(Mp + ct*(BT*BT) + r*64 + c);
        }
        if (tid < 64) {
            sElec[tid] = Elec[(size_t)bh*Tt + t0 + tid];
            sCoef[tid] = Coef[(size_t)bh*Tt + t0 + tid];
        }
        __syncthreads();

        // ---- Phase A: e = k@W^T - v  AND  zq = q@W^T ----
        u64t za01, za23, zb01, zb23;
        {
            float4 va = *(float4*)&sVE[ta*VS + v0];
            float4 vb = *(float4*)&sVE[tb*VS + v0];
            u64t ea01 = pk2(-va.x, -va.y), ea23 = pk2(-va.z, -va.w);
            u64t eb01 = pk2(-vb.x, -vb.y), eb23 = pk2(-vb.z, -vb.w);
            za01 = 0ull; za23 = 0ull; zb01 = 0ull; zb23 = 0ull;
#pragma unroll 4
            for (int kk = 0; kk < Kk; kk++) {
                double2 wd = *(double2*)&sWt[kk*VS + v0];
                u64t w01 = d2u(wd.x), w23 = d2u(wd.y);
                float ka = sK[ta*132 + kk];
                float kb = sK[tb*132 + kk];
                float qa = sQ[ta*132 + kk];
                float qb = sQ[tb*132 + kk];
                u64t ka2 = pk2(ka, ka), kb2 = pk2(kb, kb);
                u64t qa2 = pk2(qa, qa), qb2 = pk2(qb, qb);
                ea01 = fma2(ka2, w01, ea01);
                ea23 = fma2(ka2, w23, ea23);
                eb01 = fma2(kb2, w01, eb01);
                eb23 = fma2(kb2, w23, eb23);
                za01 = fma2(qa2, w01, za01);
                za23 = fma2(qa2, w23, za23);
                zb01 = fma2(qb2, w01, zb01);
                zb23 = fma2(qb2, w23, zb23);
            }
            *(double2*)&sVE[ta*VS + v0] = make_double2(u2d(ea01), u2d(ea23));
            *(double2*)&sVE[tb*VS + v0] = make_double2(u2d(eb01), u2d(eb23));
        }
        __syncthreads();

        // ---- Fused B+C ----
        {
            float ea = sElec[ta], eb = sElec[tb];
            u64t ea2 = pk2(ea, ea), eb2 = pk2(eb, eb);
            za01 = mul2(za01, ea2); za23 = mul2(za23, ea2);
            zb01 = mul2(zb01, eb2); zb23 = mul2(zb23, eb2);
            u64t sa01 = 0ull, sa23 = 0ull, sb01 = 0ull, sb23 = 0ull;
            u64t ca01[4], ca23[4];
#pragma unroll
            for (int i = 0; i < 4; i++) { ca01[i] = 0ull; ca23[i] = 0ull; }
#pragma unroll 2
            for (int t = 0; t < BT; t++) {
                double2 ed = *(double2*)&sVE[t*VS + v0];
                u64t e01 = d2u(ed.x), e23 = d2u(ed.y);
                float ma = sM[ta*68 + t];
                float mb = sM[tb*68 + t];
                u64t ma2 = pk2(ma, ma), mb2 = pk2(mb, mb);
                sa01 = fma2(ma2, e01, sa01);
                sa23 = fma2(ma2, e23, sa23);
                sb01 = fma2(mb2, e01, sb01);
                sb23 = fma2(mb2, e23, sb23);
                float cf = -sCoef[t];
                u64t cf2 = pk2(cf, cf);
                u64t ce01 = mul2(e01, cf2);
                u64t ce23 = mul2(e23, cf2);
                float4 k4 = *(float4*)&sK[t*132 + k0];
                u64t k20 = pk2(k4.x, k4.x), k21 = pk2(k4.y, k4.y);
                u64t k22 = pk2(k4.z, k4.z), k23 = pk2(k4.w, k4.w);
                ca01[0] = fma2(k20, ce01, ca01[0]); ca23[0] = fma2(k20, ce23, ca23[0]);
                ca01[1] = fma2(k21, ce01, ca01[1]); ca23[1] = fma2(k21, ce23, ca23[1]);
                ca01[2] = fma2(k22, ce01, ca01[2]); ca23[2] = fma2(k22, ce23, ca23[2]);
                ca01[3] = fma2(k23, ce01, ca01[3]); ca23[3] = fma2(k23, ce23, ca23[3]);
            }
            float z0, z1, s0, s1;
            float4 oa, ob;
            upk2(za01, z0, z1); upk2(sa01, s0, s1); oa.x = z0 - s0; oa.y = z1 - s1;
            upk2(za23, z0, z1); upk2(sa23, s0, s1); oa.z = z0 - s0; oa.w = z1 - s1;
            upk2(zb01, z0, z1); upk2(sb01, s0, s1); ob.x = z0 - s0; ob.y = z1 - s1;
            upk2(zb23, z0, z1); upk2(sb23, s0, s1); ob.z = z0 - s0; ob.w = z1 - s1;
            *(float4*)(Zp + (size_t)(t0+ta)*HD + v0) = oa;
            *(float4*)(Zp + (size_t)(t0+tb)*HD + v0) = ob;

            float dk = sElec[63];
            u64t dk2 = pk2(dk, dk);
#pragma unroll
            for (int i = 0; i < 4; i++) {
                double2 wv = *(double2*)&sWt[(k0+i)*VS + v0];
                u64t w01 = fma2(d2u(wv.x), dk2, ca01[i]);
                u64t w23 = fma2(d2u(wv.y), dk2, ca23[i]);
                *(double2*)&sWt[(k0+i)*VS + v0] = make_double2(u2d(w01), u2d(w23));
            }
        }
    }
}

// ---------------- gated RMS norm -> fp16 hi/lo split ----------------
__global__ __launch_bounds__(256)
void gated_rms_split(const float* __restrict__ Zin, const float* __restrict__ G,
                     const float* __restrict__ nw, __half* __restrict__ hi,
                     __half* __restrict__ lo)
{
    const int gw   = blockIdx.x * 8 + (threadIdx.x >> 5);
    const int lane = threadIdx.x & 31;
    const size_t base = (size_t)gw * 128;
    float4 zv = *(const float4*)(Zin + base + lane*4);
    float ss = zv.x*zv.x + zv.y*zv.y + zv.z*zv.z + zv.w*zv.w;
#pragma unroll
    for (int o = 16; o; o >>= 1) ss += __shfl_xor_sync(0xffffffffu, ss, o);
    float r = rsqrtf(ss * (1.f/128.f) + 1e-5f);
    float4 gv = *(const float4*)(G  + base + lane*4);
    float4 wv = *(const float4*)(nw + lane*4);
    float ov[4];
    ov[0] = zv.x*r*wv.x * (gv.x / (1.f + expf(-gv.x)));
    ov[1] = zv.y*r*wv.y * (gv.y / (1.f + expf(-gv.y)));
    ov[2] = zv.z*r*wv.z * (gv.z / (1.f + expf(-gv.z)));
    ov[3] = zv.w*r*wv.w * (gv.w / (1.f + expf(-gv.w)));
    __align__(8) __half h[4], l[4];
#pragma unroll
    for (int j = 0; j < 4; j++) {
        h[j] = __float2half(ov[j]);
        l[j] = __float2half(ov[j] - __half2float(h[j]));
    }
    *(uint2*)(hi + base + lane*4) = *(uint2*)h;
    *(uint2*)(lo + base + lane*4) = *(uint2*)l;
}

// ---------------- launch ----------------
extern "C" void kernel_launch(void* const* d_in, const int* in_sizes, int n_in,
                              void* d_out, int out_size)
{
    const float* X    = (const float*)d_in[0];
    const float* Wq   = (const float*)d_in[1];
    const float* Wk   = (const float*)d_in[2];
    const float* Wv   = (const float*)d_in[3];
    const float* Weta = (const float*)d_in[4];
    const float* Wth  = (const float*)d_in[5];
    const float* Wg   = (const float*)d_in[6];
    const float* nw   = (const float*)d_in[7];
    const float* Wo   = (const float*)d_in[8];
    float* out = (float*)d_out;

    float *v, *g, *z, *eta, *th, *lec, *elec, *coef, *Mbuf;
    __half *xhi, *xlo, *w16, *w32hi, *w32lo, *oghi, *oglo, *qhi, *qlo, *khi, *klo;
    cudaGetSymbolAddress((void**)&v,    g_v);
    cudaGetSymbolAddress((void**)&g,    g_g);
    cudaGetSymbolAddress((void**)&z,    g_z);
    cudaGetSymbolAddress((void**)&eta,  g_eta);
    cudaGetSymbolAddress((void**)&th,   g_theta);
    cudaGetSymbolAddress((void**)&lec,  g_lec);
    cudaGetSymbolAddress((void**)&elec, g_elec);
    cudaGetSymbolAddress((void**)&coef, g_coef);
    cudaGetSymbolAddress((void**)&Mbuf, g_M);
    cudaGetSymbolAddress((void**)&xhi,  g_xhi);
    cudaGetSymbolAddress((void**)&xlo,  g_xlo);
    cudaGetSymbolAddress((void**)&w16,  g_w16);
    cudaGetSymbolAddress((void**)&w32hi,g_w32hi);
    cudaGetSymbolAddress((void**)&w32lo,g_w32lo);
    cudaGetSymbolAddress((void**)&oghi, g_oghi);
    cudaGetSymbolAddress((void**)&oglo, g_oglo);
    cudaGetSymbolAddress((void**)&qhi,  g_qhi);
    cudaGetSymbolAddress((void**)&qlo,  g_qlo);
    cudaGetSymbolAddress((void**)&khi,  g_khi);
    cudaGetSymbolAddress((void**)&klo,  g_klo);

    const int scan_smem = (128*VS + 64*132 + 64*132 + 64*VS + 64*68 + 2*64) * 4;
    cudaFuncSetAttribute(scan_kernel, cudaFuncAttributeMaxDynamicSharedMemorySize, scan_smem);
    const int qkm_smem = 4*64*QROW*2 + 2*64*4;   // 70144
    cudaFuncSetAttribute(qkm_hmma, cudaFuncAttributeMaxDynamicSharedMemorySize, qkm_smem);
    const int gemm_smem = NSTG * STG_BYTES;   // 81920
    cudaFuncSetAttribute(gemm2_f16, cudaFuncAttributeMaxDynamicSharedMemorySize, gemm_smem);
    cudaFuncSetAttribute(gemm2_qkvg, cudaFuncAttributeMaxDynamicSharedMemorySize, gemm_smem);
    const int eta_smem = 4 * 160 * ROWB;      // 51200
    cudaFuncSetAttribute(eta_theta_hmma, cudaFuncAttributeMaxDynamicSharedMemorySize, eta_smem);

    const int WN = Dd * Dd;
    const float qscale = 0.08838834764831845f;  // 128^-0.5

    split_fp16_kernel<<<TOKS*Dd/4/256, 256>>>(X, xhi, xlo, TOKS*Dd/4);
    conv_fp16_4<<<4*4096, 256>>>(Wq, Wk, Wv, Wg, w16);
    conv_fp16_kernel<<<4096, 256>>>(Wo, w16 + 4*(size_t)WN, WN/4);
    split_w32<<<32*Dd/4/256, 256>>>(Weta, Wth, w32hi, w32lo);

    eta_theta_hmma<<<TOKS/128, 128, eta_smem>>>(xhi, xlo, w32hi, w32lo, eta, th);
    decay_prep_kernel<<<2048/8, 256>>>(eta, th, lec, elec, coef);

    gemm2_qkvg<<<dim3(64, TOKS/128), 128, gemm_smem>>>(xhi, xlo, w16, v, g,
                                                       qhi, qlo, khi, klo, qscale);

    qkm_hmma<<<32*NT, 128, qkm_smem>>>(qhi, qlo, khi, klo, lec, th, Mbuf);

    scan_kernel<<<dim3(Bb*Hh, NVS), 256, scan_smem>>>(qhi, qlo, khi, klo, v, elec, coef, Mbuf, z);

    gated_rms_split<<<TOKS*Hh/8, 256>>>(z, g, nw, oghi, oglo);
    gemm2_f16<<<dim3(HD/128, TOKS/128), 128, gemm_smem>>>(oghi, oglo, w16 + 4*(size_t)WN, out, 1.f);
}

// round 14
// speedup vs baseline: 1.5693x; 1.0146x over previous
#include <cuda_runtime.h>
#include <cuda_fp16.h>
#include <math.h>
#include <cstdint>

// Problem constants (fixed shapes)
#define Bb 2
#define Tt 4096
#define Dd 2048
#define Hh 16
#define Kk 128
#define Vv 128
#define BT 64
#define NT 64
#define TOKS (Bb*Tt)          // 8192
#define HD   (Hh*Kk)          // 2048
#define VS   32               // v-slice width in scan
#define NVS  (Vv/VS)          // 4

// ---------------- scratch (device globals; no runtime alloc) ----------------
__device__ float g_v [TOKS*HD];
__device__ float g_g [TOKS*HD];
__device__ float g_z [TOKS*HD];
__device__ float g_eta  [TOKS*Hh];
__device__ float g_theta[TOKS*Hh];
__device__ float g_lec  [32*Tt];
__device__ float g_elec [32*Tt];
__device__ float g_coef [32*Tt];
__device__ float g_M    [32*NT*BT*BT];
__device__ __half g_xhi[TOKS*Dd];
__device__ __half g_xlo[TOKS*Dd];
__device__ __half g_w16[5*Dd*Dd];
__device__ __half g_w32hi[32*Dd];
__device__ __half g_w32lo[32*Dd];
__device__ __half g_oghi[TOKS*HD];
__device__ __half g_oglo[TOKS*HD];
__device__ __half g_qhi[TOKS*HD];
__device__ __half g_qlo[TOKS*HD];
__device__ __half g_khi[TOKS*HD];
__device__ __half g_klo[TOKS*HD];

// ---------------- helpers ----------------
typedef unsigned long long u64t;

__device__ __forceinline__ uint32_t smem_u32(const void* p) {
    uint32_t a;
    asm("{ .reg .u64 t; cvta.to.shared.u64 t, %1; cvt.u32.u64 %0, t; }" : "=r"(a) : "l"(p));
    return a;
}
__device__ __forceinline__ void ldm_x4(uint32_t (&r)[4], uint32_t addr) {
    asm volatile("ldmatrix.sync.aligned.m8n8.x4.shared.b16 {%0,%1,%2,%3}, [%4];"
                 : "=r"(r[0]), "=r"(r[1]), "=r"(r[2]), "=r"(r[3]) : "r"(addr));
}
__device__ __forceinline__ void mma16816(float (&d)[4], const uint32_t (&a)[4],
                                         uint32_t b0, uint32_t b1) {
    asm volatile(
        "mma.sync.aligned.m16n8k16.row.col.f32.f16.f16.f32 "
        "{%0,%1,%2,%3}, {%4,%5,%6,%7}, {%8,%9}, {%0,%1,%2,%3};"
        : "+f"(d[0]), "+f"(d[1]), "+f"(d[2]), "+f"(d[3])
        : "r"(a[0]), "r"(a[1]), "r"(a[2]), "r"(a[3]), "r"(b0), "r"(b1));
}
// packed f32x2 (FFMA2 path)
__device__ __forceinline__ u64t pk2(float lo, float hi) {
    u64t d; asm("mov.b64 %0, {%1,%2};" : "=l"(d) : "f"(lo), "f"(hi)); return d;
}
__device__ __forceinline__ void upk2(u64t s, float& lo, float& hi) {
    asm("mov.b64 {%0,%1}, %2;" : "=f"(lo), "=f"(hi) : "l"(s));
}
__device__ __forceinline__ u64t fma2(u64t a, u64t b, u64t c) {
    u64t d; asm("fma.rn.f32x2 %0, %1, %2, %3;" : "=l"(d) : "l"(a), "l"(b), "l"(c)); return d;
}
__device__ __forceinline__ u64t mul2(u64t a, u64t b) {
    u64t d; asm("mul.rn.f32x2 %0, %1, %2;" : "=l"(d) : "l"(a), "l"(b)); return d;
}
__device__ __forceinline__ u64t d2u(double x) { return __double_as_longlong(x); }
__device__ __forceinline__ double u2d(u64t x) { return __longlong_as_double(x); }
#define CP16(dst, src) \
    asm volatile("cp.async.cg.shared.global [%0], [%1], 16;" :: "r"(dst), "l"(src) : "memory")
// combine hi/lo fp16 quad -> float4
__device__ __forceinline__ float4 cvt4(uint2 h, uint2 l) {
    float2 f0 = __half22float2(*(__half2*)&h.x);
    float2 f1 = __half22float2(*(__half2*)&h.y);
    float2 g0 = __half22float2(*(__half2*)&l.x);
    float2 g1 = __half22float2(*(__half2*)&l.y);
    float4 r;
    r.x = f0.x + g0.x; r.y = f0.y + g0.y;
    r.z = f1.x + g1.x; r.w = f1.y + g1.y;
    return r;
}

// ---------------- fp32 -> (hi,lo) fp16 split (activations) ----------------
__global__ __launch_bounds__(256)
void split_fp16_kernel(const float* __restrict__ x, __half* __restrict__ hi,
                       __half* __restrict__ lo, int n4)
{
    int i = blockIdx.x * 256 + threadIdx.x;
    if (i >= n4) return;
    float4 v = ((const float4*)x)[i];
    float vv[4] = {v.x, v.y, v.z, v.w};
    __align__(8) __half h[4], l[4];
#pragma unroll
    for (int j = 0; j < 4; j++) {
        h[j] = __float2half(vv[j]);
        l[j] = __float2half(vv[j] - __half2float(h[j]));
    }
    ((uint2*)hi)[i] = *(uint2*)h;
    ((uint2*)lo)[i] = *(uint2*)l;
}

// ---------------- fp32 -> fp16 convert (single weight) ----------------
__global__ __launch_bounds__(256)
void conv_fp16_kernel(const float* __restrict__ x, __half* __restrict__ w, int n4)
{
    int i = blockIdx.x * 256 + threadIdx.x;
    if (i >= n4) return;
    float4 v = ((const float4*)x)[i];
    __align__(8) __half h[4];
    h[0] = __float2half(v.x); h[1] = __float2half(v.y);
    h[2] = __float2half(v.z); h[3] = __float2half(v.w);
    ((uint2*)w)[i] = *(uint2*)h;
}

// ---------------- fp32 -> fp16 convert, 4 weights in one launch ----------------
__global__ __launch_bounds__(256)
void conv_fp16_4(const float* __restrict__ w0, const float* __restrict__ w1,
                 const float* __restrict__ w2, const float* __restrict__ w3,
                 __half* __restrict__ out)
{
    const int sel = blockIdx.x >> 12;
    const int i = (blockIdx.x & 4095) * 256 + threadIdx.x;
    const float* src = (sel == 0) ? w0 : (sel == 1) ? w1 : (sel == 2) ? w2 : w3;
    float4 v = ((const float4*)src)[i];
    __align__(8) __half h[4];
    h[0] = __float2half(v.x); h[1] = __float2half(v.y);
    h[2] = __float2half(v.z); h[3] = __float2half(v.w);
    ((uint2*)(out + (size_t)sel * Dd * Dd))[i] = *(uint2*)h;
}

// ---------------- Weta||Wth -> 32-row hi/lo fp16 split ----------------
__global__ __launch_bounds__(256)
void split_w32(const float* __restrict__ Weta, const float* __restrict__ Wth,
               __half* __restrict__ hi, __half* __restrict__ lo)
{
    int i = blockIdx.x * 256 + threadIdx.x;
    int e = i * 4;
    const float* src = (e < 16*Dd) ? (Weta + e) : (Wth + e - 16*Dd);
    float4 v = *(const float4*)src;
    float vv[4] = {v.x, v.y, v.z, v.w};
    __align__(8) __half h[4], l[4];
#pragma unroll
    for (int j = 0; j < 4; j++) {
        h[j] = __float2half(vv[j]);
        l[j] = __float2half(vv[j] - __half2float(h[j]));
    }
    ((uint2*)hi)[i] = *(uint2*)h;
    ((uint2*)lo)[i] = *(uint2*)l;
}

// ---------------- HMMA 2xFP16 GEMM body ----------------
#define BKT 32
#define NKT 128                 // 2 * (2048/32)
#define ROWB 80                 // smem row stride (32 fp16 + 8 pad)
#define STG_BYTES (128*ROWB*2)  // 20480
#define NSTG 4

__device__ __forceinline__ void ld_stage(uint32_t sA, uint32_t sB,
    const __half* __restrict__ A, const __half* __restrict__ B,
    int bm, int bn, int k0, int tid)
{
#pragma unroll
    for (int i = 0; i < 4; i++) {
        int idx = tid + i * 128;
        int row = idx >> 2, c = idx & 3;
        uint32_t dA = sA + row * ROWB + c * 16;
        const void* pA = A + (size_t)(bm + row) * 2048 + k0 + c * 8;
        CP16(dA, pA);
        uint32_t dB = sB + row * ROWB + c * 16;
        const void* pB = B + (size_t)(bn + row) * 2048 + k0 + c * 8;
        CP16(dB, pB);
    }
}

// writes fp32 C, or (when Hhi/Hlo set) fp16 hi/lo dual-store instead
__device__ __forceinline__ void gemm2_body(
    const __half* __restrict__ Ahi, const __half* __restrict__ Alo,
    const __half* __restrict__ B,
    float* __restrict__ C, __half* __restrict__ Hhi, __half* __restrict__ Hlo,
    float alpha, int bm, int bn, char* dyn)
{
    const int tid  = threadIdx.x;
    const int wid  = tid >> 5;
    const int lane = tid & 31;
    const uint32_t dynb = smem_u32(dyn);

    const int wm0 = (wid >> 1) * 64;
    const int wn0 = (wid & 1) * 64;

    const int q = lane >> 3, l8 = lane & 7;
    const uint32_t aoff = (uint32_t)((l8 + (q & 1) * 8) * ROWB + (q >> 1) * 16);
    const uint32_t boff = (uint32_t)((l8 + (q >> 1) * 8) * ROWB + (q & 1) * 16);

    float acc[4][8][4];
#pragma unroll
    for (int mf = 0; mf < 4; mf++)
#pragma unroll
        for (int nf = 0; nf < 8; nf++)
#pragma unroll
            for (int j = 0; j < 4; j++) acc[mf][nf][j] = 0.f;

#pragma unroll
    for (int s = 0; s < 3; s++) {
        uint32_t base = dynb + s * STG_BYTES;
        ld_stage(base, base + 128 * ROWB, Ahi, B, bm, bn, s * BKT, tid);
        asm volatile("cp.async.commit_group;" ::: "memory");
    }

    for (int kt = 0; kt < NKT; kt++) {
        asm volatile("cp.async.wait_group 2;" ::: "memory");
        __syncthreads();

        {
            int ktn = kt + 3;
            if (ktn < NKT) {
                int seg = ktn >> 6;
                int k0  = (ktn & 63) * BKT;
                const __half* As_ = seg ? Alo : Ahi;
                uint32_t base = dynb + (ktn & 3) * STG_BYTES;
                ld_stage(base, base + 128 * ROWB, As_, B, bm, bn, k0, tid);
            }
            asm volatile("cp.async.commit_group;" ::: "memory");
        }

        const uint32_t sA = dynb + (kt & 3) * STG_BYTES;
        const uint32_t sB = sA + 128 * ROWB;
#pragma unroll
        for (int ks = 0; ks < 2; ks++) {
            uint32_t a[4][4];
#pragma unroll
            for (int mf = 0; mf < 4; mf++)
                ldm_x4(a[mf], sA + (uint32_t)(wm0 + mf * 16) * ROWB + ks * 32 + aoff);
            uint32_t b[4][4];
#pragma unroll
            for (int p = 0; p < 4; p++)
                ldm_x4(b[p], sB + (uint32_t)(wn0 + p * 16) * ROWB + ks * 32 + boff);
#pragma unroll
            for (int mf = 0; mf < 4; mf++)
#pragma unroll
                for (int p = 0; p < 4; p++) {
                    mma16816(acc[mf][2*p],   a[mf], b[p][0], b[p][1]);
                    mma16816(acc[mf][2*p+1], a[mf], b[p][2], b[p][3]);
                }
        }
    }

    const int r0 = lane >> 2, c0 = (lane & 3) * 2;
#pragma unroll
    for (int mf = 0; mf < 4; mf++) {
        int rowa = bm + wm0 + mf * 16 + r0;
#pragma unroll
        for (int nf = 0; nf < 8; nf++) {
            int col = bn + wn0 + nf * 8 + c0;
            float2 v0 = {alpha * acc[mf][nf][0], alpha * acc[mf][nf][1]};
            float2 v1 = {alpha * acc[mf][nf][2], alpha * acc[mf][nf][3]};
            if (!Hhi) {
                *(float2*)(C + (size_t)rowa * 2048 + col)       = v0;
                *(float2*)(C + (size_t)(rowa + 8) * 2048 + col) = v1;
            } else {
                __half hx = __float2half(v0.x), hy = __float2half(v0.y);
                __half lx = __float2half(v0.x - __half2float(hx));
                __half ly = __float2half(v0.y - __half2float(hy));
                *(__half2*)(Hhi + (size_t)rowa * 2048 + col) = __halves2half2(hx, hy);
                *(__half2*)(Hlo + (size_t)rowa * 2048 + col) = __halves2half2(lx, ly);
                hx = __float2half(v1.x); hy = __float2half(v1.y);
                lx = __float2half(v1.x - __half2float(hx));
                ly = __float2half(v1.y - __half2float(hy));
                *(__half2*)(Hhi + (size_t)(rowa + 8) * 2048 + col) = __halves2half2(hx, hy);
                *(__half2*)(Hlo + (size_t)(rowa + 8) * 2048 + col) = __halves2half2(lx, ly);
            }
        }
    }
}

// Fused q/k/v/g projections; q,k stored ONLY as fp16 hi/lo (exact), v,g fp32.
__global__ __launch_bounds__(128, 2)
void gemm2_qkvg(const __half* __restrict__ Ahi, const __half* __restrict__ Alo,
                const __half* __restrict__ W,
                float* __restrict__ Cv, float* __restrict__ Cg,
                __half* __restrict__ Qhi, __half* __restrict__ Qlo,
                __half* __restrict__ Khi, __half* __restrict__ Klo, float qscale)
{
    extern __shared__ __align__(128) char dyn[];
    const int sel = blockIdx.x >> 4;
    const int bn  = (blockIdx.x & 15) * 128;
    const int bm  = blockIdx.y * 128;
    const __half* B = W + (size_t)sel * Dd * Dd;
    float* C = (sel == 2) ? Cv : (sel == 3) ? Cg : (float*)0;
    __half* Hhi = (sel == 0) ? Qhi : (sel == 1) ? Khi : (__half*)0;
    __half* Hlo = (sel == 0) ? Qlo : (sel == 1) ? Klo : (__half*)0;
    float alpha = (sel == 0) ? qscale : 1.f;
    gemm2_body(Ahi, Alo, B, C, Hhi, Hlo, alpha, bm, bn, dyn);
}

// Single GEMM (output projection)
__global__ __launch_bounds__(128, 2)
void gemm2_f16(const __half* __restrict__ Ahi, const __half* __restrict__ Alo,
               const __half* __restrict__ B, float* __restrict__ C, float alpha)
{
    extern __shared__ __align__(128) char dyn[];
    gemm2_body(Ahi, Alo, B, C, (__half*)0, (__half*)0, alpha,
               blockIdx.y * 128, blockIdx.x * 128, dyn);
}

// ---------------- eta/theta via HMMA ----------------
#define ENKT 192
__global__ __launch_bounds__(128)
void eta_theta_hmma(const __half* __restrict__ Xhi, const __half* __restrict__ Xlo,
                    const __half* __restrict__ Whi, const __half* __restrict__ Wlo,
                    float* __restrict__ Eta, float* __restrict__ Th)
{
    extern __shared__ __align__(128) char dyn[];
    const int tid  = threadIdx.x;
    const int wid  = tid >> 5;
    const int lane = tid & 31;
    const int bm   = blockIdx.x * 128;
    const uint32_t dynb = smem_u32(dyn);
    const uint32_t STG_E = 160 * ROWB;

    const int wm0 = wid * 32;
    const int q = lane >> 3, l8 = lane & 7;
    const uint32_t aoff = (uint32_t)((l8 + (q & 1) * 8) * ROWB + (q >> 1) * 16);
    const uint32_t boff = (uint32_t)((l8 + (q >> 1) * 8) * ROWB + (q & 1) * 16);

    float acc[2][4][4];
#pragma unroll
    for (int mf = 0; mf < 2; mf++)
#pragma unroll
        for (int nf = 0; nf < 4; nf++)
#pragma unroll
            for (int j = 0; j < 4; j++) acc[mf][nf][j] = 0.f;

#define ELD(stg, Asrc, Bsrc, k0) do { \
    uint32_t bsA = dynb + (stg) * STG_E; \
    uint32_t bsB = bsA + 128 * ROWB; \
    _Pragma("unroll") \
    for (int i_ = 0; i_ < 4; i_++) { \
        int idx_ = tid + i_ * 128; \
        int row_ = idx_ >> 2, c_ = idx_ & 3; \
        CP16(bsA + row_ * ROWB + c_ * 16, (const void*)((Asrc) + (size_t)(bm + row_) * 2048 + (k0) + c_ * 8)); \
    } \
    { int row_ = tid >> 2, c_ = tid & 3; \
      CP16(bsB + row_ * ROWB + c_ * 16, (const void*)((Bsrc) + (size_t)row_ * 2048 + (k0) + c_ * 8)); } \
    asm volatile("cp.async.commit_group;" ::: "memory"); \
} while (0)

#pragma unroll
    for (int s = 0; s < 3; s++) ELD(s, Xhi, Whi, s * BKT);

    for (int kt = 0; kt < ENKT; kt++) {
        asm volatile("cp.async.wait_group 2;" ::: "memory");
        __syncthreads();
        {
            int ktn = kt + 3;
            if (ktn < ENKT) {
                int seg = ktn >> 6;
                int k0  = (ktn & 63) * BKT;
                const __half* As_ = (seg == 1) ? Xlo : Xhi;
                const __half* Bs_ = (seg == 2) ? Wlo : Whi;
                ELD(ktn & 3, As_, Bs_, k0);
            } else {
                asm volatile("cp.async.commit_group;" ::: "memory");
            }
        }
        const uint32_t sA = dynb + (kt & 3) * STG_E;
        const uint32_t sB = sA + 128 * ROWB;
#pragma unroll
        for (int ks = 0; ks < 2; ks++) {
            uint32_t a[2][4];
#pragma unroll
            for (int mf = 0; mf < 2; mf++)
                ldm_x4(a[mf], sA + (uint32_t)(wm0 + mf * 16) * ROWB + ks * 32 + aoff);
            uint32_t b[2][4];
#pragma unroll
            for (int p = 0; p < 2; p++)
                ldm_x4(b[p], sB + (uint32_t)(p * 16) * ROWB + ks * 32 + boff);
#pragma unroll
            for (int mf = 0; mf < 2; mf++)
#pragma unroll
                for (int p = 0; p < 2; p++) {
                    mma16816(acc[mf][2*p],   a[mf], b[p][0], b[p][1]);
                    mma16816(acc[mf][2*p+1], a[mf], b[p][2], b[p][3]);
                }
        }
        __syncthreads();
    }
#undef ELD

    const int r0 = lane >> 2, c0 = (lane & 3) * 2;
#pragma unroll
    for (int mf = 0; mf < 2; mf++) {
        int tok0 = bm + wm0 + mf * 16 + r0;
#pragma unroll
        for (int nf = 0; nf < 4; nf++) {
            int col = nf * 8 + c0;
            float s0 = acc[mf][nf][0], s1 = acc[mf][nf][1];
            float s2 = acc[mf][nf][2], s3 = acc[mf][nf][3];
            float g0 = 1.f / (1.f + expf(-s0));
            float g1 = 1.f / (1.f + expf(-s1));
            float g2 = 1.f / (1.f + expf(-s2));
            float g3 = 1.f / (1.f + expf(-s3));
            if (col < 16) {
                float2 a0 = {g0, g1}, a1 = {g2, g3};
                *(float2*)(Eta + (size_t)tok0 * Hh + col)       = a0;
                *(float2*)(Eta + (size_t)(tok0 + 8) * Hh + col) = a1;
            } else {
                float2 a0 = {0.1f*g0, 0.1f*g1}, a1 = {0.1f*g2, 0.1f*g3};
                *(float2*)(Th + (size_t)tok0 * Hh + col - 16)       = a0;
                *(float2*)(Th + (size_t)(tok0 + 8) * Hh + col - 16) = a1;
            }
        }
    }
}

// ---------------- decay prep ----------------
__global__ __launch_bounds__(256)
void decay_prep_kernel(const float* __restrict__ Eta, const float* __restrict__ Th,
                       float* __restrict__ Lec, float* __restrict__ Elec,
                       float* __restrict__ Coef)
{
    const int wc   = blockIdx.x * 8 + (threadIdx.x >> 5);
    const int lane = threadIdx.x & 31;
    const int bh = wc >> 6, ct = wc & 63;
    const int b = bh >> 4, h = bh & 15;
    const size_t tokbase = (size_t)b * Tt;
    const int t = ct * BT + lane * 2;
    float e0  = Eta[(tokbase + t) * Hh + h];
    float e1  = Eta[(tokbase + t + 1) * Hh + h];
    float th0 = Th [(tokbase + t) * Hh + h];
    float th1 = Th [(tokbase + t + 1) * Hh + h];
    float l0 = logf(fmaxf(e0, 1e-8f));
    float l1 = logf(fmaxf(e1, 1e-8f));
    float s = l0 + l1;
#pragma unroll
    for (int o = 1; o < 32; o <<= 1) {
        float n = __shfl_up_sync(0xffffffffu, s, o);
        if (lane >= o) s += n;
    }
    float lec1 = s;
    float lec0 = s - l1;
    float ltot = __shfl_sync(0xffffffffu, s, 31);
    size_t base = (size_t)bh * Tt + t;
    float2 lv = {lec0, lec1};
    float2 ev = {expf(lec0), expf(lec1)};
    float2 cv = {expf(ltot - lec0) * th0, expf(ltot - lec1) * th1};
    *(float2*)(Lec  + base) = lv;
    *(float2*)(Elec + base) = ev;
    *(float2*)(Coef + base) = cv;
}

// ---------------- qkm via HMMA ----------------
#define QROW 136
#define QROWB (QROW*2)
__global__ __launch_bounds__(128)
void qkm_hmma(const __half* __restrict__ Qhi, const __half* __restrict__ Qlo,
              const __half* __restrict__ Khi, const __half* __restrict__ Klo,
              const float* __restrict__ Lec, const float* __restrict__ Th,
              float* __restrict__ Mout)
{
    extern __shared__ __align__(16) char qsmc[];
    float*  sLec = (float*)(qsmc + 4*64*QROWB);
    float*  sTh  = sLec + 64;

    const int blk = blockIdx.x;
    const int bh = blk >> 6, ct = blk & 63;
    const int b = bh >> 4, h = bh & 15;
    const int tid = threadIdx.x;
    const size_t tokbase = (size_t)b * Tt;
    const int t0 = ct * BT;
    const size_t goff = tokbase * HD + (size_t)h * Kk;

    const uint32_t sb = smem_u32(qsmc);
#pragma unroll
    for (int i = 0; i < 8; i++) {
        int idx = tid + i * 128;
        int r = idx >> 4, c = (idx & 15) * 8;
        uint32_t d0 = sb + (uint32_t)(r * QROW + c) * 2u;
        size_t gsrc = goff + (size_t)(t0 + r) * HD + c;
        CP16(d0,                (const void*)(Qhi + gsrc));
        CP16(d0 + 64u*QROWB,    (const void*)(Qlo + gsrc));
        CP16(d0 + 2u*64u*QROWB, (const void*)(Khi + gsrc));
        CP16(d0 + 3u*64u*QROWB, (const void*)(Klo + gsrc));
    }
    if (tid < 64) {
        sLec[tid] = Lec[(size_t)bh * Tt + t0 + tid];
        sTh[tid]  = Th[(tokbase + t0 + tid) * Hh + h];
    }
    asm volatile("cp.async.commit_group;" ::: "memory");
    asm volatile("cp.async.wait_group 0;" ::: "memory");
    __syncthreads();

    const int wid = tid >> 5, lane = tid & 31;
    const int wm0 = wid * 16;
    const int q8 = lane >> 3, l8 = lane & 7;
    const uint32_t aoff = (uint32_t)((l8 + (q8 & 1) * 8) * QROWB + (q8 >> 1) * 16);
    const uint32_t boff = (uint32_t)((l8 + (q8 >> 1) * 8) * QROWB + (q8 & 1) * 16);

    float acc[8][4];
#pragma unroll
    for (int nf = 0; nf < 8; nf++)
#pragma unroll
        for (int j = 0; j < 4; j++) acc[nf][j] = 0.f;

    const uint32_t bQh = sb, bQl = sb + 64u*QROWB, bKh = sb + 2u*64u*QROWB, bKl = sb + 3u*64u*QROWB;
    const uint32_t Ab[3] = {bQh, bQl, bQh};
    const uint32_t Bbv[3] = {bKh, bKh, bKl};
#pragma unroll
    for (int seg = 0; seg < 3; seg++) {
        const uint32_t As = Ab[seg] + (uint32_t)wm0 * QROWB;
        const uint32_t Bs = Bbv[seg];
#pragma unroll
        for (int ks = 0; ks < 8; ks++) {
            uint32_t a[4];
            ldm_x4(a, As + ks * 32 + aoff);
#pragma unroll
            for (int p = 0; p < 4; p++) {
                uint32_t bb[4];
                ldm_x4(bb, Bs + (uint32_t)(p * 16) * QROWB + ks * 32 + boff);
                mma16816(acc[2*p],   a, bb[0], bb[1]);
                mma16816(acc[2*p+1], a, bb[2], bb[3]);
            }
        }
    }

    const int r0 = lane >> 2, c0 = (lane & 3) * 2;
    float* Mo = Mout + (size_t)blk * (BT*BT);
#pragma unroll
    for (int half_ = 0; half_ < 2; half_++) {
        int ii = wm0 + r0 + half_ * 8;
        float li = sLec[ii];
#pragma unroll
        for (int nf = 0; nf < 8; nf++) {
            int col = nf * 8 + c0;
            float m0 = 0.f, m1 = 0.f;
            if (col <= ii)
                m0 = acc[nf][half_*2]   * expf(fminf(li - sLec[col], 0.f)) * sTh[col];
            if (col + 1 <= ii)
                m1 = acc[nf][half_*2+1] * expf(fminf(li - sLec[col+1], 0.f)) * sTh[col+1];
            float2 mv = {m0, m1};
            *(float2*)(Mo + ii * 64 + col) = mv;
        }
    }
}

// ---------------- scan: phase A on HMMA (W split fp16 per chunk), B/C on f32x2 ----------------
// smem layout (floats then halves):
//   sW   fp32 [32 v][132]      state W[v][k]
//   sVE  fp32 [64][32]         v then e
//   sZQ  fp32 [64][32]         elec*(q@W)
//   sM   fp32 [64][68]
//   sElec/sCoef [64] each
//   sWh,sWl  half [32][136]
//   sKh,sKl,sQh,sQl half [64][136]
#define SROW 136
#define SROWB (SROW*2)
__global__ __launch_bounds__(256, 1)
void scan_kernel(const __half* __restrict__ Qhi, const __half* __restrict__ Qlo,
                 const __half* __restrict__ Khi, const __half* __restrict__ Klo,
                 const float* __restrict__ Vc, const float* __restrict__ Elec,
                 const float* __restrict__ Coef, const float* __restrict__ Mg,
                 float* __restrict__ Z)
{
    extern __shared__ float sm[];
    float* sW    = sm;                    // 32*132 = 4224
    float* sVE   = sW + 32*132;           // 2048
    float* sZQ   = sVE + 64*32;           // 2048
    float* sM    = sZQ + 64*32;           // 4352
    float* sElec = sM + 64*68;            // 64
    float* sCoef = sElec + 64;            // 64
    __half* sWh  = (__half*)(sCoef + 64); // 32*136
    __half* sWl  = sWh + 32*SROW;
    __half* sKh  = sWl + 32*SROW;
    __half* sKl  = sKh + 64*SROW;
    __half* sQh  = sKl + 64*SROW;
    __half* sQl  = sQh + 64*SROW;

    const int tid = threadIdx.x;
    const int bh  = blockIdx.x;
    const int b = bh >> 4, h = bh & 15;
    const int vs0 = blockIdx.y * VS;

    const size_t tokbase = (size_t)b * Tt;
    const size_t goff = tokbase * HD + (size_t)h * Kk;
    const __half* Qh = Qhi + goff;
    const __half* Ql = Qlo + goff;
    const __half* Kh = Khi + goff;
    const __half* Kl = Klo + goff;
    const float* Vp = Vc + tokbase*HD + (size_t)h*Vv + vs0;
    const float* Mp = Mg + (size_t)bh * (NT*BT*BT);
    float*       Zp = Z  + tokbase*HD + (size_t)h*Vv + vs0;

    for (int i = tid; i < 32*132; i += 256) sW[i] = 0.f;

    // MMA thread map (phase A): 8 warps = 4(M) x 2(N)
    const int wid = tid >> 5, lane = tid & 31;
    const int wm = wid >> 1, wn = wid & 1;
    const int q8 = lane >> 3, l8 = lane & 7;
    const uint32_t aoff = (uint32_t)((l8 + (q8 & 1) * 8) * SROWB + (q8 >> 1) * 16);
    const uint32_t boff = (uint32_t)((l8 + (q8 >> 1) * 8) * SROWB + (q8 & 1) * 16);
    const uint32_t uWh = smem_u32(sWh), uWl = smem_u32(sWl);
    const uint32_t uKh = smem_u32(sKh), uKl = smem_u32(sKl);
    const uint32_t uQh = smem_u32(sQh), uQl = smem_u32(sQl);
    const int fr0 = lane >> 2, fc0 = (lane & 3) * 2;

    // B/C thread map
    const int tx = tid & 7;               // v quad
    const int ty = tid >> 3;              // 0..31
    const int v0 = tx << 2;
    const int ta = ty*2, tb = ta + 1;
    const int k0 = ty << 2;               // 4 k cols for W update

    for (int ct = 0; ct < NT; ct++) {
        const int t0 = ct * BT;
        __syncthreads();   // prev chunk readers done; W update visible

        // ---- loads: fp16 tiles (uint4 = 8 halfs) ----
#pragma unroll
        for (int i = 0; i < 4; i++) {
            int idx = tid + i*256;                 // 0..1023
            int r = idx >> 4, c = (idx & 15) * 8;
            size_t off = (size_t)(t0 + r) * HD + c;
            *(uint4*)&sKh[r*SROW + c] = *(const uint4*)(Kh + off);
            *(uint4*)&sKl[r*SROW + c] = *(const uint4*)(Kl + off);
            *(uint4*)&sQh[r*SROW + c] = *(const uint4*)(Qh + off);
            *(uint4*)&sQl[r*SROW + c] = *(const uint4*)(Ql + off);
        }
#pragma unroll
        for (int i = 0; i < 2; i++) {
            int idx = tid + i*256;
            int r = idx >> 3;
            int c = (idx & 7) << 2;
            *(float4*)&sVE[r*VS + c] = *(const float4*)(Vp + (size_t)(t0+r)*HD + c);
        }
#pragma unroll
        for (int i = 0; i < 4; i++) {
            int idx = tid + i*256;
            int r = idx >> 4;
            int c = (idx & 15) << 2;
            *(float4*)&sM[r*68 + c] = *(const float4*)(Mp + ct*(BT*BT) + r*64 + c);
        }
        if (tid < 64) {
            sElec[tid] = Elec[(size_t)bh*Tt + t0 + tid];
            sCoef[tid] = Coef[(size_t)bh*Tt + t0 + tid];
        }
        // ---- W fp32 -> fp16 hi/lo split (reads sW, W update from prev chunk done) ----
#pragma unroll
        for (int i = 0; i < 4; i++) {
            int idx = tid + i*256;                 // 0..1023 float4 groups
            int r = idx >> 5;                      // 0..31
            int c4 = (idx & 31) << 2;              // 0..124
            float4 w4 = *(float4*)&sW[r*132 + c4];
            __half hx = __float2half(w4.x), hy = __float2half(w4.y);
            __half hz = __float2half(w4.z), hw = __float2half(w4.w);
            __half lx = __float2half(w4.x - __half2float(hx));
            __half ly = __float2half(w4.y - __half2float(hy));
            __half lz = __float2half(w4.z - __half2float(hz));
            __half lw = __float2half(w4.w - __half2float(hw));
            *(__half2*)&sWh[r*SROW + c4]     = __halves2half2(hx, hy);
            *(__half2*)&sWh[r*SROW + c4 + 2] = __halves2half2(hz, hw);
            *(__half2*)&sWl[r*SROW + c4]     = __halves2half2(lx, ly);
            *(__half2*)&sWl[r*SROW + c4 + 2] = __halves2half2(lz, lw);
        }
        __syncthreads();

        // ---- Phase A (HMMA): e = k@W^T - v ; zq = elec*(q@W^T) ----
        {
            float ae[2][4], az[2][4];
#pragma unroll
            for (int nf = 0; nf < 2; nf++)
#pragma unroll
                for (int j = 0; j < 4; j++) { ae[nf][j] = 0.f; az[nf][j] = 0.f; }

            const uint32_t Akv[3] = {uKh, uKl, uKh};
            const uint32_t Aqv[3] = {uQh, uQl, uQh};
            const uint32_t Bwv[3] = {uWh, uWh, uWl};
#pragma unroll
            for (int seg = 0; seg < 3; seg++) {
                const uint32_t Ak = Akv[seg] + (uint32_t)(wm*16) * SROWB;
                const uint32_t Aq = Aqv[seg] + (uint32_t)(wm*16) * SROWB;
                const uint32_t Bw = Bwv[seg] + (uint32_t)(wn*16) * SROWB;
#pragma unroll
                for (int ks = 0; ks < 8; ks++) {
                    uint32_t bb[4];
                    ldm_x4(bb, Bw + ks * 32 + boff);
                    uint32_t ak[4];
                    ldm_x4(ak, Ak + ks * 32 + aoff);
                    mma16816(ae[0], ak, bb[0], bb[1]);
                    mma16816(ae[1], ak, bb[2], bb[3]);
                    uint32_t aq[4];
                    ldm_x4(aq, Aq + ks * 32 + aoff);
                    mma16816(az[0], aq, bb[0], bb[1]);
                    mma16816(az[1], aq, bb[2], bb[3]);
                }
            }
            // epilogue: sVE = acc_e - v ; sZQ = elec * acc_z
#pragma unroll
            for (int h8 = 0; h8 < 2; h8++) {
                int r = wm*16 + fr0 + h8*8;
                float el = sElec[r];
#pragma unroll
                for (int nf = 0; nf < 2; nf++) {
                    int c = wn*16 + nf*8 + fc0;
                    float2 vv = *(float2*)&sVE[r*VS + c];
                    float2 ev = {ae[nf][h8*2] - vv.x, ae[nf][h8*2+1] - vv.y};
                    *(float2*)&sVE[r*VS + c] = ev;
                    float2 zv = {az[nf][h8*2] * el, az[nf][h8*2+1] * el};
                    *(float2*)&sZQ[r*VS + c] = zv;
                }
            }
        }
        __syncthreads();

        // ---- Fused B+C (f32x2): z = zq - M@e ; W[v][k] update ----
        {
            float4 za4 = *(float4*)&sZQ[ta*VS + v0];
            float4 zb4 = *(float4*)&sZQ[tb*VS + v0];
            u64t za01 = pk2(za4.x, za4.y), za23 = pk2(za4.z, za4.w);
            u64t zb01 = pk2(zb4.x, zb4.y), zb23 = pk2(zb4.z, zb4.w);
            u64t sa01 = 0ull, sa23 = 0ull, sb01 = 0ull, sb23 = 0ull;
            u64t ca01[4], ca23[4];   // [v] over k-pairs (k0,k0+1),(k0+2,k0+3)
#pragma unroll
            for (int i = 0; i < 4; i++) { ca01[i] = 0ull; ca23[i] = 0ull; }
#pragma unroll 2
            for (int t = 0; t < BT; t++) {
                double2 ed = *(double2*)&sVE[t*VS + v0];
                u64t e01 = d2u(ed.x), e23 = d2u(ed.y);
                float ma = sM[ta*68 + t];
                float mb = sM[tb*68 + t];
                u64t ma2 = pk2(ma, ma), mb2 = pk2(mb, mb);
                sa01 = fma2(ma2, e01, sa01);
                sa23 = fma2(ma2, e23, sa23);
                sb01 = fma2(mb2, e01, sb01);
                sb23 = fma2(mb2, e23, sb23);
                float cf = -sCoef[t];
                float e0, e1, e2, e3;
                upk2(e01, e0, e1); upk2(e23, e2, e3);
                uint2 kh2 = *(uint2*)&sKh[t*SROW + k0];
                uint2 kl2 = *(uint2*)&sKl[t*SROW + k0];
                float4 k4 = cvt4(kh2, kl2);
                u64t k01 = pk2(k4.x, k4.y), k23 = pk2(k4.z, k4.w);
                u64t c0p = pk2(cf*e0, cf*e0), c1p = pk2(cf*e1, cf*e1);
                u64t c2p = pk2(cf*e2, cf*e2), c3p = pk2(cf*e3, cf*e3);
                ca01[0] = fma2(k01, c0p, ca01[0]); ca23[0] = fma2(k23, c0p, ca23[0]);
                ca01[1] = fma2(k01, c1p, ca01[1]); ca23[1] = fma2(k23, c1p, ca23[1]);
                ca01[2] = fma2(k01, c2p, ca01[2]); ca23[2] = fma2(k23, c2p, ca23[2]);
                ca01[3] = fma2(k01, c3p, ca01[3]); ca23[3] = fma2(k23, c3p, ca23[3]);
            }
            float z0, z1, s0, s1;
            float4 oa, ob;
            upk2(za01, z0, z1); upk2(sa01, s0, s1); oa.x = z0 - s0; oa.y = z1 - s1;
            upk2(za23, z0, z1); upk2(sa23, s0, s1); oa.z = z0 - s0; oa.w = z1 - s1;
            upk2(zb01, z0, z1); upk2(sb01, s0, s1); ob.x = z0 - s0; ob.y = z1 - s1;
            upk2(zb23, z0, z1); upk2(sb23, s0, s1); ob.z = z0 - s0; ob.w = z1 - s1;
            *(float4*)(Zp + (size_t)(t0+ta)*HD + v0) = oa;
            *(float4*)(Zp + (size_t)(t0+tb)*HD + v0) = ob;

            // W[v0+i][k0..k0+3] = W*decay + ca (sW read only by split step, guarded by top barrier)
            float dk = sElec[63];
            u64t dk2 = pk2(dk, dk);
#pragma unroll
            for (int i = 0; i < 4; i++) {
                double2 wv = *(double2*)&sW[(v0+i)*132 + k0];
                u64t w01 = fma2(d2u(wv.x), dk2, ca01[i]);
                u64t w23 = fma2(d2u(wv.y), dk2, ca23[i]);
                *(double2*)&sW[(v0+i)*132 + k0] = make_double2(u2d(w01), u2d(w23));
            }
        }
    }
}

// ---------------- gated RMS norm -> fp16 hi/lo split ----------------
__global__ __launch_bounds__(256)
void gated_rms_split(const float* __restrict__ Zin, const float* __restrict__ G,
                     const float* __restrict__ nw, __half* __restrict__ hi,
                     __half* __restrict__ lo)
{
    const int gw   = blockIdx.x * 8 + (threadIdx.x >> 5);
    const int lane = threadIdx.x & 31;
    const size_t base = (size_t)gw * 128;
    float4 zv = *(const float4*)(Zin + base + lane*4);
    float ss = zv.x*zv.x + zv.y*zv.y + zv.z*zv.z + zv.w*zv.w;
#pragma unroll
    for (int o = 16; o; o >>= 1) ss += __shfl_xor_sync(0xffffffffu, ss, o);
    float r = rsqrtf(ss * (1.f/128.f) + 1e-5f);
    float4 gv = *(const float4*)(G  + base + lane*4);
    float4 wv = *(const float4*)(nw + lane*4);
    float ov[4];
    ov[0] = zv.x*r*wv.x * (gv.x / (1.f + expf(-gv.x)));
    ov[1] = zv.y*r*wv.y * (gv.y / (1.f + expf(-gv.y)));
    ov[2] = zv.z*r*wv.z * (gv.z / (1.f + expf(-gv.z)));
    ov[3] = zv.w*r*wv.w * (gv.w / (1.f + expf(-gv.w)));
    __align__(8) __half h[4], l[4];
#pragma unroll
    for (int j = 0; j < 4; j++) {
        h[j] = __float2half(ov[j]);
        l[j] = __float2half(ov[j] - __half2float(h[j]));
    }
    *(uint2*)(hi + base + lane*4) = *(uint2*)h;
    *(uint2*)(lo + base + lane*4) = *(uint2*)l;
}

// ---------------- launch ----------------
extern "C" void kernel_launch(void* const* d_in, const int* in_sizes, int n_in,
                              void* d_out, int out_size)
{
    const float* X    = (const float*)d_in[0];
    const float* Wq   = (const float*)d_in[1];
    const float* Wk   = (const float*)d_in[2];
    const float* Wv   = (const float*)d_in[3];
    const float* Weta = (const float*)d_in[4];
    const float* Wth  = (const float*)d_in[5];
    const float* Wg   = (const float*)d_in[6];
    const float* nw   = (const float*)d_in[7];
    const float* Wo   = (const float*)d_in[8];
    float* out = (float*)d_out;

    float *v, *g, *z, *eta, *th, *lec, *elec, *coef, *Mbuf;
    __half *xhi, *xlo, *w16, *w32hi, *w32lo, *oghi, *oglo, *qhi, *qlo, *khi, *klo;
    cudaGetSymbolAddress((void**)&v,    g_v);
    cudaGetSymbolAddress((void**)&g,    g_g);
    cudaGetSymbolAddress((void**)&z,    g_z);
    cudaGetSymbolAddress((void**)&eta,  g_eta);
    cudaGetSymbolAddress((void**)&th,   g_theta);
    cudaGetSymbolAddress((void**)&lec,  g_lec);
    cudaGetSymbolAddress((void**)&elec, g_elec);
    cudaGetSymbolAddress((void**)&coef, g_coef);
    cudaGetSymbolAddress((void**)&Mbuf, g_M);
    cudaGetSymbolAddress((void**)&xhi,  g_xhi);
    cudaGetSymbolAddress((void**)&xlo,  g_xlo);
    cudaGetSymbolAddress((void**)&w16,  g_w16);
    cudaGetSymbolAddress((void**)&w32hi,g_w32hi);
    cudaGetSymbolAddress((void**)&w32lo,g_w32lo);
    cudaGetSymbolAddress((void**)&oghi, g_oghi);
    cudaGetSymbolAddress((void**)&oglo, g_oglo);
    cudaGetSymbolAddress((void**)&qhi,  g_qhi);
    cudaGetSymbolAddress((void**)&qlo,  g_qlo);
    cudaGetSymbolAddress((void**)&khi,  g_khi);
    cudaGetSymbolAddress((void**)&klo,  g_klo);

    // scan smem: fp32 regions (12800 floats) + fp16 regions (43520 halfs)
    const int scan_smem = 12800*4 + 43520*2;   // 138240
    cudaFuncSetAttribute(scan_kernel, cudaFuncAttributeMaxDynamicSharedMemorySize, scan_smem);
    const int qkm_smem = 4*64*QROWB + 2*64*4;   // 70144
    cudaFuncSetAttribute(qkm_hmma, cudaFuncAttributeMaxDynamicSharedMemorySize, qkm_smem);
    const int gemm_smem = NSTG * STG_BYTES;   // 81920
    cudaFuncSetAttribute(gemm2_f16, cudaFuncAttributeMaxDynamicSharedMemorySize, gemm_smem);
    cudaFuncSetAttribute(gemm2_qkvg, cudaFuncAttributeMaxDynamicSharedMemorySize, gemm_smem);
    const int eta_smem = 4 * 160 * ROWB;      // 51200
    cudaFuncSetAttribute(eta_theta_hmma, cudaFuncAttributeMaxDynamicSharedMemorySize, eta_smem);

    const int WN = Dd * Dd;
    const float qscale = 0.08838834764831845f;  // 128^-0.5

    split_fp16_kernel<<<TOKS*Dd/4/256, 256>>>(X, xhi, xlo, TOKS*Dd/4);
    conv_fp16_4<<<4*4096, 256>>>(Wq, Wk, Wv, Wg, w16);
    conv_fp16_kernel<<<4096, 256>>>(Wo, w16 + 4*(size_t)WN, WN/4);
    split_w32<<<32*Dd/4/256, 256>>>(Weta, Wth, w32hi, w32lo);

    eta_theta_hmma<<<TOKS/128, 128, eta_smem>>>(xhi, xlo, w32hi, w32lo, eta, th);
    decay_prep_kernel<<<2048/8, 256>>>(eta, th, lec, elec, coef);

    gemm2_qkvg<<<dim3(64, TOKS/128), 128, gemm_smem>>>(xhi, xlo, w16, v, g,
                                                       qhi, qlo, khi, klo, qscale);

    qkm_hmma<<<32*NT, 128, qkm_smem>>>(qhi, qlo, khi, klo, lec, th, Mbuf);

    scan_kernel<<<dim3(Bb*Hh, NVS), 256, scan_smem>>>(qhi, qlo, khi, klo, v, elec, coef, Mbuf, z);

    gated_rms_split<<<TOKS*Hh/8, 256>>>(z, g, nw, oghi, oglo);
    gemm2_f16<<<dim3(HD/128, TOKS/128), 128, gemm_smem>>>(oghi, oglo, w16 + 4*(size_t)WN, out, 1.f);
}

// round 15
// speedup vs baseline: 1.8212x; 1.1606x over previous
#include <cuda_runtime.h>
#include <cuda_fp16.h>
#include <math.h>
#include <cstdint>

// Problem constants (fixed shapes)
#define Bb 2
#define Tt 4096
#define Dd 2048
#define Hh 16
#define Kk 128
#define Vv 128
#define BT 64
#define NT 64
#define TOKS (Bb*Tt)          // 8192
#define HD   (Hh*Kk)          // 2048
#define VS   32               // v-slice width in scan
#define NVS  (Vv/VS)          // 4

// ---------------- scratch (device globals; no runtime alloc) ----------------
__device__ float g_v [TOKS*HD];
__device__ float g_g [TOKS*HD];
__device__ float g_z [TOKS*HD];
__device__ float g_eta  [TOKS*Hh];
__device__ float g_theta[TOKS*Hh];
__device__ float g_lec  [32*Tt];
__device__ float g_elec [32*Tt];
__device__ float g_coef [32*Tt];
__device__ float g_M    [32*NT*BT*BT];
__device__ __half g_xhi[TOKS*Dd];
__device__ __half g_xlo[TOKS*Dd];
__device__ __half g_w16[5*Dd*Dd];
__device__ __half g_w32hi[32*Dd];
__device__ __half g_w32lo[32*Dd];
__device__ __half g_og16[TOKS*HD];
__device__ __half g_qhi[TOKS*HD];
__device__ __half g_qlo[TOKS*HD];
__device__ __half g_khi[TOKS*HD];
__device__ __half g_klo[TOKS*HD];

// ---------------- helpers ----------------
typedef unsigned long long u64t;

__device__ __forceinline__ uint32_t smem_u32(const void* p) {
    uint32_t a;
    asm("{ .reg .u64 t; cvta.to.shared.u64 t, %1; cvt.u32.u64 %0, t; }" : "=r"(a) : "l"(p));
    return a;
}
__device__ __forceinline__ void ldm_x4(uint32_t (&r)[4], uint32_t addr) {
    asm volatile("ldmatrix.sync.aligned.m8n8.x4.shared.b16 {%0,%1,%2,%3}, [%4];"
                 : "=r"(r[0]), "=r"(r[1]), "=r"(r[2]), "=r"(r[3]) : "r"(addr));
}
__device__ __forceinline__ void mma16816(float (&d)[4], const uint32_t (&a)[4],
                                         uint32_t b0, uint32_t b1) {
    asm volatile(
        "mma.sync.aligned.m16n8k16.row.col.f32.f16.f16.f32 "
        "{%0,%1,%2,%3}, {%4,%5,%6,%7}, {%8,%9}, {%0,%1,%2,%3};"
        : "+f"(d[0]), "+f"(d[1]), "+f"(d[2]), "+f"(d[3])
        : "r"(a[0]), "r"(a[1]), "r"(a[2]), "r"(a[3]), "r"(b0), "r"(b1));
}
// packed f32x2 (FFMA2 path)
__device__ __forceinline__ u64t pk2(float lo, float hi) {
    u64t d; asm("mov.b64 %0, {%1,%2};" : "=l"(d) : "f"(lo), "f"(hi)); return d;
}
__device__ __forceinline__ void upk2(u64t s, float& lo, float& hi) {
    asm("mov.b64 {%0,%1}, %2;" : "=f"(lo), "=f"(hi) : "l"(s));
}
__device__ __forceinline__ u64t fma2(u64t a, u64t b, u64t c) {
    u64t d; asm("fma.rn.f32x2 %0, %1, %2, %3;" : "=l"(d) : "l"(a), "l"(b), "l"(c)); return d;
}
__device__ __forceinline__ u64t mul2(u64t a, u64t b) {
    u64t d; asm("mul.rn.f32x2 %0, %1, %2;" : "=l"(d) : "l"(a), "l"(b)); return d;
}
__device__ __forceinline__ u64t d2u(double x) { return __double_as_longlong(x); }
__device__ __forceinline__ double u2d(u64t x) { return __longlong_as_double(x); }
#define CP16(dst, src) \
    asm volatile("cp.async.cg.shared.global [%0], [%1], 16;" :: "r"(dst), "l"(src) : "memory")
// combine hi/lo fp16 quad -> float4
__device__ __forceinline__ float4 cvt4(uint2 h, uint2 l) {
    float2 f0 = __half22float2(*(__half2*)&h.x);
    float2 f1 = __half22float2(*(__half2*)&h.y);
    float2 g0 = __half22float2(*(__half2*)&l.x);
    float2 g1 = __half22float2(*(__half2*)&l.y);
    float4 r;
    r.x = f0.x + g0.x; r.y = f0.y + g0.y;
    r.z = f1.x + g1.x; r.w = f1.y + g1.y;
    return r;
}

// ---------------- fp32 -> (hi,lo) fp16 split (activations) ----------------
__global__ __launch_bounds__(256)
void split_fp16_kernel(const float* __restrict__ x, __half* __restrict__ hi,
                       __half* __restrict__ lo, int n4)
{
    int i = blockIdx.x * 256 + threadIdx.x;
    if (i >= n4) return;
    float4 v = ((const float4*)x)[i];
    float vv[4] = {v.x, v.y, v.z, v.w};
    __align__(8) __half h[4], l[4];
#pragma unroll
    for (int j = 0; j < 4; j++) {
        h[j] = __float2half(vv[j]);
        l[j] = __float2half(vv[j] - __half2float(h[j]));
    }
    ((uint2*)hi)[i] = *(uint2*)h;
    ((uint2*)lo)[i] = *(uint2*)l;
}

// ---------------- fp32 -> fp16 convert (single weight) ----------------
__global__ __launch_bounds__(256)
void conv_fp16_kernel(const float* __restrict__ x, __half* __restrict__ w, int n4)
{
    int i = blockIdx.x * 256 + threadIdx.x;
    if (i >= n4) return;
    float4 v = ((const float4*)x)[i];
    __align__(8) __half h[4];
    h[0] = __float2half(v.x); h[1] = __float2half(v.y);
    h[2] = __float2half(v.z); h[3] = __float2half(v.w);
    ((uint2*)w)[i] = *(uint2*)h;
}

// ---------------- fp32 -> fp16 convert, 4 weights in one launch ----------------
__global__ __launch_bounds__(256)
void conv_fp16_4(const float* __restrict__ w0, const float* __restrict__ w1,
                 const float* __restrict__ w2, const float* __restrict__ w3,
                 __half* __restrict__ out)
{
    const int sel = blockIdx.x >> 12;
    const int i = (blockIdx.x & 4095) * 256 + threadIdx.x;
    const float* src = (sel == 0) ? w0 : (sel == 1) ? w1 : (sel == 2) ? w2 : w3;
    float4 v = ((const float4*)src)[i];
    __align__(8) __half h[4];
    h[0] = __float2half(v.x); h[1] = __float2half(v.y);
    h[2] = __float2half(v.z); h[3] = __float2half(v.w);
    ((uint2*)(out + (size_t)sel * Dd * Dd))[i] = *(uint2*)h;
}

// ---------------- Weta||Wth -> 32-row hi/lo fp16 split ----------------
__global__ __launch_bounds__(256)
void split_w32(const float* __restrict__ Weta, const float* __restrict__ Wth,
               __half* __restrict__ hi, __half* __restrict__ lo)
{
    int i = blockIdx.x * 256 + threadIdx.x;
    int e = i * 4;
    const float* src = (e < 16*Dd) ? (Weta + e) : (Wth + e - 16*Dd);
    float4 v = *(const float4*)src;
    float vv[4] = {v.x, v.y, v.z, v.w};
    __align__(8) __half h[4], l[4];
#pragma unroll
    for (int j = 0; j < 4; j++) {
        h[j] = __float2half(vv[j]);
        l[j] = __float2half(vv[j] - __half2float(h[j]));
    }
    ((uint2*)hi)[i] = *(uint2*)h;
    ((uint2*)lo)[i] = *(uint2*)l;
}

// ---------------- HMMA fp16 GEMM body (runtime segment count) ----------------
#define BKT 32
#define ROWB 80                 // smem row stride (32 fp16 + 8 pad)
#define STG_BYTES (128*ROWB*2)  // 20480
#define NSTG 4

__device__ __forceinline__ void ld_stage(uint32_t sA, uint32_t sB,
    const __half* __restrict__ A, const __half* __restrict__ B,
    int bm, int bn, int k0, int tid)
{
#pragma unroll
    for (int i = 0; i < 4; i++) {
        int idx = tid + i * 128;
        int row = idx >> 2, c = idx & 3;
        uint32_t dA = sA + row * ROWB + c * 16;
        const void* pA = A + (size_t)(bm + row) * 2048 + k0 + c * 8;
        CP16(dA, pA);
        uint32_t dB = sB + row * ROWB + c * 16;
        const void* pB = B + (size_t)(bn + row) * 2048 + k0 + c * 8;
        CP16(dB, pB);
    }
}

// writes fp32 C, or fp16 hi/lo dual-store (Hhi&Hlo), or single fp16 (Hhi only)
__device__ __forceinline__ void gemm2_body(
    const __half* __restrict__ Ahi, const __half* __restrict__ Alo,
    const __half* __restrict__ B, int nkt,
    float* __restrict__ C, __half* __restrict__ Hhi, __half* __restrict__ Hlo,
    float alpha, int bm, int bn, char* dyn)
{
    const int tid  = threadIdx.x;
    const int wid  = tid >> 5;
    const int lane = tid & 31;
    const uint32_t dynb = smem_u32(dyn);

    const int wm0 = (wid >> 1) * 64;
    const int wn0 = (wid & 1) * 64;

    const int q = lane >> 3, l8 = lane & 7;
    const uint32_t aoff = (uint32_t)((l8 + (q & 1) * 8) * ROWB + (q >> 1) * 16);
    const uint32_t boff = (uint32_t)((l8 + (q >> 1) * 8) * ROWB + (q & 1) * 16);

    float acc[4][8][4];
#pragma unroll
    for (int mf = 0; mf < 4; mf++)
#pragma unroll
        for (int nf = 0; nf < 8; nf++)
#pragma unroll
            for (int j = 0; j < 4; j++) acc[mf][nf][j] = 0.f;

#pragma unroll
    for (int s = 0; s < 3; s++) {
        uint32_t base = dynb + s * STG_BYTES;
        ld_stage(base, base + 128 * ROWB, Ahi, B, bm, bn, s * BKT, tid);
        asm volatile("cp.async.commit_group;" ::: "memory");
    }

    for (int kt = 0; kt < nkt; kt++) {
        asm volatile("cp.async.wait_group 2;" ::: "memory");
        __syncthreads();

        {
            int ktn = kt + 3;
            if (ktn < nkt) {
                int seg = ktn >> 6;
                int k0  = (ktn & 63) * BKT;
                const __half* As_ = seg ? Alo : Ahi;
                uint32_t base = dynb + (ktn & 3) * STG_BYTES;
                ld_stage(base, base + 128 * ROWB, As_, B, bm, bn, k0, tid);
            }
            asm volatile("cp.async.commit_group;" ::: "memory");
        }

        const uint32_t sA = dynb + (kt & 3) * STG_BYTES;
        const uint32_t sB = sA + 128 * ROWB;
#pragma unroll
        for (int ks = 0; ks < 2; ks++) {
            uint32_t a[4][4];
#pragma unroll
            for (int mf = 0; mf < 4; mf++)
                ldm_x4(a[mf], sA + (uint32_t)(wm0 + mf * 16) * ROWB + ks * 32 + aoff);
            uint32_t b[4][4];
#pragma unroll
            for (int p = 0; p < 4; p++)
                ldm_x4(b[p], sB + (uint32_t)(wn0 + p * 16) * ROWB + ks * 32 + boff);
#pragma unroll
            for (int mf = 0; mf < 4; mf++)
#pragma unroll
                for (int p = 0; p < 4; p++) {
                    mma16816(acc[mf][2*p],   a[mf], b[p][0], b[p][1]);
                    mma16816(acc[mf][2*p+1], a[mf], b[p][2], b[p][3]);
                }
        }
    }

    const int r0 = lane >> 2, c0 = (lane & 3) * 2;
#pragma unroll
    for (int mf = 0; mf < 4; mf++) {
        int rowa = bm + wm0 + mf * 16 + r0;
#pragma unroll
        for (int nf = 0; nf < 8; nf++) {
            int col = bn + wn0 + nf * 8 + c0;
            float2 v0 = {alpha * acc[mf][nf][0], alpha * acc[mf][nf][1]};
            float2 v1 = {alpha * acc[mf][nf][2], alpha * acc[mf][nf][3]};
            if (C) {
                *(float2*)(C + (size_t)rowa * 2048 + col)       = v0;
                *(float2*)(C + (size_t)(rowa + 8) * 2048 + col) = v1;
            }
            if (Hhi) {
                __half hx = __float2half(v0.x), hy = __float2half(v0.y);
                *(__half2*)(Hhi + (size_t)rowa * 2048 + col) = __halves2half2(hx, hy);
                if (Hlo) {
                    __half lx = __float2half(v0.x - __half2float(hx));
                    __half ly = __float2half(v0.y - __half2float(hy));
                    *(__half2*)(Hlo + (size_t)rowa * 2048 + col) = __halves2half2(lx, ly);
                }
                hx = __float2half(v1.x); hy = __float2half(v1.y);
                *(__half2*)(Hhi + (size_t)(rowa + 8) * 2048 + col) = __halves2half2(hx, hy);
                if (Hlo) {
                    __half lx = __float2half(v1.x - __half2float(hx));
                    __half ly = __float2half(v1.y - __half2float(hy));
                    *(__half2*)(Hlo + (size_t)(rowa + 8) * 2048 + col) = __halves2half2(lx, ly);
                }
            }
        }
    }
}

// Fused q/k/v/g projections; q,k dual fp16 hi/lo (exact); v,g fp32; g uses 1 segment.
__global__ __launch_bounds__(128, 2)
void gemm2_qkvg(const __half* __restrict__ Ahi, const __half* __restrict__ Alo,
                const __half* __restrict__ W,
                float* __restrict__ Cv, float* __restrict__ Cg,
                __half* __restrict__ Qhi, __half* __restrict__ Qlo,
                __half* __restrict__ Khi, __half* __restrict__ Klo, float qscale)
{
    extern __shared__ __align__(128) char dyn[];
    const int sel = blockIdx.x >> 4;
    const int bn  = (blockIdx.x & 15) * 128;
    const int bm  = blockIdx.y * 128;
    const __half* B = W + (size_t)sel * Dd * Dd;
    float* C = (sel == 2) ? Cv : (sel == 3) ? Cg : (float*)0;
    __half* Hhi = (sel == 0) ? Qhi : (sel == 1) ? Khi : (__half*)0;
    __half* Hlo = (sel == 0) ? Qlo : (sel == 1) ? Klo : (__half*)0;
    float alpha = (sel == 0) ? qscale : 1.f;
    const int nkt = (sel == 3) ? 64 : 128;   // gate: hi-only activations
    gemm2_body(Ahi, Alo, B, nkt, C, Hhi, Hlo, alpha, bm, bn, dyn);
}

// Output projection: single-segment (og fp16, hi only)
__global__ __launch_bounds__(128, 2)
void gemm2_f16(const __half* __restrict__ Ahi,
               const __half* __restrict__ B, float* __restrict__ C, float alpha)
{
    extern __shared__ __align__(128) char dyn[];
    gemm2_body(Ahi, Ahi, B, 64, C, (__half*)0, (__half*)0, alpha,
               blockIdx.y * 128, blockIdx.x * 128, dyn);
}

// ---------------- eta/theta via HMMA ----------------
#define ENKT 192
__global__ __launch_bounds__(128)
void eta_theta_hmma(const __half* __restrict__ Xhi, const __half* __restrict__ Xlo,
                    const __half* __restrict__ Whi, const __half* __restrict__ Wlo,
                    float* __restrict__ Eta, float* __restrict__ Th)
{
    extern __shared__ __align__(128) char dyn[];
    const int tid  = threadIdx.x;
    const int wid  = tid >> 5;
    const int lane = tid & 31;
    const int bm   = blockIdx.x * 128;
    const uint32_t dynb = smem_u32(dyn);
    const uint32_t STG_E = 160 * ROWB;

    const int wm0 = wid * 32;
    const int q = lane >> 3, l8 = lane & 7;
    const uint32_t aoff = (uint32_t)((l8 + (q & 1) * 8) * ROWB + (q >> 1) * 16);
    const uint32_t boff = (uint32_t)((l8 + (q >> 1) * 8) * ROWB + (q & 1) * 16);

    float acc[2][4][4];
#pragma unroll
    for (int mf = 0; mf < 2; mf++)
#pragma unroll
        for (int nf = 0; nf < 4; nf++)
#pragma unroll
            for (int j = 0; j < 4; j++) acc[mf][nf][j] = 0.f;

#define ELD(stg, Asrc, Bsrc, k0) do { \
    uint32_t bsA = dynb + (stg) * STG_E; \
    uint32_t bsB = bsA + 128 * ROWB; \
    _Pragma("unroll") \
    for (int i_ = 0; i_ < 4; i_++) { \
        int idx_ = tid + i_ * 128; \
        int row_ = idx_ >> 2, c_ = idx_ & 3; \
        CP16(bsA + row_ * ROWB + c_ * 16, (const void*)((Asrc) + (size_t)(bm + row_) * 2048 + (k0) + c_ * 8)); \
    } \
    { int row_ = tid >> 2, c_ = tid & 3; \
      CP16(bsB + row_ * ROWB + c_ * 16, (const void*)((Bsrc) + (size_t)row_ * 2048 + (k0) + c_ * 8)); } \
    asm volatile("cp.async.commit_group;" ::: "memory"); \
} while (0)

#pragma unroll
    for (int s = 0; s < 3; s++) ELD(s, Xhi, Whi, s * BKT);

    for (int kt = 0; kt < ENKT; kt++) {
        asm volatile("cp.async.wait_group 2;" ::: "memory");
        __syncthreads();
        {
            int ktn = kt + 3;
            if (ktn < ENKT) {
                int seg = ktn >> 6;
                int k0  = (ktn & 63) * BKT;
                const __half* As_ = (seg == 1) ? Xlo : Xhi;
                const __half* Bs_ = (seg == 2) ? Wlo : Whi;
                ELD(ktn & 3, As_, Bs_, k0);
            } else {
                asm volatile("cp.async.commit_group;" ::: "memory");
            }
        }
        const uint32_t sA = dynb + (kt & 3) * STG_E;
        const uint32_t sB = sA + 128 * ROWB;
#pragma unroll
        for (int ks = 0; ks < 2; ks++) {
            uint32_t a[2][4];
#pragma unroll
            for (int mf = 0; mf < 2; mf++)
                ldm_x4(a[mf], sA + (uint32_t)(wm0 + mf * 16) * ROWB + ks * 32 + aoff);
            uint32_t b[2][4];
#pragma unroll
            for (int p = 0; p < 2; p++)
                ldm_x4(b[p], sB + (uint32_t)(p * 16) * ROWB + ks * 32 + boff);
#pragma unroll
            for (int mf = 0; mf < 2; mf++)
#pragma unroll
                for (int p = 0; p < 2; p++) {
                    mma16816(acc[mf][2*p],   a[mf], b[p][0], b[p][1]);
                    mma16816(acc[mf][2*p+1], a[mf], b[p][2], b[p][3]);
                }
        }
        __syncthreads();
    }
#undef ELD

    const int r0 = lane >> 2, c0 = (lane & 3) * 2;
#pragma unroll
    for (int mf = 0; mf < 2; mf++) {
        int tok0 = bm + wm0 + mf * 16 + r0;
#pragma unroll
        for (int nf = 0; nf < 4; nf++) {
            int col = nf * 8 + c0;
            float s0 = acc[mf][nf][0], s1 = acc[mf][nf][1];
            float s2 = acc[mf][nf][2], s3 = acc[mf][nf][3];
            float g0 = 1.f / (1.f + expf(-s0));
            float g1 = 1.f / (1.f + expf(-s1));
            float g2 = 1.f / (1.f + expf(-s2));
            float g3 = 1.f / (1.f + expf(-s3));
            if (col < 16) {
                float2 a0 = {g0, g1}, a1 = {g2, g3};
                *(float2*)(Eta + (size_t)tok0 * Hh + col)       = a0;
                *(float2*)(Eta + (size_t)(tok0 + 8) * Hh + col) = a1;
            } else {
                float2 a0 = {0.1f*g0, 0.1f*g1}, a1 = {0.1f*g2, 0.1f*g3};
                *(float2*)(Th + (size_t)tok0 * Hh + col - 16)       = a0;
                *(float2*)(Th + (size_t)(tok0 + 8) * Hh + col - 16) = a1;
            }
        }
    }
}

// ---------------- decay prep ----------------
__global__ __launch_bounds__(256)
void decay_prep_kernel(const float* __restrict__ Eta, const float* __restrict__ Th,
                       float* __restrict__ Lec, float* __restrict__ Elec,
                       float* __restrict__ Coef)
{
    const int wc   = blockIdx.x * 8 + (threadIdx.x >> 5);
    const int lane = threadIdx.x & 31;
    const int bh = wc >> 6, ct = wc & 63;
    const int b = bh >> 4, h = bh & 15;
    const size_t tokbase = (size_t)b * Tt;
    const int t = ct * BT + lane * 2;
    float e0  = Eta[(tokbase + t) * Hh + h];
    float e1  = Eta[(tokbase + t + 1) * Hh + h];
    float th0 = Th [(tokbase + t) * Hh + h];
    float th1 = Th [(tokbase + t + 1) * Hh + h];
    float l0 = logf(fmaxf(e0, 1e-8f));
    float l1 = logf(fmaxf(e1, 1e-8f));
    float s = l0 + l1;
#pragma unroll
    for (int o = 1; o < 32; o <<= 1) {
        float n = __shfl_up_sync(0xffffffffu, s, o);
        if (lane >= o) s += n;
    }
    float lec1 = s;
    float lec0 = s - l1;
    float ltot = __shfl_sync(0xffffffffu, s, 31);
    size_t base = (size_t)bh * Tt + t;
    float2 lv = {lec0, lec1};
    float2 ev = {expf(lec0), expf(lec1)};
    float2 cv = {expf(ltot - lec0) * th0, expf(ltot - lec1) * th1};
    *(float2*)(Lec  + base) = lv;
    *(float2*)(Elec + base) = ev;
    *(float2*)(Coef + base) = cv;
}

// ---------------- qkm via HMMA ----------------
#define QROW 136
#define QROWB (QROW*2)
__global__ __launch_bounds__(128)
void qkm_hmma(const __half* __restrict__ Qhi, const __half* __restrict__ Qlo,
              const __half* __restrict__ Khi, const __half* __restrict__ Klo,
              const float* __restrict__ Lec, const float* __restrict__ Th,
              float* __restrict__ Mout)
{
    extern __shared__ __align__(16) char qsmc[];
    float*  sLec = (float*)(qsmc + 4*64*QROWB);
    float*  sTh  = sLec + 64;

    const int blk = blockIdx.x;
    const int bh = blk >> 6, ct = blk & 63;
    const int b = bh >> 4, h = bh & 15;
    const int tid = threadIdx.x;
    const size_t tokbase = (size_t)b * Tt;
    const int t0 = ct * BT;
    const size_t goff = tokbase * HD + (size_t)h * Kk;

    const uint32_t sb = smem_u32(qsmc);
#pragma unroll
    for (int i = 0; i < 8; i++) {
        int idx = tid + i * 128;
        int r = idx >> 4, c = (idx & 15) * 8;
        uint32_t d0 = sb + (uint32_t)(r * QROW + c) * 2u;
        size_t gsrc = goff + (size_t)(t0 + r) * HD + c;
        CP16(d0,                (const void*)(Qhi + gsrc));
        CP16(d0 + 64u*QROWB,    (const void*)(Qlo + gsrc));
        CP16(d0 + 2u*64u*QROWB, (const void*)(Khi + gsrc));
        CP16(d0 + 3u*64u*QROWB, (const void*)(Klo + gsrc));
    }
    if (tid < 64) {
        sLec[tid] = Lec[(size_t)bh * Tt + t0 + tid];
        sTh[tid]  = Th[(tokbase + t0 + tid) * Hh + h];
    }
    asm volatile("cp.async.commit_group;" ::: "memory");
    asm volatile("cp.async.wait_group 0;" ::: "memory");
    __syncthreads();

    const int wid = tid >> 5, lane = tid & 31;
    const int wm0 = wid * 16;
    const int q8 = lane >> 3, l8 = lane & 7;
    const uint32_t aoff = (uint32_t)((l8 + (q8 & 1) * 8) * QROWB + (q8 >> 1) * 16);
    const uint32_t boff = (uint32_t)((l8 + (q8 >> 1) * 8) * QROWB + (q8 & 1) * 16);

    float acc[8][4];
#pragma unroll
    for (int nf = 0; nf < 8; nf++)
#pragma unroll
        for (int j = 0; j < 4; j++) acc[nf][j] = 0.f;

    const uint32_t bQh = sb, bQl = sb + 64u*QROWB, bKh = sb + 2u*64u*QROWB, bKl = sb + 3u*64u*QROWB;
    const uint32_t Ab[3] = {bQh, bQl, bQh};
    const uint32_t Bbv[3] = {bKh, bKh, bKl};
#pragma unroll
    for (int seg = 0; seg < 3; seg++) {
        const uint32_t As = Ab[seg] + (uint32_t)wm0 * QROWB;
        const uint32_t Bs = Bbv[seg];
#pragma unroll
        for (int ks = 0; ks < 8; ks++) {
            uint32_t a[4];
            ldm_x4(a, As + ks * 32 + aoff);
#pragma unroll
            for (int p = 0; p < 4; p++) {
                uint32_t bb[4];
                ldm_x4(bb, Bs + (uint32_t)(p * 16) * QROWB + ks * 32 + boff);
                mma16816(acc[2*p],   a, bb[0], bb[1]);
                mma16816(acc[2*p+1], a, bb[2], bb[3]);
            }
        }
    }

    const int r0 = lane >> 2, c0 = (lane & 3) * 2;
    float* Mo = Mout + (size_t)blk * (BT*BT);
#pragma unroll
    for (int half_ = 0; half_ < 2; half_++) {
        int ii = wm0 + r0 + half_ * 8;
        float li = sLec[ii];
#pragma unroll
        for (int nf = 0; nf < 8; nf++) {
            int col = nf * 8 + c0;
            float m0 = 0.f, m1 = 0.f;
            if (col <= ii)
                m0 = acc[nf][half_*2]   * expf(fminf(li - sLec[col], 0.f)) * sTh[col];
            if (col + 1 <= ii)
                m1 = acc[nf][half_*2+1] * expf(fminf(li - sLec[col+1], 0.f)) * sTh[col+1];
            float2 mv = {m0, m1};
            *(float2*)(Mo + ii * 64 + col) = mv;
        }
    }
}

// ---------------- scan: phase A on HMMA, B/C on f32x2 (R14) ----------------
#define SROW 136
#define SROWB (SROW*2)
__global__ __launch_bounds__(256, 1)
void scan_kernel(const __half* __restrict__ Qhi, const __half* __restrict__ Qlo,
                 const __half* __restrict__ Khi, const __half* __restrict__ Klo,
                 const float* __restrict__ Vc, const float* __restrict__ Elec,
                 const float* __restrict__ Coef, const float* __restrict__ Mg,
                 float* __restrict__ Z)
{
    extern __shared__ float sm[];
    float* sW    = sm;                    // 32*132
    float* sVE   = sW + 32*132;
    float* sZQ   = sVE + 64*32;
    float* sM    = sZQ + 64*32;
    float* sElec = sM + 64*68;
    float* sCoef = sElec + 64;
    __half* sWh  = (__half*)(sCoef + 64);
    __half* sWl  = sWh + 32*SROW;
    __half* sKh  = sWl + 32*SROW;
    __half* sKl  = sKh + 64*SROW;
    __half* sQh  = sKl + 64*SROW;
    __half* sQl  = sQh + 64*SROW;

    const int tid = threadIdx.x;
    const int bh  = blockIdx.x;
    const int b = bh >> 4, h = bh & 15;
    const int vs0 = blockIdx.y * VS;

    const size_t tokbase = (size_t)b * Tt;
    const size_t goff = tokbase * HD + (size_t)h * Kk;
    const __half* Qh = Qhi + goff;
    const __half* Ql = Qlo + goff;
    const __half* Kh = Khi + goff;
    const __half* Kl = Klo + goff;
    const float* Vp = Vc + tokbase*HD + (size_t)h*Vv + vs0;
    const float* Mp = Mg + (size_t)bh * (NT*BT*BT);
    float*       Zp = Z  + tokbase*HD + (size_t)h*Vv + vs0;

    for (int i = tid; i < 32*132; i += 256) sW[i] = 0.f;

    const int wid = tid >> 5, lane = tid & 31;
    const int wm = wid >> 1, wn = wid & 1;
    const int q8 = lane >> 3, l8 = lane & 7;
    const uint32_t aoff = (uint32_t)((l8 + (q8 & 1) * 8) * SROWB + (q8 >> 1) * 16);
    const uint32_t boff = (uint32_t)((l8 + (q8 >> 1) * 8) * SROWB + (q8 & 1) * 16);
    const uint32_t uWh = smem_u32(sWh), uWl = smem_u32(sWl);
    const uint32_t uKh = smem_u32(sKh), uKl = smem_u32(sKl);
    const uint32_t uQh = smem_u32(sQh), uQl = smem_u32(sQl);
    const int fr0 = lane >> 2, fc0 = (lane & 3) * 2;

    const int tx = tid & 7;
    const int ty = tid >> 3;
    const int v0 = tx << 2;
    const int ta = ty*2, tb = ta + 1;
    const int k0 = ty << 2;

    for (int ct = 0; ct < NT; ct++) {
        const int t0 = ct * BT;
        __syncthreads();

#pragma unroll
        for (int i = 0; i < 4; i++) {
            int idx = tid + i*256;
            int r = idx >> 4, c = (idx & 15) * 8;
            size_t off = (size_t)(t0 + r) * HD + c;
            *(uint4*)&sKh[r*SROW + c] = *(const uint4*)(Kh + off);
            *(uint4*)&sKl[r*SROW + c] = *(const uint4*)(Kl + off);
            *(uint4*)&sQh[r*SROW + c] = *(const uint4*)(Qh + off);
            *(uint4*)&sQl[r*SROW + c] = *(const uint4*)(Ql + off);
        }
#pragma unroll
        for (int i = 0; i < 2; i++) {
            int idx = tid + i*256;
            int r = idx >> 3;
            int c = (idx & 7) << 2;
            *(float4*)&sVE[r*VS + c] = *(const float4*)(Vp + (size_t)(t0+r)*HD + c);
        }
#pragma unroll
        for (int i = 0; i < 4; i++) {
            int idx = tid + i*256;
            int r = idx >> 4;
            int c = (idx & 15) << 2;
            *(float4*)&sM[r*68 + c] = *(const float4*)(Mp + ct*(BT*BT) + r*64 + c);
        }
        if (tid < 64) {
            sElec[tid] = Elec[(size_t)bh*Tt + t0 + tid];
            sCoef[tid] = Coef[(size_t)bh*Tt + t0 + tid];
        }
#pragma unroll
        for (int i = 0; i < 4; i++) {
            int idx = tid + i*256;
            int r = idx >> 5;
            int c4 = (idx & 31) << 2;
            float4 w4 = *(float4*)&sW[r*132 + c4];
            __half hx = __float2half(w4.x), hy = __float2half(w4.y);
            __half hz = __float2half(w4.z), hw = __float2half(w4.w);
            __half lx = __float2half(w4.x - __half2float(hx));
            __half ly = __float2half(w4.y - __half2float(hy));
            __half lz = __float2half(w4.z - __half2float(hz));
            __half lw = __float2half(w4.w - __half2float(hw));
            *(__half2*)&sWh[r*SROW + c4]     = __halves2half2(hx, hy);
            *(__half2*)&sWh[r*SROW + c4 + 2] = __halves2half2(hz, hw);
            *(__half2*)&sWl[r*SROW + c4]     = __halves2half2(lx, ly);
            *(__half2*)&sWl[r*SROW + c4 + 2] = __halves2half2(lz, lw);
        }
        __syncthreads();

        // ---- Phase A (HMMA) ----
        {
            float ae[2][4], az[2][4];
#pragma unroll
            for (int nf = 0; nf < 2; nf++)
#pragma unroll
                for (int j = 0; j < 4; j++) { ae[nf][j] = 0.f; az[nf][j] = 0.f; }

            const uint32_t Akv[3] = {uKh, uKl, uKh};
            const uint32_t Aqv[3] = {uQh, uQl, uQh};
            const uint32_t Bwv[3] = {uWh, uWh, uWl};
#pragma unroll
            for (int seg = 0; seg < 3; seg++) {
                const uint32_t Ak = Akv[seg] + (uint32_t)(wm*16) * SROWB;
                const uint32_t Aq = Aqv[seg] + (uint32_t)(wm*16) * SROWB;
                const uint32_t Bw = Bwv[seg] + (uint32_t)(wn*16) * SROWB;
#pragma unroll
                for (int ks = 0; ks < 8; ks++) {
                    uint32_t bb[4];
                    ldm_x4(bb, Bw + ks * 32 + boff);
                    uint32_t ak[4];
                    ldm_x4(ak, Ak + ks * 32 + aoff);
                    mma16816(ae[0], ak, bb[0], bb[1]);
                    mma16816(ae[1], ak, bb[2], bb[3]);
                    uint32_t aq[4];
                    ldm_x4(aq, Aq + ks * 32 + aoff);
                    mma16816(az[0], aq, bb[0], bb[1]);
                    mma16816(az[1], aq, bb[2], bb[3]);
                }
            }
#pragma unroll
            for (int h8 = 0; h8 < 2; h8++) {
                int r = wm*16 + fr0 + h8*8;
                float el = sElec[r];
#pragma unroll
                for (int nf = 0; nf < 2; nf++) {
                    int c = wn*16 + nf*8 + fc0;
                    float2 vv = *(float2*)&sVE[r*VS + c];
                    float2 ev = {ae[nf][h8*2] - vv.x, ae[nf][h8*2+1] - vv.y};
                    *(float2*)&sVE[r*VS + c] = ev;
                    float2 zv = {az[nf][h8*2] * el, az[nf][h8*2+1] * el};
                    *(float2*)&sZQ[r*VS + c] = zv;
                }
            }
        }
        __syncthreads();

        // ---- Fused B+C (f32x2) ----
        {
            float4 za4 = *(float4*)&sZQ[ta*VS + v0];
            float4 zb4 = *(float4*)&sZQ[tb*VS + v0];
            u64t za01 = pk2(za4.x, za4.y), za23 = pk2(za4.z, za4.w);
            u64t zb01 = pk2(zb4.x, zb4.y), zb23 = pk2(zb4.z, zb4.w);
            u64t sa01 = 0ull, sa23 = 0ull, sb01 = 0ull, sb23 = 0ull;
            u64t ca01[4], ca23[4];
#pragma unroll
            for (int i = 0; i < 4; i++) { ca01[i] = 0ull; ca23[i] = 0ull; }
#pragma unroll 2
            for (int t = 0; t < BT; t++) {
                double2 ed = *(double2*)&sVE[t*VS + v0];
                u64t e01 = d2u(ed.x), e23 = d2u(ed.y);
                float ma = sM[ta*68 + t];
                float mb = sM[tb*68 + t];
                u64t ma2 = pk2(ma, ma), mb2 = pk2(mb, mb);
                sa01 = fma2(ma2, e01, sa01);
                sa23 = fma2(ma2, e23, sa23);
                sb01 = fma2(mb2, e01, sb01);
                sb23 = fma2(mb2, e23, sb23);
                float cf = -sCoef[t];
                float e0, e1, e2, e3;
                upk2(e01, e0, e1); upk2(e23, e2, e3);
                uint2 kh2 = *(uint2*)&sKh[t*SROW + k0];
                uint2 kl2 = *(uint2*)&sKl[t*SROW + k0];
                float4 k4 = cvt4(kh2, kl2);
                u64t k01 = pk2(k4.x, k4.y), k23 = pk2(k4.z, k4.w);
                u64t c0p = pk2(cf*e0, cf*e0), c1p = pk2(cf*e1, cf*e1);
                u64t c2p = pk2(cf*e2, cf*e2), c3p = pk2(cf*e3, cf*e3);
                ca01[0] = fma2(k01, c0p, ca01[0]); ca23[0] = fma2(k23, c0p, ca23[0]);
                ca01[1] = fma2(k01, c1p, ca01[1]); ca23[1] = fma2(k23, c1p, ca23[1]);
                ca01[2] = fma2(k01, c2p, ca01[2]); ca23[2] = fma2(k23, c2p, ca23[2]);
                ca01[3] = fma2(k01, c3p, ca01[3]); ca23[3] = fma2(k23, c3p, ca23[3]);
            }
            float z0, z1, s0, s1;
            float4 oa, ob;
            upk2(za01, z0, z1); upk2(sa01, s0, s1); oa.x = z0 - s0; oa.y = z1 - s1;
            upk2(za23, z0, z1); upk2(sa23, s0, s1); oa.z = z0 - s0; oa.w = z1 - s1;
            upk2(zb01, z0, z1); upk2(sb01, s0, s1); ob.x = z0 - s0; ob.y = z1 - s1;
            upk2(zb23, z0, z1); upk2(sb23, s0, s1); ob.z = z0 - s0; ob.w = z1 - s1;
            *(float4*)(Zp + (size_t)(t0+ta)*HD + v0) = oa;
            *(float4*)(Zp + (size_t)(t0+tb)*HD + v0) = ob;

            float dk = sElec[63];
            u64t dk2 = pk2(dk, dk);
#pragma unroll
            for (int i = 0; i < 4; i++) {
                double2 wv = *(double2*)&sW[(v0+i)*132 + k0];
                u64t w01 = fma2(d2u(wv.x), dk2, ca01[i]);
                u64t w23 = fma2(d2u(wv.y), dk2, ca23[i]);
                *(double2*)&sW[(v0+i)*132 + k0] = make_double2(u2d(w01), u2d(w23));
            }
        }
    }
}

// ---------------- gated RMS norm -> fp16 (single) ----------------
__global__ __launch_bounds__(256)
void gated_rms_f16(const float* __restrict__ Zin, const float* __restrict__ G,
                   const float* __restrict__ nw, __half* __restrict__ og)
{
    const int gw   = blockIdx.x * 8 + (threadIdx.x >> 5);
    const int lane = threadIdx.x & 31;
    const size_t base = (size_t)gw * 128;
    float4 zv = *(const float4*)(Zin + base + lane*4);
    float ss = zv.x*zv.x + zv.y*zv.y + zv.z*zv.z + zv.w*zv.w;
#pragma unroll
    for (int o = 16; o; o >>= 1) ss += __shfl_xor_sync(0xffffffffu, ss, o);
    float r = rsqrtf(ss * (1.f/128.f) + 1e-5f);
    float4 gv = *(const float4*)(G  + base + lane*4);
    float4 wv = *(const float4*)(nw + lane*4);
    float ov[4];
    ov[0] = zv.x*r*wv.x * (gv.x / (1.f + expf(-gv.x)));
    ov[1] = zv.y*r*wv.y * (gv.y / (1.f + expf(-gv.y)));
    ov[2] = zv.z*r*wv.z * (gv.z / (1.f + expf(-gv.z)));
    ov[3] = zv.w*r*wv.w * (gv.w / (1.f + expf(-gv.w)));
    __align__(8) __half h[4];
#pragma unroll
    for (int j = 0; j < 4; j++) h[j] = __float2half(ov[j]);
    *(uint2*)(og + base + lane*4) = *(uint2*)h;
}

// ---------------- launch ----------------
extern "C" void kernel_launch(void* const* d_in, const int* in_sizes, int n_in,
                              void* d_out, int out_size)
{
    const float* X    = (const float*)d_in[0];
    const float* Wq   = (const float*)d_in[1];
    const float* Wk   = (const float*)d_in[2];
    const float* Wv   = (const float*)d_in[3];
    const float* Weta = (const float*)d_in[4];
    const float* Wth  = (const float*)d_in[5];
    const float* Wg   = (const float*)d_in[6];
    const float* nw   = (const float*)d_in[7];
    const float* Wo   = (const float*)d_in[8];
    float* out = (float*)d_out;

    float *v, *g, *z, *eta, *th, *lec, *elec, *coef, *Mbuf;
    __half *xhi, *xlo, *w16, *w32hi, *w32lo, *og16, *qhi, *qlo, *khi, *klo;
    cudaGetSymbolAddress((void**)&v,    g_v);
    cudaGetSymbolAddress((void**)&g,    g_g);
    cudaGetSymbolAddress((void**)&z,    g_z);
    cudaGetSymbolAddress((void**)&eta,  g_eta);
    cudaGetSymbolAddress((void**)&th,   g_theta);
    cudaGetSymbolAddress((void**)&lec,  g_lec);
    cudaGetSymbolAddress((void**)&elec, g_elec);
    cudaGetSymbolAddress((void**)&coef, g_coef);
    cudaGetSymbolAddress((void**)&Mbuf, g_M);
    cudaGetSymbolAddress((void**)&xhi,  g_xhi);
    cudaGetSymbolAddress((void**)&xlo,  g_xlo);
    cudaGetSymbolAddress((void**)&w16,  g_w16);
    cudaGetSymbolAddress((void**)&w32hi,g_w32hi);
    cudaGetSymbolAddress((void**)&w32lo,g_w32lo);
    cudaGetSymbolAddress((void**)&og16, g_og16);
    cudaGetSymbolAddress((void**)&qhi,  g_qhi);
    cudaGetSymbolAddress((void**)&qlo,  g_qlo);
    cudaGetSymbolAddress((void**)&khi,  g_khi);
    cudaGetSymbolAddress((void**)&klo,  g_klo);

    const int scan_smem = 12800*4 + 43520*2;   // 138240
    cudaFuncSetAttribute(scan_kernel, cudaFuncAttributeMaxDynamicSharedMemorySize, scan_smem);
    const int qkm_smem = 4*64*QROWB + 2*64*4;   // 70144
    cudaFuncSetAttribute(qkm_hmma, cudaFuncAttributeMaxDynamicSharedMemorySize, qkm_smem);
    const int gemm_smem = NSTG * STG_BYTES;   // 81920
    cudaFuncSetAttribute(gemm2_f16, cudaFuncAttributeMaxDynamicSharedMemorySize, gemm_smem);
    cudaFuncSetAttribute(gemm2_qkvg, cudaFuncAttributeMaxDynamicSharedMemorySize, gemm_smem);
    const int eta_smem = 4 * 160 * ROWB;      // 51200
    cudaFuncSetAttribute(eta_theta_hmma, cudaFuncAttributeMaxDynamicSharedMemorySize, eta_smem);

    const int WN = Dd * Dd;
    const float qscale = 0.08838834764831845f;  // 128^-0.5

    split_fp16_kernel<<<TOKS*Dd/4/256, 256>>>(X, xhi, xlo, TOKS*Dd/4);
    conv_fp16_4<<<4*4096, 256>>>(Wq, Wk, Wv, Wg, w16);
    conv_fp16_kernel<<<4096, 256>>>(Wo, w16 + 4*(size_t)WN, WN/4);
    split_w32<<<32*Dd/4/256, 256>>>(Weta, Wth, w32hi, w32lo);

    eta_theta_hmma<<<TOKS/128, 128, eta_smem>>>(xhi, xlo, w32hi, w32lo, eta, th);
    decay_prep_kernel<<<2048/8, 256>>>(eta, th, lec, elec, coef);

    gemm2_qkvg<<<dim3(64, TOKS/128), 128, gemm_smem>>>(xhi, xlo, w16, v, g,
                                                       qhi, qlo, khi, klo, qscale);

    qkm_hmma<<<32*NT, 128, qkm_smem>>>(qhi, qlo, khi, klo, lec, th, Mbuf);

    scan_kernel<<<dim3(Bb*Hh, NVS), 256, scan_smem>>>(qhi, qlo, khi, klo, v, elec, coef, Mbuf, z);

    gated_rms_f16<<<TOKS*Hh/8, 256>>>(z, g, nw, og16);
    gemm2_f16<<<dim3(HD/128, TOKS/128), 128, gemm_smem>>>(og16, w16 + 4*(size_t)WN, out, 1.f);
}

// round 17
// speedup vs baseline: 2.0197x; 1.1090x over previous
#include <cuda_runtime.h>
#include <cuda_fp16.h>
#include <math.h>
#include <cstdint>

// Problem constants (fixed shapes)
#define Bb 2
#define Tt 4096
#define Dd 2048
#define Hh 16
#define Kk 128
#define Vv 128
#define BT 64
#define NT 64
#define TOKS (Bb*Tt)          // 8192
#define HD   (Hh*Kk)          // 2048
#define VS   32               // v-slice width in scan
#define NVS  (Vv/VS)          // 4

// ---------------- scratch (device globals; no runtime alloc) ----------------
__device__ float g_v [TOKS*HD];
__device__ float g_g [TOKS*HD];
__device__ float g_z [TOKS*HD];
__device__ float g_eta  [TOKS*Hh];
__device__ float g_theta[TOKS*Hh];
__device__ float g_lec  [32*Tt];
__device__ float g_elec [32*Tt];
__device__ float g_coef [32*Tt];
__device__ float g_M    [32*NT*BT*BT];
__device__ __half g_xhi[TOKS*Dd];
__device__ __half g_xlo[TOKS*Dd];
__device__ __half g_w16[5*Dd*Dd];
__device__ __half g_w32hi[32*Dd];
__device__ __half g_w32lo[32*Dd];
__device__ __half g_og16[TOKS*HD];
__device__ __half g_q16[TOKS*HD];
__device__ __half g_khi[TOKS*HD];
__device__ __half g_klo[TOKS*HD];

// ---------------- helpers ----------------
typedef unsigned long long u64t;

__device__ __forceinline__ uint32_t smem_u32(const void* p) {
    uint32_t a;
    asm("{ .reg .u64 t; cvta.to.shared.u64 t, %1; cvt.u32.u64 %0, t; }" : "=r"(a) : "l"(p));
    return a;
}
__device__ __forceinline__ void ldm_x4(uint32_t (&r)[4], uint32_t addr) {
    asm volatile("ldmatrix.sync.aligned.m8n8.x4.shared.b16 {%0,%1,%2,%3}, [%4];"
                 : "=r"(r[0]), "=r"(r[1]), "=r"(r[2]), "=r"(r[3]) : "r"(addr));
}
__device__ __forceinline__ void mma16816(float (&d)[4], const uint32_t (&a)[4],
                                         uint32_t b0, uint32_t b1) {
    asm volatile(
        "mma.sync.aligned.m16n8k16.row.col.f32.f16.f16.f32 "
        "{%0,%1,%2,%3}, {%4,%5,%6,%7}, {%8,%9}, {%0,%1,%2,%3};"
        : "+f"(d[0]), "+f"(d[1]), "+f"(d[2]), "+f"(d[3])
        : "r"(a[0]), "r"(a[1]), "r"(a[2]), "r"(a[3]), "r"(b0), "r"(b1));
}
// packed f32x2 (FFMA2 path)
__device__ __forceinline__ u64t pk2(float lo, float hi) {
    u64t d; asm("mov.b64 %0, {%1,%2};" : "=l"(d) : "f"(lo), "f"(hi)); return d;
}
__device__ __forceinline__ void upk2(u64t s, float& lo, float& hi) {
    asm("mov.b64 {%0,%1}, %2;" : "=f"(lo), "=f"(hi) : "l"(s));
}
__device__ __forceinline__ u64t fma2(u64t a, u64t b, u64t c) {
    u64t d; asm("fma.rn.f32x2 %0, %1, %2, %3;" : "=l"(d) : "l"(a), "l"(b), "l"(c)); return d;
}
__device__ __forceinline__ u64t mul2(u64t a, u64t b) {
    u64t d; asm("mul.rn.f32x2 %0, %1, %2;" : "=l"(d) : "l"(a), "l"(b)); return d;
}
__device__ __forceinline__ u64t d2u(double x) { return __double_as_longlong(x); }
__device__ __forceinline__ double u2d(u64t x) { return __longlong_as_double(x); }
#define CP16(dst, src) \
    asm volatile("cp.async.cg.shared.global [%0], [%1], 16;" :: "r"(dst), "l"(src) : "memory")
// combine hi/lo fp16 quad -> float4
__device__ __forceinline__ float4 cvt4(uint2 h, uint2 l) {
    float2 f0 = __half22float2(*(__half2*)&h.x);
    float2 f1 = __half22float2(*(__half2*)&h.y);
    float2 g0 = __half22float2(*(__half2*)&l.x);
    float2 g1 = __half22float2(*(__half2*)&l.y);
    float4 r;
    r.x = f0.x + g0.x; r.y = f0.y + g0.y;
    r.z = f1.x + g1.x; r.w = f1.y + g1.y;
    return r;
}

// ---------------- fp32 -> (hi,lo) fp16 split (activations) ----------------
__global__ __launch_bounds__(256)
void split_fp16_kernel(const float* __restrict__ x, __half* __restrict__ hi,
                       __half* __restrict__ lo, int n4)
{
    int i = blockIdx.x * 256 + threadIdx.x;
    if (i >= n4) return;
    float4 v = ((const float4*)x)[i];
    float vv[4] = {v.x, v.y, v.z, v.w};
    __align__(8) __half h[4], l[4];
#pragma unroll
    for (int j = 0; j < 4; j++) {
        h[j] = __float2half(vv[j]);
        l[j] = __float2half(vv[j] - __half2float(h[j]));
    }
    ((uint2*)hi)[i] = *(uint2*)h;
    ((uint2*)lo)[i] = *(uint2*)l;
}

// ---------------- fp32 -> fp16 convert (single weight) ----------------
__global__ __launch_bounds__(256)
void conv_fp16_kernel(const float* __restrict__ x, __half* __restrict__ w, int n4)
{
    int i = blockIdx.x * 256 + threadIdx.x;
    if (i >= n4) return;
    float4 v = ((const float4*)x)[i];
    __align__(8) __half h[4];
    h[0] = __float2half(v.x); h[1] = __float2half(v.y);
    h[2] = __float2half(v.z); h[3] = __float2half(v.w);
    ((uint2*)w)[i] = *(uint2*)h;
}

// ---------------- fp32 -> fp16 convert, 4 weights in one launch ----------------
__global__ __launch_bounds__(256)
void conv_fp16_4(const float* __restrict__ w0, const float* __restrict__ w1,
                 const float* __restrict__ w2, const float* __restrict__ w3,
                 __half* __restrict__ out)
{
    const int sel = blockIdx.x >> 12;
    const int i = (blockIdx.x & 4095) * 256 + threadIdx.x;
    const float* src = (sel == 0) ? w0 : (sel == 1) ? w1 : (sel == 2) ? w2 : w3;
    float4 v = ((const float4*)src)[i];
    __align__(8) __half h[4];
    h[0] = __float2half(v.x); h[1] = __float2half(v.y);
    h[2] = __float2half(v.z); h[3] = __float2half(v.w);
    ((uint2*)(out + (size_t)sel * Dd * Dd))[i] = *(uint2*)h;
}

// ---------------- Weta||Wth -> 32-row hi/lo fp16 split ----------------
__global__ __launch_bounds__(256)
void split_w32(const float* __restrict__ Weta, const float* __restrict__ Wth,
               __half* __restrict__ hi, __half* __restrict__ lo)
{
    int i = blockIdx.x * 256 + threadIdx.x;
    int e = i * 4;
    const float* src = (e < 16*Dd) ? (Weta + e) : (Wth + e - 16*Dd);
    float4 v = *(const float4*)src;
    float vv[4] = {v.x, v.y, v.z, v.w};
    __align__(8) __half h[4], l[4];
#pragma unroll
    for (int j = 0; j < 4; j++) {
        h[j] = __float2half(vv[j]);
        l[j] = __float2half(vv[j] - __half2float(h[j]));
    }
    ((uint2*)hi)[i] = *(uint2*)h;
    ((uint2*)lo)[i] = *(uint2*)l;
}

// ---------------- HMMA fp16 GEMM body (runtime segment count) ----------------
#define BKT 32
#define ROWB 80                 // smem row stride (32 fp16 + 8 pad)
#define STG_BYTES (128*ROWB*2)  // 20480
#define NSTG 4

__device__ __forceinline__ void ld_stage(uint32_t sA, uint32_t sB,
    const __half* __restrict__ A, const __half* __restrict__ B,
    int bm, int bn, int k0, int tid)
{
#pragma unroll
    for (int i = 0; i < 4; i++) {
        int idx = tid + i * 128;
        int row = idx >> 2, c = idx & 3;
        uint32_t dA = sA + row * ROWB + c * 16;
        const void* pA = A + (size_t)(bm + row) * 2048 + k0 + c * 8;
        CP16(dA, pA);
        uint32_t dB = sB + row * ROWB + c * 16;
        const void* pB = B + (size_t)(bn + row) * 2048 + k0 + c * 8;
        CP16(dB, pB);
    }
}

// writes fp32 C, and/or fp16 Hhi (with optional compensation Hlo)
__device__ __forceinline__ void gemm2_body(
    const __half* __restrict__ Ahi, const __half* __restrict__ Alo,
    const __half* __restrict__ B, int nkt,
    float* __restrict__ C, __half* __restrict__ Hhi, __half* __restrict__ Hlo,
    float alpha, int bm, int bn, char* dyn)
{
    const int tid  = threadIdx.x;
    const int wid  = tid >> 5;
    const int lane = tid & 31;
    const uint32_t dynb = smem_u32(dyn);

    const int wm0 = (wid >> 1) * 64;
    const int wn0 = (wid & 1) * 64;

    const int q = lane >> 3, l8 = lane & 7;
    const uint32_t aoff = (uint32_t)((l8 + (q & 1) * 8) * ROWB + (q >> 1) * 16);
    const uint32_t boff = (uint32_t)((l8 + (q >> 1) * 8) * ROWB + (q & 1) * 16);

    float acc[4][8][4];
#pragma unroll
    for (int mf = 0; mf < 4; mf++)
#pragma unroll
        for (int nf = 0; nf < 8; nf++)
#pragma unroll
            for (int j = 0; j < 4; j++) acc[mf][nf][j] = 0.f;

#pragma unroll
    for (int s = 0; s < 3; s++) {
        uint32_t base = dynb + s * STG_BYTES;
        ld_stage(base, base + 128 * ROWB, Ahi, B, bm, bn, s * BKT, tid);
        asm volatile("cp.async.commit_group;" ::: "memory");
    }

    for (int kt = 0; kt < nkt; kt++) {
        asm volatile("cp.async.wait_group 2;" ::: "memory");
        __syncthreads();

        {
            int ktn = kt + 3;
            if (ktn < nkt) {
                int seg = ktn >> 6;
                int k0  = (ktn & 63) * BKT;
                const __half* As_ = seg ? Alo : Ahi;
                uint32_t base = dynb + (ktn & 3) * STG_BYTES;
                ld_stage(base, base + 128 * ROWB, As_, B, bm, bn, k0, tid);
            }
            asm volatile("cp.async.commit_group;" ::: "memory");
        }

        const uint32_t sA = dynb + (kt & 3) * STG_BYTES;
        const uint32_t sB = sA + 128 * ROWB;
#pragma unroll
        for (int ks = 0; ks < 2; ks++) {
            uint32_t a[4][4];
#pragma unroll
            for (int mf = 0; mf < 4; mf++)
                ldm_x4(a[mf], sA + (uint32_t)(wm0 + mf * 16) * ROWB + ks * 32 + aoff);
            uint32_t b[4][4];
#pragma unroll
            for (int p = 0; p < 4; p++)
                ldm_x4(b[p], sB + (uint32_t)(wn0 + p * 16) * ROWB + ks * 32 + boff);
#pragma unroll
            for (int mf = 0; mf < 4; mf++)
#pragma unroll
                for (int p = 0; p < 4; p++) {
                    mma16816(acc[mf][2*p],   a[mf], b[p][0], b[p][1]);
                    mma16816(acc[mf][2*p+1], a[mf], b[p][2], b[p][3]);
                }
        }
    }

    const int r0 = lane >> 2, c0 = (lane & 3) * 2;
#pragma unroll
    for (int mf = 0; mf < 4; mf++) {
        int rowa = bm + wm0 + mf * 16 + r0;
#pragma unroll
        for (int nf = 0; nf < 8; nf++) {
            int col = bn + wn0 + nf * 8 + c0;
            float2 v0 = {alpha * acc[mf][nf][0], alpha * acc[mf][nf][1]};
            float2 v1 = {alpha * acc[mf][nf][2], alpha * acc[mf][nf][3]};
            if (C) {
                *(float2*)(C + (size_t)rowa * 2048 + col)       = v0;
                *(float2*)(C + (size_t)(rowa + 8) * 2048 + col) = v1;
            }
            if (Hhi) {
                __half hx = __float2half(v0.x), hy = __float2half(v0.y);
                *(__half2*)(Hhi + (size_t)rowa * 2048 + col) = __halves2half2(hx, hy);
                if (Hlo) {
                    __half lx = __float2half(v0.x - __half2float(hx));
                    __half ly = __float2half(v0.y - __half2float(hy));
                    *(__half2*)(Hlo + (size_t)rowa * 2048 + col) = __halves2half2(lx, ly);
                }
                hx = __float2half(v1.x); hy = __float2half(v1.y);
                *(__half2*)(Hhi + (size_t)(rowa + 8) * 2048 + col) = __halves2half2(hx, hy);
                if (Hlo) {
                    __half lx = __float2half(v1.x - __half2float(hx));
                    __half ly = __float2half(v1.y - __half2float(hy));
                    *(__half2*)(Hlo + (size_t)(rowa + 8) * 2048 + col) = __halves2half2(lx, ly);
                }
            }
        }
    }
}

// Fused q/k/v/g projections.
// q: 1 segment, fp16 out (rounded).  k: 2 segments, exact fp16 hi/lo out.
// v: 2 segments, fp32 out.  g: 1 segment, fp32 out.
__global__ __launch_bounds__(128, 2)
void gemm2_qkvg(const __half* __restrict__ Ahi, const __half* __restrict__ Alo,
                const __half* __restrict__ W,
                float* __restrict__ Cv, float* __restrict__ Cg,
                __half* __restrict__ Q16,
                __half* __restrict__ Khi, __half* __restrict__ Klo, float qscale)
{
    extern __shared__ __align__(128) char dyn[];
    const int sel = blockIdx.x >> 4;
    const int bn  = (blockIdx.x & 15) * 128;
    const int bm  = blockIdx.y * 128;
    const __half* B = W + (size_t)sel * Dd * Dd;
    float* C = (sel == 2) ? Cv : (sel == 3) ? Cg : (float*)0;
    __half* Hhi = (sel == 0) ? Q16 : (sel == 1) ? Khi : (__half*)0;
    __half* Hlo = (sel == 1) ? Klo : (__half*)0;
    float alpha = (sel == 0) ? qscale : 1.f;
    const int nkt = (sel == 1 || sel == 2) ? 128 : 64;   // k,v keep activation-lo
    gemm2_body(Ahi, Alo, B, nkt, C, Hhi, Hlo, alpha, bm, bn, dyn);
}

// Output projection: single-segment (og fp16)
__global__ __launch_bounds__(128, 2)
void gemm2_f16(const __half* __restrict__ Ahi,
               const __half* __restrict__ B, float* __restrict__ C, float alpha)
{
    extern __shared__ __align__(128) char dyn[];
    gemm2_body(Ahi, Ahi, B, 64, C, (__half*)0, (__half*)0, alpha,
               blockIdx.y * 128, blockIdx.x * 128, dyn);
}

// ---------------- eta/theta via HMMA ----------------
#define ENKT 192
__global__ __launch_bounds__(128)
void eta_theta_hmma(const __half* __restrict__ Xhi, const __half* __restrict__ Xlo,
                    const __half* __restrict__ Whi, const __half* __restrict__ Wlo,
                    float* __restrict__ Eta, float* __restrict__ Th)
{
    extern __shared__ __align__(128) char dyn[];
    const int tid  = threadIdx.x;
    const int wid  = tid >> 5;
    const int lane = tid & 31;
    const int bm   = blockIdx.x * 128;
    const uint32_t dynb = smem_u32(dyn);
    const uint32_t STG_E = 160 * ROWB;

    const int wm0 = wid * 32;
    const int q = lane >> 3, l8 = lane & 7;
    const uint32_t aoff = (uint32_t)((l8 + (q & 1) * 8) * ROWB + (q >> 1) * 16);
    const uint32_t boff = (uint32_t)((l8 + (q >> 1) * 8) * ROWB + (q & 1) * 16);

    float acc[2][4][4];
#pragma unroll
    for (int mf = 0; mf < 2; mf++)
#pragma unroll
        for (int nf = 0; nf < 4; nf++)
#pragma unroll
            for (int j = 0; j < 4; j++) acc[mf][nf][j] = 0.f;

#define ELD(stg, Asrc, Bsrc, k0) do { \
    uint32_t bsA = dynb + (stg) * STG_E; \
    uint32_t bsB = bsA + 128 * ROWB; \
    _Pragma("unroll") \
    for (int i_ = 0; i_ < 4; i_++) { \
        int idx_ = tid + i_ * 128; \
        int row_ = idx_ >> 2, c_ = idx_ & 3; \
        CP16(bsA + row_ * ROWB + c_ * 16, (const void*)((Asrc) + (size_t)(bm + row_) * 2048 + (k0) + c_ * 8)); \
    } \
    { int row_ = tid >> 2, c_ = tid & 3; \
      CP16(bsB + row_ * ROWB + c_ * 16, (const void*)((Bsrc) + (size_t)row_ * 2048 + (k0) + c_ * 8)); } \
    asm volatile("cp.async.commit_group;" ::: "memory"); \
} while (0)

#pragma unroll
    for (int s = 0; s < 3; s++) ELD(s, Xhi, Whi, s * BKT);

    for (int kt = 0; kt < ENKT; kt++) {
        asm volatile("cp.async.wait_group 2;" ::: "memory");
        __syncthreads();
        {
            int ktn = kt + 3;
            if (ktn < ENKT) {
                int seg = ktn >> 6;
                int k0  = (ktn & 63) * BKT;
                const __half* As_ = (seg == 1) ? Xlo : Xhi;
                const __half* Bs_ = (seg == 2) ? Wlo : Whi;
                ELD(ktn & 3, As_, Bs_, k0);
            } else {
                asm volatile("cp.async.commit_group;" ::: "memory");
            }
        }
        const uint32_t sA = dynb + (kt & 3) * STG_E;
        const uint32_t sB = sA + 128 * ROWB;
#pragma unroll
        for (int ks = 0; ks < 2; ks++) {
            uint32_t a[2][4];
#pragma unroll
            for (int mf = 0; mf < 2; mf++)
                ldm_x4(a[mf], sA + (uint32_t)(wm0 + mf * 16) * ROWB + ks * 32 + aoff);
            uint32_t b[2][4];
#pragma unroll
            for (int p = 0; p < 2; p++)
                ldm_x4(b[p], sB + (uint32_t)(p * 16) * ROWB + ks * 32 + boff);
#pragma unroll
            for (int mf = 0; mf < 2; mf++)
#pragma unroll
                for (int p = 0; p < 2; p++) {
                    mma16816(acc[mf][2*p],   a[mf], b[p][0], b[p][1]);
                    mma16816(acc[mf][2*p+1], a[mf], b[p][2], b[p][3]);
                }
        }
        __syncthreads();
    }
#undef ELD

    const int r0 = lane >> 2, c0 = (lane & 3) * 2;
#pragma unroll
    for (int mf = 0; mf < 2; mf++) {
        int tok0 = bm + wm0 + mf * 16 + r0;
#pragma unroll
        for (int nf = 0; nf < 4; nf++) {
            int col = nf * 8 + c0;
            float s0 = acc[mf][nf][0], s1 = acc[mf][nf][1];
            float s2 = acc[mf][nf][2], s3 = acc[mf][nf][3];
            float g0 = 1.f / (1.f + expf(-s0));
            float g1 = 1.f / (1.f + expf(-s1));
            float g2 = 1.f / (1.f + expf(-s2));
            float g3 = 1.f / (1.f + expf(-s3));
            if (col < 16) {
                float2 a0 = {g0, g1}, a1 = {g2, g3};
                *(float2*)(Eta + (size_t)tok0 * Hh + col)       = a0;
                *(float2*)(Eta + (size_t)(tok0 + 8) * Hh + col) = a1;
            } else {
                float2 a0 = {0.1f*g0, 0.1f*g1}, a1 = {0.1f*g2, 0.1f*g3};
                *(float2*)(Th + (size_t)tok0 * Hh + col - 16)       = a0;
                *(float2*)(Th + (size_t)(tok0 + 8) * Hh + col - 16) = a1;
            }
        }
    }
}

// ---------------- decay prep ----------------
__global__ __launch_bounds__(256)
void decay_prep_kernel(const float* __restrict__ Eta, const float* __restrict__ Th,
                       float* __restrict__ Lec, float* __restrict__ Elec,
                       float* __restrict__ Coef)
{
    const int wc   = blockIdx.x * 8 + (threadIdx.x >> 5);
    const int lane = threadIdx.x & 31;
    const int bh = wc >> 6, ct = wc & 63;
    const int b = bh >> 4, h = bh & 15;
    const size_t tokbase = (size_t)b * Tt;
    const int t = ct * BT + lane * 2;
    float e0  = Eta[(tokbase + t) * Hh + h];
    float e1  = Eta[(tokbase + t + 1) * Hh + h];
    float th0 = Th [(tokbase + t) * Hh + h];
    float th1 = Th [(tokbase + t + 1) * Hh + h];
    float l0 = logf(fmaxf(e0, 1e-8f));
    float l1 = logf(fmaxf(e1, 1e-8f));
    float s = l0 + l1;
#pragma unroll
    for (int o = 1; o < 32; o <<= 1) {
        float n = __shfl_up_sync(0xffffffffu, s, o);
        if (lane >= o) s += n;
    }
    float lec1 = s;
    float lec0 = s - l1;
    float ltot = __shfl_sync(0xffffffffu, s, 31);
    size_t base = (size_t)bh * Tt + t;
    float2 lv = {lec0, lec1};
    float2 ev = {expf(lec0), expf(lec1)};
    float2 cv = {expf(ltot - lec0) * th0, expf(ltot - lec1) * th1};
    *(float2*)(Lec  + base) = lv;
    *(float2*)(Elec + base) = ev;
    *(float2*)(Coef + base) = cv;
}

// ---------------- qkm via HMMA: q16 x (khi + klo), 2 segments ----------------
#define QROW 136
#define QROWB (QROW*2)
__global__ __launch_bounds__(128)
void qkm_hmma(const __half* __restrict__ Q16,
              const __half* __restrict__ Khi, const __half* __restrict__ Klo,
              const float* __restrict__ Lec, const float* __restrict__ Th,
              float* __restrict__ Mout)
{
    extern __shared__ __align__(16) char qsmc[];
    float*  sLec = (float*)(qsmc + 3*64*QROWB);
    float*  sTh  = sLec + 64;

    const int blk = blockIdx.x;
    const int bh = blk >> 6, ct = blk & 63;
    const int b = bh >> 4, h = bh & 15;
    const int tid = threadIdx.x;
    const size_t tokbase = (size_t)b * Tt;
    const int t0 = ct * BT;
    const size_t goff = tokbase * HD + (size_t)h * Kk;

    const uint32_t sb = smem_u32(qsmc);
#pragma unroll
    for (int i = 0; i < 8; i++) {
        int idx = tid + i * 128;
        int r = idx >> 4, c = (idx & 15) * 8;
        uint32_t d0 = sb + (uint32_t)(r * QROW + c) * 2u;
        size_t gsrc = goff + (size_t)(t0 + r) * HD + c;
        CP16(d0,                (const void*)(Q16 + gsrc));
        CP16(d0 + 64u*QROWB,    (const void*)(Khi + gsrc));
        CP16(d0 + 2u*64u*QROWB, (const void*)(Klo + gsrc));
    }
    if (tid < 64) {
        sLec[tid] = Lec[(size_t)bh * Tt + t0 + tid];
        sTh[tid]  = Th[(tokbase + t0 + tid) * Hh + h];
    }
    asm volatile("cp.async.commit_group;" ::: "memory");
    asm volatile("cp.async.wait_group 0;" ::: "memory");
    __syncthreads();

    const int wid = tid >> 5, lane = tid & 31;
    const int wm0 = wid * 16;
    const int q8 = lane >> 3, l8 = lane & 7;
    const uint32_t aoff = (uint32_t)((l8 + (q8 & 1) * 8) * QROWB + (q8 >> 1) * 16);
    const uint32_t boff = (uint32_t)((l8 + (q8 >> 1) * 8) * QROWB + (q8 & 1) * 16);

    float acc[8][4];
#pragma unroll
    for (int nf = 0; nf < 8; nf++)
#pragma unroll
        for (int j = 0; j < 4; j++) acc[nf][j] = 0.f;

    const uint32_t As = sb + (uint32_t)wm0 * QROWB;        // Q tile
    const uint32_t Bsv[2] = {sb + 64u*QROWB, sb + 2u*64u*QROWB};  // Khi, Klo
#pragma unroll
    for (int seg = 0; seg < 2; seg++) {
        const uint32_t Bs = Bsv[seg];
#pragma unroll
        for (int ks = 0; ks < 8; ks++) {
            uint32_t a[4];
            ldm_x4(a, As + ks * 32 + aoff);
#pragma unroll
            for (int p = 0; p < 4; p++) {
                uint32_t bb[4];
                ldm_x4(bb, Bs + (uint32_t)(p * 16) * QROWB + ks * 32 + boff);
                mma16816(acc[2*p],   a, bb[0], bb[1]);
                mma16816(acc[2*p+1], a, bb[2], bb[3]);
            }
        }
    }

    const int r0 = lane >> 2, c0 = (lane & 3) * 2;
    float* Mo = Mout + (size_t)blk * (BT*BT);
#pragma unroll
    for (int half_ = 0; half_ < 2; half_++) {
        int ii = wm0 + r0 + half_ * 8;
        float li = sLec[ii];
#pragma unroll
        for (int nf = 0; nf < 8; nf++) {
            int col = nf * 8 + c0;
            float m0 = 0.f, m1 = 0.f;
            if (col <= ii)
                m0 = acc[nf][half_*2]   * expf(fminf(li - sLec[col], 0.f)) * sTh[col];
            if (col + 1 <= ii)
                m1 = acc[nf][half_*2+1] * expf(fminf(li - sLec[col+1], 0.f)) * sTh[col+1];
            float2 mv = {m0, m1};
            *(float2*)(Mo + ii * 64 + col) = mv;
        }
    }
}

// ---------------- scan: phase A on HMMA (e: 3-seg compensated k/W; zq: 2-seg), B/C f32x2 ----------------
#define SROW 136
#define SROWB (SROW*2)
__global__ __launch_bounds__(256, 1)
void scan_kernel(const __half* __restrict__ Q16,
                 const __half* __restrict__ Khi, const __half* __restrict__ Klo,
                 const float* __restrict__ Vc, const float* __restrict__ Elec,
                 const float* __restrict__ Coef, const float* __restrict__ Mg,
                 float* __restrict__ Z)
{
    extern __shared__ float sm[];
    float* sW    = sm;                    // 32*132
    float* sVE   = sW + 32*132;
    float* sZQ   = sVE + 64*32;
    float* sM    = sZQ + 64*32;
    float* sElec = sM + 64*68;
    float* sCoef = sElec + 64;
    __half* sWh  = (__half*)(sCoef + 64); // 32*SROW
    __half* sWl  = sWh + 32*SROW;         // 32*SROW
    __half* sKh  = sWl + 32*SROW;         // 64*SROW
    __half* sKl  = sKh + 64*SROW;         // 64*SROW
    __half* sQh  = sKl + 64*SROW;         // 64*SROW

    const int tid = threadIdx.x;
    const int bh  = blockIdx.x;
    const int b = bh >> 4, h = bh & 15;
    const int vs0 = blockIdx.y * VS;

    const size_t tokbase = (size_t)b * Tt;
    const size_t goff = tokbase * HD + (size_t)h * Kk;
    const __half* Qh = Q16 + goff;
    const __half* Kh = Khi + goff;
    const __half* Kl = Klo + goff;
    const float* Vp = Vc + tokbase*HD + (size_t)h*Vv + vs0;
    const float* Mp = Mg + (size_t)bh * (NT*BT*BT);
    float*       Zp = Z  + tokbase*HD + (size_t)h*Vv + vs0;

    for (int i = tid; i < 32*132; i += 256) sW[i] = 0.f;

    const int wid = tid >> 5, lane = tid & 31;
    const int wm = wid >> 1, wn = wid & 1;
    const int q8 = lane >> 3, l8 = lane & 7;
    const uint32_t aoff = (uint32_t)((l8 + (q8 & 1) * 8) * SROWB + (q8 >> 1) * 16);
    const uint32_t boff = (uint32_t)((l8 + (q8 >> 1) * 8) * SROWB + (q8 & 1) * 16);
    const uint32_t uWh = smem_u32(sWh), uWl = smem_u32(sWl);
    const uint32_t uKh = smem_u32(sKh), uKl = smem_u32(sKl);
    const uint32_t uQh = smem_u32(sQh);
    const int fr0 = lane >> 2, fc0 = (lane & 3) * 2;

    const int tx = tid & 7;
    const int ty = tid >> 3;
    const int v0 = tx << 2;
    const int ta = ty*2, tb = ta + 1;
    const int k0 = ty << 2;

    for (int ct = 0; ct < NT; ct++) {
        const int t0 = ct * BT;
        __syncthreads();

#pragma unroll
        for (int i = 0; i < 4; i++) {
            int idx = tid + i*256;
            int r = idx >> 4, c = (idx & 15) * 8;
            size_t off = (size_t)(t0 + r) * HD + c;
            *(uint4*)&sKh[r*SROW + c] = *(const uint4*)(Kh + off);
            *(uint4*)&sKl[r*SROW + c] = *(const uint4*)(Kl + off);
            *(uint4*)&sQh[r*SROW + c] = *(const uint4*)(Qh + off);
        }
#pragma unroll
        for (int i = 0; i < 2; i++) {
            int idx = tid + i*256;
            int r = idx >> 3;
            int c = (idx & 7) << 2;
            *(float4*)&sVE[r*VS + c] = *(const float4*)(Vp + (size_t)(t0+r)*HD + c);
        }
#pragma unroll
        for (int i = 0; i < 4; i++) {
            int idx = tid + i*256;
            int r = idx >> 4;
            int c = (idx & 15) << 2;
            *(float4*)&sM[r*68 + c] = *(const float4*)(Mp + ct*(BT*BT) + r*64 + c);
        }
        if (tid < 64) {
            sElec[tid] = Elec[(size_t)bh*Tt + t0 + tid];
            sCoef[tid] = Coef[(size_t)bh*Tt + t0 + tid];
        }
        // W fp32 -> fp16 hi/lo split
#pragma unroll
        for (int i = 0; i < 4; i++) {
            int idx = tid + i*256;
            int r = idx >> 5;
            int c4 = (idx & 31) << 2;
            float4 w4 = *(float4*)&sW[r*132 + c4];
            __half hx = __float2half(w4.x), hy = __float2half(w4.y);
            __half hz = __float2half(w4.z), hw = __float2half(w4.w);
            __half lx = __float2half(w4.x - __half2float(hx));
            __half ly = __float2half(w4.y - __half2float(hy));
            __half lz = __float2half(w4.z - __half2float(hz));
            __half lw = __float2half(w4.w - __half2float(hw));
            *(__half2*)&sWh[r*SROW + c4]     = __halves2half2(hx, hy);
            *(__half2*)&sWh[r*SROW + c4 + 2] = __halves2half2(hz, hw);
            *(__half2*)&sWl[r*SROW + c4]     = __halves2half2(lx, ly);
            *(__half2*)&sWl[r*SROW + c4 + 2] = __halves2half2(lz, lw);
        }
        __syncthreads();

        // ---- Phase A (HMMA): e 3-segment compensated; zq 2-segment ----
        {
            float ae[2][4], az[2][4];
#pragma unroll
            for (int nf = 0; nf < 2; nf++)
#pragma unroll
                for (int j = 0; j < 4; j++) { ae[nf][j] = 0.f; az[nf][j] = 0.f; }

            const uint32_t Ak = uKh + (uint32_t)(wm*16) * SROWB;
            const uint32_t Akl = uKl + (uint32_t)(wm*16) * SROWB;
            const uint32_t Aq = uQh + (uint32_t)(wm*16) * SROWB;
            const uint32_t Bh = uWh + (uint32_t)(wn*16) * SROWB;
            const uint32_t Bl = uWl + (uint32_t)(wn*16) * SROWB;
            // e segments: (khi,Whi), (klo,Whi), (khi,Wlo); zq: (q,Whi), (q,Wlo)
            const uint32_t Aev[3] = {Ak, Akl, Ak};
            const uint32_t Bev[3] = {Bh, Bh, Bl};
#pragma unroll
            for (int seg = 0; seg < 3; seg++) {
#pragma unroll
                for (int ks = 0; ks < 8; ks++) {
                    uint32_t bb[4];
                    ldm_x4(bb, Bev[seg] + ks * 32 + boff);
                    uint32_t ak[4];
                    ldm_x4(ak, Aev[seg] + ks * 32 + aoff);
                    mma16816(ae[0], ak, bb[0], bb[1]);
                    mma16816(ae[1], ak, bb[2], bb[3]);
                    if (seg < 2) {
                        uint32_t aq[4];
                        ldm_x4(aq, Aq + ks * 32 + aoff);
                        uint32_t bq0 = bb[0], bq1 = bb[1], bq2 = bb[2], bq3 = bb[3];
                        if (seg == 1) {   // zq's second segment is (q, Wlo)
                            uint32_t bl[4];
                            ldm_x4(bl, Bl + ks * 32 + boff);
                            bq0 = bl[0]; bq1 = bl[1]; bq2 = bl[2]; bq3 = bl[3];
                        }
                        mma16816(az[0], aq, bq0, bq1);
                        mma16816(az[1], aq, bq2, bq3);
                    }
                }
            }
#pragma unroll
            for (int h8 = 0; h8 < 2; h8++) {
                int r = wm*16 + fr0 + h8*8;
                float el = sElec[r];
#pragma unroll
                for (int nf = 0; nf < 2; nf++) {
                    int c = wn*16 + nf*8 + fc0;
                    float2 vv = *(float2*)&sVE[r*VS + c];
                    float2 ev = {ae[nf][h8*2] - vv.x, ae[nf][h8*2+1] - vv.y};
                    *(float2*)&sVE[r*VS + c] = ev;
                    float2 zv = {az[nf][h8*2] * el, az[nf][h8*2+1] * el};
                    *(float2*)&sZQ[r*VS + c] = zv;
                }
            }
        }
        __syncthreads();

        // ---- Fused B+C (f32x2) ----
        {
            float4 za4 = *(float4*)&sZQ[ta*VS + v0];
            float4 zb4 = *(float4*)&sZQ[tb*VS + v0];
            u64t za01 = pk2(za4.x, za4.y), za23 = pk2(za4.z, za4.w);
            u64t zb01 = pk2(zb4.x, zb4.y), zb23 = pk2(zb4.z, zb4.w);
            u64t sa01 = 0ull, sa23 = 0ull, sb01 = 0ull, sb23 = 0ull;
            u64t ca01[4], ca23[4];
#pragma unroll
            for (int i = 0; i < 4; i++) { ca01[i] = 0ull; ca23[i] = 0ull; }
#pragma unroll 2
            for (int t = 0; t < BT; t++) {
                double2 ed = *(double2*)&sVE[t*VS + v0];
                u64t e01 = d2u(ed.x), e23 = d2u(ed.y);
                float ma = sM[ta*68 + t];
                float mb = sM[tb*68 + t];
                u64t ma2 = pk2(ma, ma), mb2 = pk2(mb, mb);
                sa01 = fma2(ma2, e01, sa01);
                sa23 = fma2(ma2, e23, sa23);
                sb01 = fma2(mb2, e01, sb01);
                sb23 = fma2(mb2, e23, sb23);
                float cf = -sCoef[t];
                float e0, e1, e2, e3;
                upk2(e01, e0, e1); upk2(e23, e2, e3);
                uint2 kh2 = *(uint2*)&sKh[t*SROW + k0];
                uint2 kl2 = *(uint2*)&sKl[t*SROW + k0];
                float4 k4 = cvt4(kh2, kl2);
                u64t k01 = pk2(k4.x, k4.y), k23 = pk2(k4.z, k4.w);
                u64t c0p = pk2(cf*e0, cf*e0), c1p = pk2(cf*e1, cf*e1);
                u64t c2p = pk2(cf*e2, cf*e2), c3p = pk2(cf*e3, cf*e3);
                ca01[0] = fma2(k01, c0p, ca01[0]); ca23[0] = fma2(k23, c0p, ca23[0]);
                ca01[1] = fma2(k01, c1p, ca01[1]); ca23[1] = fma2(k23, c1p, ca23[1]);
                ca01[2] = fma2(k01, c2p, ca01[2]); ca23[2] = fma2(k23, c2p, ca23[2]);
                ca01[3] = fma2(k01, c3p, ca01[3]); ca23[3] = fma2(k23, c3p, ca23[3]);
            }
            float z0, z1, s0, s1;
            float4 oa, ob;
            upk2(za01, z0, z1); upk2(sa01, s0, s1); oa.x = z0 - s0; oa.y = z1 - s1;
            upk2(za23, z0, z1); upk2(sa23, s0, s1); oa.z = z0 - s0; oa.w = z1 - s1;
            upk2(zb01, z0, z1); upk2(sb01, s0, s1); ob.x = z0 - s0; ob.y = z1 - s1;
            upk2(zb23, z0, z1); upk2(sb23, s0, s1); ob.z = z0 - s0; ob.w = z1 - s1;
            *(float4*)(Zp + (size_t)(t0+ta)*HD + v0) = oa;
            *(float4*)(Zp + (size_t)(t0+tb)*HD + v0) = ob;

            float dk = sElec[63];
            u64t dk2 = pk2(dk, dk);
#pragma unroll
            for (int i = 0; i < 4; i++) {
                double2 wv = *(double2*)&sW[(v0+i)*132 + k0];
                u64t w01 = fma2(d2u(wv.x), dk2, ca01[i]);
                u64t w23 = fma2(d2u(wv.y), dk2, ca23[i]);
                *(double2*)&sW[(v0+i)*132 + k0] = make_double2(u2d(w01), u2d(w23));
            }
        }
    }
}

// ---------------- gated RMS norm -> fp16 ----------------
__global__ __launch_bounds__(256)
void gated_rms_f16(const float* __restrict__ Zin, const float* __restrict__ G,
                   const float* __restrict__ nw, __half* __restrict__ og)
{
    const int gw   = blockIdx.x * 8 + (threadIdx.x >> 5);
    const int lane = threadIdx.x & 31;
    const size_t base = (size_t)gw * 128;
    float4 zv = *(const float4*)(Zin + base + lane*4);
    float ss = zv.x*zv.x + zv.y*zv.y + zv.z*zv.z + zv.w*zv.w;
#pragma unroll
    for (int o = 16; o; o >>= 1) ss += __shfl_xor_sync(0xffffffffu, ss, o);
    float r = rsqrtf(ss * (1.f/128.f) + 1e-5f);
    float4 gv = *(const float4*)(G  + base + lane*4);
    float4 wv = *(const float4*)(nw + lane*4);
    float ov[4];
    ov[0] = zv.x*r*wv.x * (gv.x / (1.f + expf(-gv.x)));
    ov[1] = zv.y*r*wv.y * (gv.y / (1.f + expf(-gv.y)));
    ov[2] = zv.z*r*wv.z * (gv.z / (1.f + expf(-gv.z)));
    ov[3] = zv.w*r*wv.w * (gv.w / (1.f + expf(-gv.w)));
    __align__(8) __half h[4];
#pragma unroll
    for (int j = 0; j < 4; j++) h[j] = __float2half(ov[j]);
    *(uint2*)(og + base + lane*4) = *(uint2*)h;
}

// ---------------- launch ----------------
extern "C" void kernel_launch(void* const* d_in, const int* in_sizes, int n_in,
                              void* d_out, int out_size)
{
    const float* X    = (const float*)d_in[0];
    const float* Wq   = (const float*)d_in[1];
    const float* Wk   = (const float*)d_in[2];
    const float* Wv   = (const float*)d_in[3];
    const float* Weta = (const float*)d_in[4];
    const float* Wth  = (const float*)d_in[5];
    const float* Wg   = (const float*)d_in[6];
    const float* nw   = (const float*)d_in[7];
    const float* Wo   = (const float*)d_in[8];
    float* out = (float*)d_out;

    float *v, *g, *z, *eta, *th, *lec, *elec, *coef, *Mbuf;
    __half *xhi, *xlo, *w16, *w32hi, *w32lo, *og16, *q16, *khi, *klo;
    cudaGetSymbolAddress((void**)&v,    g_v);
    cudaGetSymbolAddress((void**)&g,    g_g);
    cudaGetSymbolAddress((void**)&z,    g_z);
    cudaGetSymbolAddress((void**)&eta,  g_eta);
    cudaGetSymbolAddress((void**)&th,   g_theta);
    cudaGetSymbolAddress((void**)&lec,  g_lec);
    cudaGetSymbolAddress((void**)&elec, g_elec);
    cudaGetSymbolAddress((void**)&coef, g_coef);
    cudaGetSymbolAddress((void**)&Mbuf, g_M);
    cudaGetSymbolAddress((void**)&xhi,  g_xhi);
    cudaGetSymbolAddress((void**)&xlo,  g_xlo);
    cudaGetSymbolAddress((void**)&w16,  g_w16);
    cudaGetSymbolAddress((void**)&w32hi,g_w32hi);
    cudaGetSymbolAddress((void**)&w32lo,g_w32lo);
    cudaGetSymbolAddress((void**)&og16, g_og16);
    cudaGetSymbolAddress((void**)&q16,  g_q16);
    cudaGetSymbolAddress((void**)&khi,  g_khi);
    cudaGetSymbolAddress((void**)&klo,  g_klo);

    // scan smem: fp32 12800 floats + fp16 (2*32 + 3*64)*136 = 34816 halfs
    const int scan_smem = 12800*4 + 34816*2;   // 120832
    cudaFuncSetAttribute(scan_kernel, cudaFuncAttributeMaxDynamicSharedMemorySize, scan_smem);
    const int qkm_smem = 3*64*QROWB + 2*64*4;   // 52736
    cudaFuncSetAttribute(qkm_hmma, cudaFuncAttributeMaxDynamicSharedMemorySize, qkm_smem);
    const int gemm_smem = NSTG * STG_BYTES;   // 81920
    cudaFuncSetAttribute(gemm2_f16, cudaFuncAttributeMaxDynamicSharedMemorySize, gemm_smem);
    cudaFuncSetAttribute(gemm2_qkvg, cudaFuncAttributeMaxDynamicSharedMemorySize, gemm_smem);
    const int eta_smem = 4 * 160 * ROWB;      // 51200
    cudaFuncSetAttribute(eta_theta_hmma, cudaFuncAttributeMaxDynamicSharedMemorySize, eta_smem);

    const int WN = Dd * Dd;
    const float qscale = 0.08838834764831845f;  // 128^-0.5

    split_fp16_kernel<<<TOKS*Dd/4/256, 256>>>(X, xhi, xlo, TOKS*Dd/4);
    conv_fp16_4<<<4*4096, 256>>>(Wq, Wk, Wv, Wg, w16);
    conv_fp16_kernel<<<4096, 256>>>(Wo, w16 + 4*(size_t)WN, WN/4);
    split_w32<<<32*Dd/4/256, 256>>>(Weta, Wth, w32hi, w32lo);

    eta_theta_hmma<<<TOKS/128, 128, eta_smem>>>(xhi, xlo, w32hi, w32lo, eta, th);
    decay_prep_kernel<<<2048/8, 256>>>(eta, th, lec, elec, coef);

    gemm2_qkvg<<<dim3(64, TOKS/128), 128, gemm_smem>>>(xhi, xlo, w16, v, g, q16, khi, klo, qscale);

    qkm_hmma<<<32*NT, 128, qkm_smem>>>(q16, khi, klo, lec, th, Mbuf);

    scan_kernel<<<dim3(Bb*Hh, NVS), 256, scan_smem>>>(q16, khi, klo, v, elec, coef, Mbuf, z);

    gated_rms_f16<<<TOKS*Hh/8, 256>>>(z, g, nw, og16);
    gemm2_f16<<<dim3(HD/128, TOKS/128), 128, gemm_smem>>>(og16, w16 + 4*(size_t)WN, out, 1.f);
}